// round 13
// baseline (speedup 1.0000x reference)
#include <cuda_runtime.h>
#include <cuda_bf16.h>
#include <cstdint>

typedef __nv_bfloat16 bf16;

// ---------------- problem constants ----------------
#define BB    4
#define TT    1024
#define CC    1024
#define HH    16
#define HD    64
#define LL    6
#define VV    16000
#define FF_   4096
#define TTXT  580
#define NPATCH 441
#define KIM   768
#define IMG   336
#define PATCH 16
#define MTOK  (BB*TT)          // 4096
#define QMAX  16256.f          // 127*128

// ---------------- scratch (device globals; no allocation) ----------------
__device__ float g_x  [(size_t)MTOK*CC];
__device__ float g_pp [(size_t)BB*NPATCH*CC];

__device__ bf16 g_qh[(size_t)MTOK*CC], g_ql[(size_t)MTOK*CC];
__device__ bf16 g_kh[(size_t)MTOK*CC], g_kl[(size_t)MTOK*CC];
__device__ bf16 g_vth[(size_t)MTOK*CC], g_vtl[(size_t)MTOK*CC];
__device__ bf16 g_ah[(size_t)MTOK*CC], g_al[(size_t)MTOK*CC];
__device__ bf16 g_fh[(size_t)MTOK*FF_], g_fl[(size_t)MTOK*FF_];

// bf16 staging for weights (source for int8 quant)
__device__ bf16 g_wqkvh[(size_t)LL*3*CC*CC], g_wqkvl[(size_t)LL*3*CC*CC];
__device__ bf16 g_woh[(size_t)LL*CC*CC], g_wol[(size_t)LL*CC*CC];
__device__ bf16 g_w1h[(size_t)LL*CC*FF_], g_w1l[(size_t)LL*CC*FF_];
__device__ bf16 g_w2h[(size_t)LL*CC*FF_], g_w2l[(size_t)LL*CC*FF_];
__device__ bf16 g_lmh[(size_t)CC*VV],    g_lml[(size_t)CC*VV];
__device__ bf16 g_pwh[(size_t)CC*KIM],   g_pwl[(size_t)CC*KIM];
__device__ bf16 g_imh[(size_t)BB*NPATCH*KIM], g_iml[(size_t)BB*NPATCH*KIM];

// int8 operands + scales
__device__ int8_t g_iah[(size_t)MTOK*FF_], g_ial[(size_t)MTOK*FF_];
__device__ float  g_sAct[MTOK];
__device__ int8_t g_imqh[(size_t)BB*NPATCH*KIM], g_imql[(size_t)BB*NPATCH*KIM];
__device__ float  g_sIm[BB*NPATCH];
__device__ int8_t g_iwqkvh[(size_t)LL*3*CC*CC], g_iwqkvl[(size_t)LL*3*CC*CC];
__device__ float  g_sWqkv[LL*3*CC];
__device__ int8_t g_iwoh[(size_t)LL*CC*CC], g_iwol[(size_t)LL*CC*CC];
__device__ float  g_sWo[LL*CC];
__device__ int8_t g_iw1h[(size_t)LL*CC*FF_], g_iw1l[(size_t)LL*CC*FF_];
__device__ float  g_sW1[LL*FF_];
__device__ int8_t g_iw2h[(size_t)LL*CC*FF_], g_iw2l[(size_t)LL*CC*FF_];
__device__ float  g_sW2[LL*CC];
__device__ int8_t g_ilmh[(size_t)CC*VV], g_ilml[(size_t)CC*VV];
__device__ float  g_sLm[VV];
__device__ int8_t g_ipwh[(size_t)CC*KIM], g_ipwl[(size_t)CC*KIM];
__device__ float  g_sPw[CC];

// ---------------- low-level helpers ----------------
__device__ __forceinline__ uint32_t smem_u32(const void* p) {
    uint32_t a;
    asm("{ .reg .u64 t; cvta.to.shared.u64 t, %1; cvt.u32.u64 %0, t; }" : "=r"(a) : "l"(p));
    return a;
}
__device__ __forceinline__ void cpa16(uint32_t dst, const void* src, int szbytes) {
    asm volatile("cp.async.cg.shared.global [%0], [%1], 16, %2;"
                 :: "r"(dst), "l"(src), "r"(szbytes) : "memory");
}
__device__ __forceinline__ void ldsm4(uint32_t (&r)[4], uint32_t addr) {
    asm volatile("ldmatrix.sync.aligned.m8n8.x4.shared.b16 {%0,%1,%2,%3}, [%4];"
                 : "=r"(r[0]), "=r"(r[1]), "=r"(r[2]), "=r"(r[3]) : "r"(addr));
}
__device__ __forceinline__ void mma_bf16(float (&d)[4], const uint32_t (&a)[4],
                                         uint32_t b0, uint32_t b1) {
    asm volatile("mma.sync.aligned.m16n8k16.row.col.f32.bf16.bf16.f32 "
                 "{%0,%1,%2,%3}, {%4,%5,%6,%7}, {%8,%9}, {%0,%1,%2,%3};"
                 : "+f"(d[0]), "+f"(d[1]), "+f"(d[2]), "+f"(d[3])
                 : "r"(a[0]), "r"(a[1]), "r"(a[2]), "r"(a[3]), "r"(b0), "r"(b1));
}
__device__ __forceinline__ void mma_s8(int (&d)[4], const uint32_t (&a)[4],
                                       uint32_t b0, uint32_t b1) {
    asm volatile("mma.sync.aligned.m16n8k32.row.col.s32.s8.s8.s32 "
                 "{%0,%1,%2,%3}, {%4,%5,%6,%7}, {%8,%9}, {%0,%1,%2,%3};"
                 : "+r"(d[0]), "+r"(d[1]), "+r"(d[2]), "+r"(d[3])
                 : "r"(a[0]), "r"(a[1]), "r"(a[2]), "r"(a[3]), "r"(b0), "r"(b1));
}
__device__ __forceinline__ uint32_t pack_split(float v0, float v1, uint32_t& lw) {
    bf16 h0 = __float2bfloat16(v0), h1 = __float2bfloat16(v1);
    float r0 = v0 - __bfloat162float(h0), r1 = v1 - __bfloat162float(h1);
    bf16 l0 = __float2bfloat16(r0), l1 = __float2bfloat16(r1);
    lw = (uint32_t)__bfloat16_as_ushort(l0) | ((uint32_t)__bfloat16_as_ushort(l1) << 16);
    return (uint32_t)__bfloat16_as_ushort(h0) | ((uint32_t)__bfloat16_as_ushort(h1) << 16);
}
__device__ __forceinline__ void q15(float v, float inv, int& h, int& l) {
    int q = __float2int_rn(v * inv);
    h = (q + 64) >> 7;
    l = q - (h << 7);
}

// ---------------- int8 split GEMM (mma.sync m16n8k32) ----------------
// C[m,n] = sA[m]*sB[n]*(16384*Σhh' + 128*Σ(hl'+lh'))  (+bias/res/relu)
// A: [M,K] int8 hi/lo; B: [N,K] int8 hi/lo. K % 64 == 0.
#define I8_LDS 80
#define I8_ASZ (128*I8_LDS)
#define I8_BSZ (64*I8_LDS)
#define SMEM_I8 (4*I8_ASZ + 4*I8_BSZ)   // 61440

__global__ __launch_bounds__(256, 2)
void gemm_i8(const int8_t* __restrict__ Ah, const int8_t* __restrict__ Al,
             const float* __restrict__ sA,
             const int8_t* __restrict__ Bh, const int8_t* __restrict__ Bl,
             const float* __restrict__ sB,
             const float* __restrict__ bias, const float* __restrict__ res,
             float* __restrict__ outF, bf16* __restrict__ outH, bf16* __restrict__ outL,
             bf16* __restrict__ okh, bf16* __restrict__ okl,
             bf16* __restrict__ ovh, bf16* __restrict__ ovl,
             int M, int Nfull, int K, int ldc, int relu, int outMode)
{
    const int m0 = blockIdx.y * 128;
    const int n0 = blockIdx.x * 64;

    extern __shared__ char smi[];
    const uint32_t sbase = smem_u32(smi);
    const int tid = threadIdx.x;
    const int wid = tid >> 5, lane = tid & 31;
    const int wr = wid & 3, wc = wid >> 2;           // warps 4x2
    const int wmBase = wr * 32, wnBase = wc * 32;    // warp tile 32x32
    const int nch = K >> 6;                          // KC = 64

    auto load_stage = [&](int st, int k0) {
        #pragma unroll
        for (int i = tid; i < 128 * 4; i += 256) {
            int r = i >> 2, c16 = (i & 3) << 4;
            int gr = m0 + r;
            int ok = (gr < M) ? 16 : 0;
            if (gr >= M) gr = m0;
            size_t go = (size_t)gr * K + k0 + c16;
            uint32_t so = (uint32_t)(st * I8_ASZ + r * I8_LDS + c16);
            cpa16(sbase + so, Ah + go, ok);
            cpa16(sbase + 2 * I8_ASZ + so, Al + go, ok);
        }
        {
            int i = tid;                              // 64*4 == 256
            int r = i >> 2, c16 = (i & 3) << 4;
            int gn = n0 + r;
            int ok = (gn < Nfull) ? 16 : 0;
            if (gn >= Nfull) gn = n0;
            size_t go = (size_t)gn * K + k0 + c16;
            uint32_t so = (uint32_t)(4 * I8_ASZ + st * I8_BSZ + r * I8_LDS + c16);
            cpa16(sbase + so, Bh + go, ok);
            cpa16(sbase + 2 * I8_BSZ + so, Bl + go, ok);
        }
        asm volatile("cp.async.commit_group;" ::: "memory");
    };

    int acc1[2][4][4], acc2[2][4][4];
    #pragma unroll
    for (int mi = 0; mi < 2; mi++)
        #pragma unroll
        for (int ni = 0; ni < 4; ni++)
            #pragma unroll
            for (int j = 0; j < 4; j++) { acc1[mi][ni][j] = 0; acc2[mi][ni][j] = 0; }

    load_stage(0, 0);

    for (int ch = 0; ch < nch; ch++) {
        asm volatile("cp.async.wait_group 0;" ::: "memory");
        __syncthreads();
        if (ch + 1 < nch) load_stage((ch + 1) & 1, (ch + 1) << 6);

        const int st = ch & 1;
        const uint32_t aHb = sbase + (uint32_t)(st * I8_ASZ);
        const uint32_t aLb = aHb + (uint32_t)(2 * I8_ASZ);
        const uint32_t bHb = sbase + (uint32_t)(4 * I8_ASZ + st * I8_BSZ);
        const uint32_t bLb = bHb + (uint32_t)(2 * I8_BSZ);

        #pragma unroll
        for (int kk = 0; kk < 2; kk++) {
            const int colOff = kk * 32 + ((lane >> 4) << 4);   // bytes
            uint32_t aH[2][4], aL[2][4];
            #pragma unroll
            for (int mi = 0; mi < 2; mi++) {
                uint32_t off = (uint32_t)((wmBase + mi * 16 + (lane & 15)) * I8_LDS + colOff);
                ldsm4(aH[mi], aHb + off);
                ldsm4(aL[mi], aLb + off);
            }
            #pragma unroll
            for (int nj = 0; nj < 2; nj++) {
                uint32_t off = (uint32_t)((wnBase + nj * 16 + (lane & 15)) * I8_LDS + colOff);
                uint32_t bH[4], bL[4];
                ldsm4(bH, bHb + off);
                ldsm4(bL, bLb + off);
                #pragma unroll
                for (int mi = 0; mi < 2; mi++) {
                    mma_s8(acc1[mi][2*nj],   aH[mi], bH[0], bH[2]);
                    mma_s8(acc1[mi][2*nj+1], aH[mi], bH[1], bH[3]);
                }
                #pragma unroll
                for (int mi = 0; mi < 2; mi++) {
                    mma_s8(acc2[mi][2*nj],   aH[mi], bL[0], bL[2]);
                    mma_s8(acc2[mi][2*nj+1], aH[mi], bL[1], bL[3]);
                }
                #pragma unroll
                for (int mi = 0; mi < 2; mi++) {
                    mma_s8(acc2[mi][2*nj],   aL[mi], bH[0], bH[2]);
                    mma_s8(acc2[mi][2*nj+1], aL[mi], bH[1], bH[3]);
                }
            }
        }
    }

    // epilogue
    const int g = lane >> 2, t4 = lane & 3;
    #pragma unroll
    for (int mi = 0; mi < 2; mi++) {
        #pragma unroll
        for (int ni = 0; ni < 4; ni++) {
            int col = n0 + wnBase + ni * 8 + t4 * 2;
            if (col >= Nfull) continue;
            float sb0 = sB[col], sb1 = sB[col + 1];
            #pragma unroll
            for (int half = 0; half < 2; half++) {
                int row = m0 + wmBase + mi * 16 + g + half * 8;
                if (row >= M) continue;
                float sa = sA[row];
                float f0 = 16384.f * (float)acc1[mi][ni][half*2+0] + 128.f * (float)acc2[mi][ni][half*2+0];
                float f1 = 16384.f * (float)acc1[mi][ni][half*2+1] + 128.f * (float)acc2[mi][ni][half*2+1];
                float v0 = sa * sb0 * f0;
                float v1 = sa * sb1 * f1;
                if (outMode == 1) {
                    int which = col >> 10;
                    int c = col & 1023;
                    int h = c >> 6, d = c & 63;
                    int b = row >> 10, t = row & 1023;
                    uint32_t lw;
                    uint32_t hw = pack_split(v0, v1, lw);
                    if (which < 2) {
                        size_t base = (((size_t)(b * HH + h)) * TT + t) * HD + d;
                        bf16* H = which ? okh : outH;
                        bf16* L = which ? okl : outL;
                        *(uint32_t*)(H + base) = hw;
                        *(uint32_t*)(L + base) = lw;
                    } else {
                        size_t vb = (((size_t)(b * HH + h)) * HD + d) * TT + t;
                        ovh[vb]      = __ushort_as_bfloat16((unsigned short)(hw & 0xffff));
                        ovh[vb + TT] = __ushort_as_bfloat16((unsigned short)(hw >> 16));
                        ovl[vb]      = __ushort_as_bfloat16((unsigned short)(lw & 0xffff));
                        ovl[vb + TT] = __ushort_as_bfloat16((unsigned short)(lw >> 16));
                    }
                } else {
                    long long base = (long long)row * ldc + col;
                    if (bias) { v0 += bias[col]; v1 += bias[col + 1]; }
                    if (res)  { v0 += res[base]; v1 += res[base + 1]; }
                    if (relu) { v0 = fmaxf(v0, 0.f); v1 = fmaxf(v1, 0.f); }
                    if (outF) *(float2*)(outF + base) = make_float2(v0, v1);
                    if (outH) {
                        uint32_t lw;
                        uint32_t hw = pack_split(v0, v1, lw);
                        *(uint32_t*)(outH + base) = hw;
                        *(uint32_t*)(outL + base) = lw;
                    }
                }
            }
        }
    }
}

// ---------------- fused flash attention (split bf16, register-P, longest-first) ----------------
#define LDF 72
__global__ __launch_bounds__(256, 2)
void flash_attn_k(const bf16* __restrict__ qh, const bf16* __restrict__ ql,
                  const bf16* __restrict__ kh, const bf16* __restrict__ kl,
                  const bf16* __restrict__ vth, const bf16* __restrict__ vtl,
                  bf16* __restrict__ oh, bf16* __restrict__ ol)
{
    extern __shared__ bf16 sm[];
    const uint32_t sbase = smem_u32(sm);
    const int id = blockIdx.x;
    const int rb = 7 - (id >> 6);
    const int bh = id & 63;
    const int m0 = rb * 128;
    const int tid = threadIdx.x, wid = tid >> 5, lane = tid & 31;
    const int g = lane >> 2, t4 = lane & 3;

    const uint32_t OQH = 0, OQL = 128*LDF;
    const uint32_t OKV = 2*128*LDF;
    const uint32_t KVS = 4*64*LDF;

    for (int i = tid; i < 128 * 8; i += 256) {
        int r = i >> 3, c = (i & 7) << 3;
        size_t go = ((size_t)bh * TT + m0 + r) * HD + c;
        cpa16(sbase + (OQH + r * LDF + c) * 2, qh + go, 16);
        cpa16(sbase + (OQL + r * LDF + c) * 2, ql + go, 16);
    }
    asm volatile("cp.async.commit_group;" ::: "memory");

    auto load_kv = [&](int st, int j0) {
        uint32_t base = OKV + (uint32_t)st * KVS;
        for (int i = tid; i < 64 * 8; i += 256) {
            int r = i >> 3, c = (i & 7) << 3;
            size_t gk = ((size_t)bh * TT + j0 + r) * HD + c;
            size_t gv = ((size_t)bh * HD + r) * TT + j0 + c;
            cpa16(sbase + (base            + r * LDF + c) * 2, kh  + gk, 16);
            cpa16(sbase + (base +   64*LDF + r * LDF + c) * 2, kl  + gk, 16);
            cpa16(sbase + (base + 2*64*LDF + r * LDF + c) * 2, vth + gv, 16);
            cpa16(sbase + (base + 3*64*LDF + r * LDF + c) * 2, vtl + gv, 16);
        }
        asm volatile("cp.async.commit_group;" ::: "memory");
    };

    const int ntiles = 2 * rb + 2;
    load_kv(0, 0);

    float oacc[8][4];
    #pragma unroll
    for (int ni = 0; ni < 8; ni++)
        #pragma unroll
        for (int j = 0; j < 4; j++) oacc[ni][j] = 0.f;
    float mrow[2] = { -1e30f, -1e30f };
    float lrow[2] = { 0.f, 0.f };

    const int row0 = m0 + wid * 16 + g;

    for (int t = 0; t < ntiles; t++) {
        const int j0 = t << 6;
        asm volatile("cp.async.wait_group 0;" ::: "memory");
        __syncthreads();
        if (t + 1 < ntiles) load_kv((t + 1) & 1, j0 + 64);

        const uint32_t kvb = OKV + (uint32_t)(t & 1) * KVS;
        const uint32_t kHb = sbase + kvb * 2;
        const uint32_t kLb = sbase + (kvb + 64*LDF) * 2;
        const uint32_t vHb = sbase + (kvb + 2*64*LDF) * 2;
        const uint32_t vLb = sbase + (kvb + 3*64*LDF) * 2;

        float acc[8][4];
        #pragma unroll
        for (int ni = 0; ni < 8; ni++)
            #pragma unroll
            for (int j = 0; j < 4; j++) acc[ni][j] = 0.f;

        #pragma unroll
        for (int kk = 0; kk < 4; kk++) {
            const int colOff = kk * 16 + ((lane >> 4) << 3);
            uint32_t aH[4], aL[4];
            uint32_t aoff = (uint32_t)(((wid * 16 + (lane & 15)) * LDF + colOff) * 2);
            ldsm4(aH, sbase + (OQH * 2) + aoff);
            ldsm4(aL, sbase + (OQL * 2) + aoff);
            #pragma unroll
            for (int nj = 0; nj < 4; nj++) {
                uint32_t boff = (uint32_t)(((nj * 16 + (lane & 15)) * LDF + colOff) * 2);
                uint32_t bH[4], bL[4];
                ldsm4(bH, kHb + boff);
                ldsm4(bL, kLb + boff);
                mma_bf16(acc[2*nj],   aH, bH[0], bH[2]);
                mma_bf16(acc[2*nj+1], aH, bH[1], bH[3]);
                mma_bf16(acc[2*nj],   aH, bL[0], bL[2]);
                mma_bf16(acc[2*nj+1], aH, bL[1], bL[3]);
                mma_bf16(acc[2*nj],   aL, bH[0], bH[2]);
                mma_bf16(acc[2*nj+1], aL, bH[1], bH[3]);
            }
        }

        #pragma unroll
        for (int ni = 0; ni < 8; ni++) {
            int colBase = j0 + ni * 8 + t4 * 2;
            #pragma unroll
            for (int j = 0; j < 4; j++) {
                int row = row0 + ((j >> 1) << 3);
                int col = colBase + (j & 1);
                float v = acc[ni][j] * 0.125f;
                acc[ni][j] = (col <= row) ? v : -1e30f;
            }
        }

        #pragma unroll
        for (int half = 0; half < 2; half++) {
            float mt = -1e30f;
            #pragma unroll
            for (int ni = 0; ni < 8; ni++) {
                mt = fmaxf(mt, acc[ni][half*2+0]);
                mt = fmaxf(mt, acc[ni][half*2+1]);
            }
            mt = fmaxf(mt, __shfl_xor_sync(0xffffffffu, mt, 1));
            mt = fmaxf(mt, __shfl_xor_sync(0xffffffffu, mt, 2));
            float mnew = fmaxf(mrow[half], mt);
            float scale = __expf(mrow[half] - mnew);
            mrow[half] = mnew;
            float sum = 0.f;
            #pragma unroll
            for (int ni = 0; ni < 8; ni++) {
                float e0 = __expf(acc[ni][half*2+0] - mnew);
                float e1 = __expf(acc[ni][half*2+1] - mnew);
                acc[ni][half*2+0] = e0;
                acc[ni][half*2+1] = e1;
                sum += e0 + e1;
            }
            sum += __shfl_xor_sync(0xffffffffu, sum, 1);
            sum += __shfl_xor_sync(0xffffffffu, sum, 2);
            lrow[half] = lrow[half] * scale + sum;
            #pragma unroll
            for (int ni = 0; ni < 8; ni++) {
                oacc[ni][half*2+0] *= scale;
                oacc[ni][half*2+1] *= scale;
            }
        }

        #pragma unroll
        for (int kk = 0; kk < 4; kk++) {
            uint32_t aH[4], aL[4];
            aH[0] = pack_split(acc[2*kk][0],   acc[2*kk][1],   aL[0]);
            aH[1] = pack_split(acc[2*kk][2],   acc[2*kk][3],   aL[1]);
            aH[2] = pack_split(acc[2*kk+1][0], acc[2*kk+1][1], aL[2]);
            aH[3] = pack_split(acc[2*kk+1][2], acc[2*kk+1][3], aL[3]);
            const int colOff = kk * 16 + ((lane >> 4) << 3);
            #pragma unroll
            for (int nj = 0; nj < 4; nj++) {
                uint32_t boff = (uint32_t)(((nj * 16 + (lane & 15)) * LDF + colOff) * 2);
                uint32_t bH[4], bL[4];
                ldsm4(bH, vHb + boff);
                ldsm4(bL, vLb + boff);
                mma_bf16(oacc[2*nj],   aH, bH[0], bH[2]);
                mma_bf16(oacc[2*nj+1], aH, bH[1], bH[3]);
                mma_bf16(oacc[2*nj],   aH, bL[0], bL[2]);
                mma_bf16(oacc[2*nj+1], aH, bL[1], bL[3]);
                mma_bf16(oacc[2*nj],   aL, bH[0], bH[2]);
                mma_bf16(oacc[2*nj+1], aL, bH[1], bH[3]);
            }
        }
    }

    const int b = bh >> 4, h = bh & 15;
    float inv0 = 1.f / lrow[0], inv1 = 1.f / lrow[1];
    #pragma unroll
    for (int ni = 0; ni < 8; ni++) {
        int d = ni * 8 + t4 * 2;
        #pragma unroll
        for (int half = 0; half < 2; half++) {
            int trow = m0 + wid * 16 + g + half * 8;
            float inv = half ? inv1 : inv0;
            size_t base = ((size_t)b * TT + trow) * CC + h * HD + d;
            uint32_t lw;
            uint32_t hw = pack_split(oacc[ni][half*2+0] * inv,
                                     oacc[ni][half*2+1] * inv, lw);
            *(uint32_t*)(oh + base) = hw;
            *(uint32_t*)(ol + base) = lw;
        }
    }
}

// ---------------- block reductions ----------------
__device__ __forceinline__ float blockReduceSum256(float v, float* sh) {
    #pragma unroll
    for (int o = 16; o > 0; o >>= 1) v += __shfl_xor_sync(0xffffffffu, v, o);
    int w = threadIdx.x >> 5;
    if ((threadIdx.x & 31) == 0) sh[w] = v;
    __syncthreads();
    if (threadIdx.x < 8) {
        v = sh[threadIdx.x];
        #pragma unroll
        for (int o = 4; o > 0; o >>= 1) v += __shfl_xor_sync(0xffu, v, o);
        if (threadIdx.x == 0) sh[0] = v;
    }
    __syncthreads();
    float r = sh[0]; __syncthreads(); return r;
}
__device__ __forceinline__ float blockReduceMax256(float v, float* sh) {
    #pragma unroll
    for (int o = 16; o > 0; o >>= 1) v = fmaxf(v, __shfl_xor_sync(0xffffffffu, v, o));
    int w = threadIdx.x >> 5;
    if ((threadIdx.x & 31) == 0) sh[w] = v;
    __syncthreads();
    if (threadIdx.x < 8) {
        v = sh[threadIdx.x];
        #pragma unroll
        for (int o = 4; o > 0; o >>= 1) v = fmaxf(v, __shfl_xor_sync(0xffu, v, o));
        if (threadIdx.x == 0) sh[0] = v;
    }
    __syncthreads();
    float r = sh[0]; __syncthreads(); return r;
}

__device__ __forceinline__ void split_store(bf16* H, bf16* L, size_t i, float v) {
    bf16 h = __float2bfloat16(v);
    H[i] = h;
    L[i] = __float2bfloat16(v - __bfloat162float(h));
}

__device__ __forceinline__ uint32_t quant_pack(const float* v, float inv, uint32_t& lw) {
    int h[4], l[4];
    #pragma unroll
    for (int j = 0; j < 4; j++) q15(v[j], inv, h[j], l[j]);
    lw = (uint32_t)(uint8_t)l[0] | ((uint32_t)(uint8_t)l[1] << 8) |
         ((uint32_t)(uint8_t)l[2] << 16) | ((uint32_t)(uint8_t)l[3] << 24);
    return (uint32_t)(uint8_t)h[0] | ((uint32_t)(uint8_t)h[1] << 8) |
           ((uint32_t)(uint8_t)h[2] << 16) | ((uint32_t)(uint8_t)h[3] << 24);
}

// ---------------- layernorm -> int8 (row-local quant) ----------------
__global__ __launch_bounds__(256)
void layernorm_quant_k(const float* __restrict__ x, const float* __restrict__ g,
                       const float* __restrict__ b,
                       int8_t* __restrict__ qh, int8_t* __restrict__ ql,
                       float* __restrict__ sc)
{
    __shared__ float sh[8];
    const size_t row = blockIdx.x;
    const float* xr = x + row * CC;
    const int c = threadIdx.x * 4;
    float4 xv = *(const float4*)(xr + c);
    float s  = xv.x + xv.y + xv.z + xv.w;
    float ss = xv.x*xv.x + xv.y*xv.y + xv.z*xv.z + xv.w*xv.w;
    s = blockReduceSum256(s, sh);
    ss = blockReduceSum256(ss, sh);
    float mean = s * (1.f / CC);
    float var = ss * (1.f / CC) - mean * mean;
    float inv = rsqrtf(var + 1e-5f);
    float4 gv = *(const float4*)(g + c);
    float4 bv = *(const float4*)(b + c);
    float y[4];
    y[0] = (xv.x - mean) * inv * gv.x + bv.x;
    y[1] = (xv.y - mean) * inv * gv.y + bv.y;
    y[2] = (xv.z - mean) * inv * gv.z + bv.z;
    y[3] = (xv.w - mean) * inv * gv.w + bv.w;
    float mx = fmaxf(fmaxf(fabsf(y[0]), fabsf(y[1])), fmaxf(fabsf(y[2]), fabsf(y[3])));
    mx = blockReduceMax256(mx, sh);
    float invq = mx > 0.f ? QMAX / mx : 0.f;
    if (threadIdx.x == 0) sc[row] = mx > 0.f ? mx / QMAX : 0.f;
    uint32_t lw;
    uint32_t hw = quant_pack(y, invq, lw);
    size_t base = row * CC + c;
    *(uint32_t*)(qh + base) = hw;
    *(uint32_t*)(ql + base) = lw;
}

// ---------------- fused embed + layer0 LN1 -> x fp32 + int8 ----------------
__global__ __launch_bounds__(256)
void embed_ln_quant_k(const int* __restrict__ toks, const float* __restrict__ tok_emb,
                      const float* __restrict__ txt_pos, const float* __restrict__ img_pos,
                      const float* __restrict__ p, const float* __restrict__ g,
                      const float* __restrict__ b,
                      float* __restrict__ x, int8_t* __restrict__ qh, int8_t* __restrict__ ql,
                      float* __restrict__ sc)
{
    __shared__ float sh[8];
    const int bt = blockIdx.x;
    const int bb = bt >> 10;
    const int t = bt & 1023;
    const int c = threadIdx.x * 4;
    const float* src;
    const float* extra = nullptr;
    if (t == 0)      src = tok_emb + 1 * CC;
    else if (t == 1) src = tok_emb + 8 * CC;
    else if (t < 443) {
        int n = t - 2;
        src = p + ((size_t)(bb * NPATCH + n)) * CC;
        extra = img_pos + (size_t)n * CC;
    }
    else if (t == 443) src = tok_emb + 9 * CC;
    else {
        int tok = toks[bb * TTXT + (t - 444)];
        src = tok_emb + (size_t)tok * CC;
    }
    float4 v = *(const float4*)(src + c);
    float4 tp = *(const float4*)(txt_pos + (size_t)t * CC + c);
    v.x += tp.x; v.y += tp.y; v.z += tp.z; v.w += tp.w;
    if (extra) {
        float4 e = *(const float4*)(extra + c);
        v.x += e.x; v.y += e.y; v.z += e.z; v.w += e.w;
    }
    size_t base = (size_t)bt * CC + c;
    *(float4*)(x + base) = v;

    float s  = v.x + v.y + v.z + v.w;
    float ss = v.x*v.x + v.y*v.y + v.z*v.z + v.w*v.w;
    s = blockReduceSum256(s, sh);
    ss = blockReduceSum256(ss, sh);
    float mean = s * (1.f / CC);
    float var = ss * (1.f / CC) - mean * mean;
    float inv = rsqrtf(var + 1e-5f);
    float4 gv = *(const float4*)(g + c);
    float4 bv = *(const float4*)(b + c);
    float y[4];
    y[0] = (v.x - mean) * inv * gv.x + bv.x;
    y[1] = (v.y - mean) * inv * gv.y + bv.y;
    y[2] = (v.z - mean) * inv * gv.z + bv.z;
    y[3] = (v.w - mean) * inv * gv.w + bv.w;
    float mx = fmaxf(fmaxf(fabsf(y[0]), fabsf(y[1])), fmaxf(fabsf(y[2]), fabsf(y[3])));
    mx = blockReduceMax256(mx, sh);
    float invq = mx > 0.f ? QMAX / mx : 0.f;
    if (threadIdx.x == 0) sc[bt] = mx > 0.f ? mx / QMAX : 0.f;
    uint32_t lw;
    uint32_t hw = quant_pack(y, invq, lw);
    *(uint32_t*)(qh + base) = hw;
    *(uint32_t*)(ql + base) = lw;
}

// ---------------- quantize rows of a split-bf16 matrix -> int8 pairs + scale ----------------
__global__ __launch_bounds__(256)
void quant_rows_k(const bf16* __restrict__ hi, const bf16* __restrict__ lo,
                  int8_t* __restrict__ qh, int8_t* __restrict__ ql,
                  float* __restrict__ sc, int K)
{
    __shared__ float sh[8];
    const size_t base = (size_t)blockIdx.x * K;
    float mx = 0.f;
    for (int j = threadIdx.x * 4; j < K; j += 1024) {
        #pragma unroll
        for (int u = 0; u < 4; u++) {
            float v = __bfloat162float(hi[base + j + u]) + __bfloat162float(lo[base + j + u]);
            mx = fmaxf(mx, fabsf(v));
        }
    }
    mx = blockReduceMax256(mx, sh);
    float invq = mx > 0.f ? QMAX / mx : 0.f;
    if (threadIdx.x == 0) sc[blockIdx.x] = mx > 0.f ? mx / QMAX : 0.f;
    for (int j = threadIdx.x * 4; j < K; j += 1024) {
        float v[4];
        #pragma unroll
        for (int u = 0; u < 4; u++)
            v[u] = __bfloat162float(hi[base + j + u]) + __bfloat162float(lo[base + j + u]);
        uint32_t lw;
        uint32_t hw = quant_pack(v, invq, lw);
        *(uint32_t*)(qh + base + j) = hw;
        *(uint32_t*)(ql + base + j) = lw;
    }
}

// ---------------- fused weight prep + im2col (bf16 staging) ----------------
__device__ __forceinline__ void transpose_tile(const float* __restrict__ W,
                                               bf16* __restrict__ hi, bf16* __restrict__ lo,
                                               int K, int N, int k0, int n0,
                                               float tbuf[32][33])
{
    int tx = threadIdx.x, ty = threadIdx.y;
    #pragma unroll
    for (int i = 0; i < 32; i += 8)
        tbuf[ty + i][tx] = W[(size_t)(k0 + ty + i) * N + n0 + tx];
    __syncthreads();
    #pragma unroll
    for (int i = 0; i < 32; i += 8)
        split_store(hi, lo, (size_t)(n0 + ty + i) * K + k0 + tx, tbuf[tx][ty + i]);
}

#define TPM_CC  1024
#define T_QKV   (LL*TPM_CC)
#define T_W1    (LL*(32*128))
#define T_LM    (32*500)
#define T_PATCH 768
#define T_IM2C  ((BB*NPATCH*KIM)/1024)

__global__ void prep_weights_k(const float* __restrict__ wq, const float* __restrict__ wk,
                               const float* __restrict__ wv, const float* __restrict__ wo,
                               const float* __restrict__ w1, const float* __restrict__ w2,
                               const float* __restrict__ lm_w, const float* __restrict__ patch_w,
                               const float* __restrict__ images,
                               bf16* qkvh, bf16* qkvl, bf16* woh, bf16* wol,
                               bf16* w1h, bf16* w1l, bf16* w2h, bf16* w2l,
                               bf16* lmh, bf16* lml, bf16* pwh, bf16* pwl,
                               bf16* imh, bf16* iml)
{
    __shared__ float tbuf[32][33];
    int t = blockIdx.x;
    const long long QKV_Z = (long long)3 * CC * CC;

    if (t < 3 * T_QKV) {
        int which = t / T_QKV;
        int r = t % T_QKV;
        int l = r / TPM_CC;
        int loc = r % TPM_CC;
        int n0 = (loc & 31) * 32, k0 = (loc >> 5) * 32;
        const float* W = (which == 0 ? wq : which == 1 ? wk : wv) + (size_t)l * CC * CC;
        bf16* hi = qkvh + (size_t)l * QKV_Z + (size_t)which * CC * CC;
        bf16* lo = qkvl + (size_t)l * QKV_Z + (size_t)which * CC * CC;
        transpose_tile(W, hi, lo, CC, CC, k0, n0, tbuf);
        return;
    }
    t -= 3 * T_QKV;
    if (t < T_QKV) {
        int l = t / TPM_CC, loc = t % TPM_CC;
        int n0 = (loc & 31) * 32, k0 = (loc >> 5) * 32;
        transpose_tile(wo + (size_t)l * CC * CC, woh + (size_t)l * CC * CC,
                       wol + (size_t)l * CC * CC, CC, CC, k0, n0, tbuf);
        return;
    }
    t -= T_QKV;
    if (t < T_W1) {
        int l = t / (32 * 128), loc = t % (32 * 128);
        int n0 = (loc % 128) * 32, k0 = (loc / 128) * 32;
        transpose_tile(w1 + (size_t)l * CC * FF_, w1h + (size_t)l * CC * FF_,
                       w1l + (size_t)l * CC * FF_, CC, FF_, k0, n0, tbuf);
        return;
    }
    t -= T_W1;
    if (t < T_W1) {
        int l = t / (128 * 32), loc = t % (128 * 32);
        int n0 = (loc & 31) * 32, k0 = (loc >> 5) * 32;
        transpose_tile(w2 + (size_t)l * CC * FF_, w2h + (size_t)l * CC * FF_,
                       w2l + (size_t)l * CC * FF_, FF_, CC, k0, n0, tbuf);
        return;
    }
    t -= T_W1;
    if (t < T_LM) {
        int n0 = (t % 500) * 32, k0 = (t / 500) * 32;
        transpose_tile(lm_w, lmh, lml, CC, VV, k0, n0, tbuf);
        return;
    }
    t -= T_LM;
    if (t < T_PATCH) {
        int base = t * 1024;
        int tid = threadIdx.y * 32 + threadIdx.x;
        #pragma unroll
        for (int i = 0; i < 4; i++) {
            int idx = base + tid + i * 256;
            split_store(pwh, pwl, idx, patch_w[idx]);
        }
        return;
    }
    t -= T_PATCH;
    {
        int tid = threadIdx.y * 32 + threadIdx.x;
        #pragma unroll
        for (int i = 0; i < 4; i++) {
            int idx = t * 1024 + tid + i * 256;
            int k = idx % KIM;
            int bn = idx / KIM;
            int n = bn % NPATCH;
            int b = bn / NPATCH;
            int ci = k >> 8;
            int rr = k & 255;
            int kh = rr >> 4;
            int kw = rr & 15;
            int ph = n / 21, pw = n % 21;
            float v = images[(((size_t)b * 3 + ci) * IMG + ph * PATCH + kh) * IMG + pw * PATCH + kw];
            split_store(imh, iml, idx, v);
        }
    }
}

// ---------------- host-side launchers ----------------
static inline void tci8(const int8_t* Ah, const int8_t* Al, const float* sA,
                        const int8_t* Bh, const int8_t* Bl, const float* sB,
                        const float* bias, const float* res,
                        float* outF, bf16* outH, bf16* outL,
                        int M, int N, int K, int ldc, int relu = 0, int outMode = 0,
                        bf16* okh = nullptr, bf16* okl = nullptr,
                        bf16* ovh = nullptr, bf16* ovl = nullptr)
{
    dim3 grid((N + 63) / 64, (M + 127) / 128);
    gemm_i8<<<grid, 256, SMEM_I8>>>(Ah, Al, sA, Bh, Bl, sB, bias, res,
        outF, outH, outL, okh, okl, ovh, ovl, M, N, K, ldc, relu, outMode);
}

#define SYM(name) ({ void* _p; cudaGetSymbolAddress(&_p, name); _p; })

extern "C" void kernel_launch(void* const* d_in, const int* in_sizes, int n_in,
                              void* d_out, int out_size)
{
    const int*   text_tokens = (const int*)  d_in[0];
    const float* images      = (const float*)d_in[1];
    const float* tok_emb     = (const float*)d_in[2];
    const float* txt_pos     = (const float*)d_in[3];
    const float* img_pos     = (const float*)d_in[4];
    const float* patch_w     = (const float*)d_in[5];
    const float* patch_b     = (const float*)d_in[6];
    const float* ln1_g       = (const float*)d_in[7];
    const float* ln1_b       = (const float*)d_in[8];
    const float* wq          = (const float*)d_in[9];
    const float* wk          = (const float*)d_in[10];
    const float* wv          = (const float*)d_in[11];
    const float* wo          = (const float*)d_in[12];
    const float* bo          = (const float*)d_in[13];
    const float* ln2_g       = (const float*)d_in[14];
    const float* ln2_b       = (const float*)d_in[15];
    const float* w1          = (const float*)d_in[16];
    const float* b1          = (const float*)d_in[17];
    const float* w2          = (const float*)d_in[18];
    const float* b2          = (const float*)d_in[19];
    const float* lnf_g       = (const float*)d_in[20];
    const float* lnf_b       = (const float*)d_in[21];
    const float* lm_w        = (const float*)d_in[22];
    const float* lm_b        = (const float*)d_in[23];
    float* out = (float*)d_out;

    cudaFuncSetAttribute(gemm_i8, cudaFuncAttributeMaxDynamicSharedMemorySize, SMEM_I8);
    const int FLASH_SMEM = (2 * 128 * LDF + 2 * 4 * 64 * LDF) * 2;
    cudaFuncSetAttribute(flash_attn_k, cudaFuncAttributeMaxDynamicSharedMemorySize, FLASH_SMEM);

    float* px   = (float*)SYM(g_x);
    float* ppp  = (float*)SYM(g_pp);
    bf16 *pqh = (bf16*)SYM(g_qh), *pql = (bf16*)SYM(g_ql);
    bf16 *pkh = (bf16*)SYM(g_kh), *pkl = (bf16*)SYM(g_kl);
    bf16 *pvth = (bf16*)SYM(g_vth), *pvtl = (bf16*)SYM(g_vtl);
    bf16 *pah = (bf16*)SYM(g_ah), *pal = (bf16*)SYM(g_al);
    bf16 *pfh = (bf16*)SYM(g_fh), *pfl = (bf16*)SYM(g_fl);
    bf16 *pwqkvh = (bf16*)SYM(g_wqkvh), *pwqkvl = (bf16*)SYM(g_wqkvl);
    bf16 *pwoh = (bf16*)SYM(g_woh), *pwol = (bf16*)SYM(g_wol);
    bf16 *pw1h = (bf16*)SYM(g_w1h), *pw1l = (bf16*)SYM(g_w1l);
    bf16 *pw2h = (bf16*)SYM(g_w2h), *pw2l = (bf16*)SYM(g_w2l);
    bf16 *plmh = (bf16*)SYM(g_lmh), *plml = (bf16*)SYM(g_lml);
    bf16 *ppwh = (bf16*)SYM(g_pwh), *ppwl = (bf16*)SYM(g_pwl);
    bf16 *pimh = (bf16*)SYM(g_imh), *piml = (bf16*)SYM(g_iml);

    int8_t *iah = (int8_t*)SYM(g_iah), *ial = (int8_t*)SYM(g_ial);
    float  *sAct = (float*)SYM(g_sAct);
    int8_t *imqh = (int8_t*)SYM(g_imqh), *imql = (int8_t*)SYM(g_imql);
    float  *sIm = (float*)SYM(g_sIm);
    int8_t *iwqkvh = (int8_t*)SYM(g_iwqkvh), *iwqkvl = (int8_t*)SYM(g_iwqkvl);
    float  *sWqkv = (float*)SYM(g_sWqkv);
    int8_t *iwoh = (int8_t*)SYM(g_iwoh), *iwol = (int8_t*)SYM(g_iwol);
    float  *sWo = (float*)SYM(g_sWo);
    int8_t *iw1h = (int8_t*)SYM(g_iw1h), *iw1l = (int8_t*)SYM(g_iw1l);
    float  *sW1 = (float*)SYM(g_sW1);
    int8_t *iw2h = (int8_t*)SYM(g_iw2h), *iw2l = (int8_t*)SYM(g_iw2l);
    float  *sW2 = (float*)SYM(g_sW2);
    int8_t *ilmh = (int8_t*)SYM(g_ilmh), *ilml = (int8_t*)SYM(g_ilml);
    float  *sLm = (float*)SYM(g_sLm);
    int8_t *ipwh = (int8_t*)SYM(g_ipwh), *ipwl = (int8_t*)SYM(g_ipwl);
    float  *sPw = (float*)SYM(g_sPw);

    // ---- [1] weight prep (bf16 staging) + im2col ----
    const int nPrep = 4 * T_QKV + 2 * T_W1 + T_LM + T_PATCH + T_IM2C;
    prep_weights_k<<<nPrep, dim3(32, 8)>>>(wq, wk, wv, wo, w1, w2, lm_w, patch_w, images,
        pwqkvh, pwqkvl, pwoh, pwol, pw1h, pw1l, pw2h, pw2l, plmh, plml, ppwh, ppwl,
        pimh, piml);

    // ---- [2] quantize weights + im2col to int8 ----
    quant_rows_k<<<LL*3*CC, 256>>>(pwqkvh, pwqkvl, iwqkvh, iwqkvl, sWqkv, CC);
    quant_rows_k<<<LL*CC,  256>>>(pwoh, pwol, iwoh, iwol, sWo, CC);
    quant_rows_k<<<LL*FF_, 256>>>(pw1h, pw1l, iw1h, iw1l, sW1, CC);
    quant_rows_k<<<LL*CC,  256>>>(pw2h, pw2l, iw2h, iw2l, sW2, FF_);
    quant_rows_k<<<VV,     256>>>(plmh, plml, ilmh, ilml, sLm, CC);
    quant_rows_k<<<CC,     256>>>(ppwh, ppwl, ipwh, ipwl, sPw, KIM);
    quant_rows_k<<<BB*NPATCH, 256>>>(pimh, piml, imqh, imql, sIm, KIM);

    // ---- [3] patch GEMM (int8)  [4] fused embed+LN1(l=0)+quant ----
    tci8(imqh, imql, sIm, ipwh, ipwl, sPw, patch_b, nullptr, ppp, nullptr, nullptr,
         BB*NPATCH, CC, KIM, CC);
    embed_ln_quant_k<<<BB*TT, 256>>>(text_tokens, tok_emb, txt_pos, img_pos, ppp,
                                     ln1_g, ln1_b, px, iah, ial, sAct);

    const int M = MTOK;
    for (int l = 0; l < LL; l++) {
        size_t wOff = (size_t)l * CC * CC, w1Off = (size_t)l * CC * FF_;
        size_t qkvOff = (size_t)l * 3 * CC * CC;

        if (l > 0)
            layernorm_quant_k<<<M, 256>>>(px, ln1_g + l*CC, ln1_b + l*CC, iah, ial, sAct);

        // fused q|k|v projection (int8) with direct split-bf16 scatter
        tci8(iah, ial, sAct, iwqkvh + qkvOff, iwqkvl + qkvOff, sWqkv + (size_t)l*3*CC,
             nullptr, nullptr, nullptr, pqh, pql, M, 3*CC, CC, 0, 0, /*outMode*/1,
             pkh, pkl, pvth, pvtl);

        flash_attn_k<<<BB*HH*8, 256, FLASH_SMEM>>>(
            pqh, pql, pkh, pkl, pvth, pvtl, pah, pal);

        // quantize attention output rows, then Wo (int8) + bias + residual
        quant_rows_k<<<M, 256>>>(pah, pal, iah, ial, sAct, CC);
        tci8(iah, ial, sAct, iwoh + wOff, iwol + wOff, sWo + (size_t)l*CC,
             bo + l*CC, px, px, nullptr, nullptr, M, CC, CC, CC);

        layernorm_quant_k<<<M, 256>>>(px, ln2_g + l*CC, ln2_b + l*CC, iah, ial, sAct);

        // FFN1 (int8, relu) -> split bf16 -> quantize -> FFN2 (int8) + residual
        tci8(iah, ial, sAct, iw1h + w1Off, iw1l + w1Off, sW1 + (size_t)l*FF_,
             b1 + l*FF_, nullptr, nullptr, pfh, pfl, M, FF_, CC, FF_, /*relu*/1);
        quant_rows_k<<<M, 256>>>(pfh, pfl, iah, ial, sAct, FF_);
        tci8(iah, ial, sAct, iw2h + w1Off, iw2l + w1Off, sW2 + (size_t)l*CC,
             b2 + l*CC, px, px, nullptr, nullptr, M, CC, FF_, CC);
    }

    // ---- final LN + LM head (int8) ----
    layernorm_quant_k<<<M, 256>>>(px, lnf_g, lnf_b, iah, ial, sAct);
    tci8(iah, ial, sAct, ilmh, ilml, sLm, lm_b, nullptr, out, nullptr, nullptr,
         M, VV, CC, VV);
}

// round 14
// speedup vs baseline: 2.1455x; 2.1455x over previous
#include <cuda_runtime.h>
#include <cuda_bf16.h>
#include <cstdint>

typedef __nv_bfloat16 bf16;

// ---------------- problem constants ----------------
#define BB    4
#define TT    1024
#define CC    1024
#define HH    16
#define HD    64
#define LL    6
#define VV    16000
#define FF_   4096
#define TTXT  580
#define NPATCH 441
#define KIM   768
#define IMG   336
#define PATCH 16
#define MTOK  (BB*TT)          // 4096

// ---------------- scratch (device globals; no allocation) ----------------
__device__ float g_x  [(size_t)MTOK*CC];
__device__ float g_pp [(size_t)BB*NPATCH*CC];

__device__ bf16 g_qh[(size_t)MTOK*CC], g_ql[(size_t)MTOK*CC];
__device__ bf16 g_kh[(size_t)MTOK*CC], g_kl[(size_t)MTOK*CC];
__device__ bf16 g_vth[(size_t)MTOK*CC], g_vtl[(size_t)MTOK*CC];
__device__ bf16 g_ah[(size_t)MTOK*CC], g_al[(size_t)MTOK*CC];
__device__ bf16 g_fh[(size_t)MTOK*FF_], g_fl[(size_t)MTOK*FF_];

__device__ bf16 g_wqkvh[(size_t)LL*3*CC*CC], g_wqkvl[(size_t)LL*3*CC*CC];
__device__ bf16 g_woh[(size_t)LL*CC*CC], g_wol[(size_t)LL*CC*CC];
__device__ bf16 g_w1h[(size_t)LL*CC*FF_], g_w1l[(size_t)LL*CC*FF_];
__device__ bf16 g_w2h[(size_t)LL*CC*FF_], g_w2l[(size_t)LL*CC*FF_];
__device__ bf16 g_lmh[(size_t)CC*VV],    g_lml[(size_t)CC*VV];
__device__ bf16 g_pwh[(size_t)CC*KIM],   g_pwl[(size_t)CC*KIM];
__device__ bf16 g_imh[(size_t)BB*NPATCH*KIM], g_iml[(size_t)BB*NPATCH*KIM];

// ---------------- low-level helpers ----------------
__device__ __forceinline__ uint32_t smem_u32(const void* p) {
    uint32_t a;
    asm("{ .reg .u64 t; cvta.to.shared.u64 t, %1; cvt.u32.u64 %0, t; }" : "=r"(a) : "l"(p));
    return a;
}
__device__ __forceinline__ void cpa16(uint32_t dst, const void* src, int szbytes) {
    asm volatile("cp.async.cg.shared.global [%0], [%1], 16, %2;"
                 :: "r"(dst), "l"(src), "r"(szbytes) : "memory");
}
__device__ __forceinline__ void ldsm4(uint32_t (&r)[4], uint32_t addr) {
    asm volatile("ldmatrix.sync.aligned.m8n8.x4.shared.b16 {%0,%1,%2,%3}, [%4];"
                 : "=r"(r[0]), "=r"(r[1]), "=r"(r[2]), "=r"(r[3]) : "r"(addr));
}
__device__ __forceinline__ void mma_bf16(float (&d)[4], const uint32_t (&a)[4],
                                         uint32_t b0, uint32_t b1) {
    asm volatile("mma.sync.aligned.m16n8k16.row.col.f32.bf16.bf16.f32 "
                 "{%0,%1,%2,%3}, {%4,%5,%6,%7}, {%8,%9}, {%0,%1,%2,%3};"
                 : "+f"(d[0]), "+f"(d[1]), "+f"(d[2]), "+f"(d[3])
                 : "r"(a[0]), "r"(a[1]), "r"(a[2]), "r"(a[3]), "r"(b0), "r"(b1));
}
__device__ __forceinline__ uint32_t pack_split(float v0, float v1, uint32_t& lw) {
    bf16 h0 = __float2bfloat16(v0), h1 = __float2bfloat16(v1);
    float r0 = v0 - __bfloat162float(h0), r1 = v1 - __bfloat162float(h1);
    bf16 l0 = __float2bfloat16(r0), l1 = __float2bfloat16(r1);
    lw = (uint32_t)__bfloat16_as_ushort(l0) | ((uint32_t)__bfloat16_as_ushort(l1) << 16);
    return (uint32_t)__bfloat16_as_ushort(h0) | ((uint32_t)__bfloat16_as_ushort(h1) << 16);
}

// ---------------- split-bf16 tensor-core GEMM (mma.sync) ----------------
#define LDS 40
#define BM  128
#define BN_ 128

// outMode: 0 = normal; 1 = QKV scatter (split q,k at [b,h,t,d], vt at [b,h,d,t])
__global__ __launch_bounds__(256, 2)
void gemm_mma(const bf16* __restrict__ Ah, const bf16* __restrict__ Al,
              const bf16* __restrict__ Bh, const bf16* __restrict__ Bl,
              const float* __restrict__ bias, const float* __restrict__ res,
              float* __restrict__ outF, bf16* __restrict__ outH, bf16* __restrict__ outL,
              bf16* __restrict__ okh, bf16* __restrict__ okl,
              bf16* __restrict__ ovh, bf16* __restrict__ ovl,
              int M, int Nfull, int K, int ldc,
              float alpha, int relu, int outMode)
{
    constexpr int MI = 2;            // warp tile 32x64
    constexpr int NI = 8;
    constexpr int ASZ = BM * LDS;
    constexpr int BSZ = BN_ * LDS;

    const int m0 = blockIdx.y * BM;
    const int n0 = blockIdx.x * BN_;

    extern __shared__ bf16 sm[];
    const uint32_t sbase = smem_u32(sm);

    const int tid = threadIdx.x;
    const int nch = K >> 5;

    auto load_stage = [&](int st, int k0) {
        #pragma unroll
        for (int i = tid; i < BM * 4; i += 256) {
            int r = i >> 2, c8 = (i & 3) << 3;
            int gr = m0 + r;
            int ok = (gr < M) ? 16 : 0;
            if (gr >= M) gr = m0;
            size_t go = (size_t)gr * K + k0 + c8;
            uint32_t so = (uint32_t)((st * ASZ + r * LDS + c8) * 2);
            cpa16(sbase + so, Ah + go, ok);
            cpa16(sbase + so + 2 * ASZ * 2, Al + go, ok);
        }
        #pragma unroll
        for (int i = tid; i < BN_ * 4; i += 256) {
            int r = i >> 2, c8 = (i & 3) << 3;
            int gn = n0 + r;
            int ok = (gn < Nfull) ? 16 : 0;
            if (gn >= Nfull) gn = n0;
            size_t go = (size_t)gn * K + k0 + c8;
            uint32_t so = (uint32_t)((4 * ASZ + st * BSZ + r * LDS + c8) * 2);
            cpa16(sbase + so, Bh + go, ok);
            cpa16(sbase + so + 2 * BSZ * 2, Bl + go, ok);
        }
        asm volatile("cp.async.commit_group;" ::: "memory");
    };

    const int wid = tid >> 5, lane = tid & 31;
    const int wr = wid & 3, wc = wid >> 2;
    const int wmBase = wr * 32, wnBase = wc * 64;

    float acc[MI][NI][4];
    #pragma unroll
    for (int mi = 0; mi < MI; mi++)
        #pragma unroll
        for (int ni = 0; ni < NI; ni++)
            #pragma unroll
            for (int j = 0; j < 4; j++) acc[mi][ni][j] = 0.f;

    load_stage(0, 0);

    for (int ch = 0; ch < nch; ch++) {
        asm volatile("cp.async.wait_group 0;" ::: "memory");
        __syncthreads();
        if (ch + 1 < nch) load_stage((ch + 1) & 1, (ch + 1) << 5);

        const int st = ch & 1;
        const uint32_t aHb = sbase + (uint32_t)(st * ASZ * 2);
        const uint32_t aLb = aHb + (uint32_t)(2 * ASZ * 2);
        const uint32_t bHb = sbase + (uint32_t)((4 * ASZ + st * BSZ) * 2);
        const uint32_t bLb = bHb + (uint32_t)(2 * BSZ * 2);

        #pragma unroll
        for (int kk = 0; kk < 2; kk++) {
            const int colOff = kk * 16 + ((lane >> 4) << 3);
            uint32_t afH[MI][4], afL[MI][4];
            #pragma unroll
            for (int mi = 0; mi < MI; mi++) {
                uint32_t off = (uint32_t)(((wmBase + mi * 16 + (lane & 15)) * LDS + colOff) * 2);
                ldsm4(afH[mi], aHb + off);
                ldsm4(afL[mi], aLb + off);
            }
            uint32_t bfH[4][4], bfL[4][4];
            #pragma unroll
            for (int nj = 0; nj < 4; nj++) {
                uint32_t off = (uint32_t)(((wnBase + nj * 16 + (lane & 15)) * LDS + colOff) * 2);
                ldsm4(bfH[nj], bHb + off);
                ldsm4(bfL[nj], bLb + off);
            }
            #pragma unroll
            for (int nj = 0; nj < 4; nj++) {
                #pragma unroll
                for (int mi = 0; mi < MI; mi++) {
                    mma_bf16(acc[mi][2*nj],   afH[mi], bfH[nj][0], bfH[nj][2]);
                    mma_bf16(acc[mi][2*nj+1], afH[mi], bfH[nj][1], bfH[nj][3]);
                }
                #pragma unroll
                for (int mi = 0; mi < MI; mi++) {
                    mma_bf16(acc[mi][2*nj],   afH[mi], bfL[nj][0], bfL[nj][2]);
                    mma_bf16(acc[mi][2*nj+1], afH[mi], bfL[nj][1], bfL[nj][3]);
                }
                #pragma unroll
                for (int mi = 0; mi < MI; mi++) {
                    mma_bf16(acc[mi][2*nj],   afL[mi], bfH[nj][0], bfH[nj][2]);
                    mma_bf16(acc[mi][2*nj+1], afL[mi], bfH[nj][1], bfH[nj][3]);
                }
            }
        }
    }

    // epilogue
    const int g = lane >> 2, t4 = lane & 3;
    #pragma unroll
    for (int mi = 0; mi < MI; mi++) {
        #pragma unroll
        for (int ni = 0; ni < NI; ni++) {
            int col = n0 + wnBase + ni * 8 + t4 * 2;
            if (col >= Nfull) continue;
            #pragma unroll
            for (int half = 0; half < 2; half++) {
                int row = m0 + wmBase + mi * 16 + g + half * 8;
                if (row >= M) continue;
                float v0 = acc[mi][ni][half * 2 + 0] * alpha;
                float v1 = acc[mi][ni][half * 2 + 1] * alpha;
                if (outMode == 1) {
                    int which = col >> 10;
                    int c = col & 1023;
                    int h = c >> 6, d = c & 63;
                    int b = row >> 10, t = row & 1023;
                    uint32_t lw;
                    uint32_t hw = pack_split(v0, v1, lw);
                    if (which < 2) {
                        size_t base = (((size_t)(b * HH + h)) * TT + t) * HD + d;
                        bf16* H = which ? okh : outH;
                        bf16* L = which ? okl : outL;
                        *(uint32_t*)(H + base) = hw;
                        *(uint32_t*)(L + base) = lw;
                    } else {
                        size_t vb = (((size_t)(b * HH + h)) * HD + d) * TT + t;
                        ovh[vb]      = __ushort_as_bfloat16((unsigned short)(hw & 0xffff));
                        ovh[vb + TT] = __ushort_as_bfloat16((unsigned short)(hw >> 16));
                        ovl[vb]      = __ushort_as_bfloat16((unsigned short)(lw & 0xffff));
                        ovl[vb + TT] = __ushort_as_bfloat16((unsigned short)(lw >> 16));
                    }
                } else {
                    long long base = (long long)row * ldc + col;
                    if (bias) { v0 += bias[col]; v1 += bias[col + 1]; }
                    if (res)  { v0 += res[base]; v1 += res[base + 1]; }
                    if (relu) { v0 = fmaxf(v0, 0.f); v1 = fmaxf(v1, 0.f); }
                    if (outF) *(float2*)(outF + base) = make_float2(v0, v1);
                    if (outH) {
                        uint32_t lw;
                        uint32_t hw = pack_split(v0, v1, lw);
                        *(uint32_t*)(outH + base) = hw;
                        *(uint32_t*)(outL + base) = lw;
                    }
                }
            }
        }
    }
}

// ---------------- fused flash attention (register-P, 2 CTA/SM, longest-first) ----------------
#define LDF 72
__global__ __launch_bounds__(256, 2)
void flash_attn_k(const bf16* __restrict__ qh, const bf16* __restrict__ ql,
                  const bf16* __restrict__ kh, const bf16* __restrict__ kl,
                  const bf16* __restrict__ vth, const bf16* __restrict__ vtl,
                  bf16* __restrict__ oh, bf16* __restrict__ ol)
{
    extern __shared__ bf16 sm[];
    const uint32_t sbase = smem_u32(sm);
    const int id = blockIdx.x;
    const int rb = 7 - (id >> 6);      // heavy diagonal blocks first
    const int bh = id & 63;
    const int m0 = rb * 128;
    const int tid = threadIdx.x, wid = tid >> 5, lane = tid & 31;
    const int g = lane >> 2, t4 = lane & 3;

    const uint32_t OQH = 0, OQL = 128*LDF;
    const uint32_t OKV = 2*128*LDF;
    const uint32_t KVS = 4*64*LDF;

    for (int i = tid; i < 128 * 8; i += 256) {
        int r = i >> 3, c = (i & 7) << 3;
        size_t go = ((size_t)bh * TT + m0 + r) * HD + c;
        cpa16(sbase + (OQH + r * LDF + c) * 2, qh + go, 16);
        cpa16(sbase + (OQL + r * LDF + c) * 2, ql + go, 16);
    }
    asm volatile("cp.async.commit_group;" ::: "memory");

    auto load_kv = [&](int st, int j0) {
        uint32_t base = OKV + (uint32_t)st * KVS;
        for (int i = tid; i < 64 * 8; i += 256) {
            int r = i >> 3, c = (i & 7) << 3;
            size_t gk = ((size_t)bh * TT + j0 + r) * HD + c;
            size_t gv = ((size_t)bh * HD + r) * TT + j0 + c;
            cpa16(sbase + (base            + r * LDF + c) * 2, kh  + gk, 16);
            cpa16(sbase + (base +   64*LDF + r * LDF + c) * 2, kl  + gk, 16);
            cpa16(sbase + (base + 2*64*LDF + r * LDF + c) * 2, vth + gv, 16);
            cpa16(sbase + (base + 3*64*LDF + r * LDF + c) * 2, vtl + gv, 16);
        }
        asm volatile("cp.async.commit_group;" ::: "memory");
    };

    const int ntiles = 2 * rb + 2;
    load_kv(0, 0);

    float oacc[8][4];
    #pragma unroll
    for (int ni = 0; ni < 8; ni++)
        #pragma unroll
        for (int j = 0; j < 4; j++) oacc[ni][j] = 0.f;
    float mrow[2] = { -1e30f, -1e30f };
    float lrow[2] = { 0.f, 0.f };

    const int row0 = m0 + wid * 16 + g;

    for (int t = 0; t < ntiles; t++) {
        const int j0 = t << 6;
        asm volatile("cp.async.wait_group 0;" ::: "memory");
        __syncthreads();
        if (t + 1 < ntiles) load_kv((t + 1) & 1, j0 + 64);

        const uint32_t kvb = OKV + (uint32_t)(t & 1) * KVS;
        const uint32_t kHb = sbase + kvb * 2;
        const uint32_t kLb = sbase + (kvb + 64*LDF) * 2;
        const uint32_t vHb = sbase + (kvb + 2*64*LDF) * 2;
        const uint32_t vLb = sbase + (kvb + 3*64*LDF) * 2;

        float acc[8][4];
        #pragma unroll
        for (int ni = 0; ni < 8; ni++)
            #pragma unroll
            for (int j = 0; j < 4; j++) acc[ni][j] = 0.f;

        #pragma unroll
        for (int kk = 0; kk < 4; kk++) {
            const int colOff = kk * 16 + ((lane >> 4) << 3);
            uint32_t aH[4], aL[4];
            uint32_t aoff = (uint32_t)(((wid * 16 + (lane & 15)) * LDF + colOff) * 2);
            ldsm4(aH, sbase + (OQH * 2) + aoff);
            ldsm4(aL, sbase + (OQL * 2) + aoff);
            uint32_t bH[4][4], bL[4][4];
            #pragma unroll
            for (int nj = 0; nj < 4; nj++) {
                uint32_t boff = (uint32_t)(((nj * 16 + (lane & 15)) * LDF + colOff) * 2);
                ldsm4(bH[nj], kHb + boff);
                ldsm4(bL[nj], kLb + boff);
            }
            #pragma unroll
            for (int nj = 0; nj < 4; nj++) {
                mma_bf16(acc[2*nj],   aH, bH[nj][0], bH[nj][2]);
                mma_bf16(acc[2*nj+1], aH, bH[nj][1], bH[nj][3]);
                mma_bf16(acc[2*nj],   aH, bL[nj][0], bL[nj][2]);
                mma_bf16(acc[2*nj+1], aH, bL[nj][1], bL[nj][3]);
                mma_bf16(acc[2*nj],   aL, bH[nj][0], bH[nj][2]);
                mma_bf16(acc[2*nj+1], aL, bH[nj][1], bH[nj][3]);
            }
        }

        #pragma unroll
        for (int ni = 0; ni < 8; ni++) {
            int colBase = j0 + ni * 8 + t4 * 2;
            #pragma unroll
            for (int j = 0; j < 4; j++) {
                int row = row0 + ((j >> 1) << 3);
                int col = colBase + (j & 1);
                float v = acc[ni][j] * 0.125f;
                acc[ni][j] = (col <= row) ? v : -1e30f;
            }
        }

        #pragma unroll
        for (int half = 0; half < 2; half++) {
            float mt = -1e30f;
            #pragma unroll
            for (int ni = 0; ni < 8; ni++) {
                mt = fmaxf(mt, acc[ni][half*2+0]);
                mt = fmaxf(mt, acc[ni][half*2+1]);
            }
            mt = fmaxf(mt, __shfl_xor_sync(0xffffffffu, mt, 1));
            mt = fmaxf(mt, __shfl_xor_sync(0xffffffffu, mt, 2));
            float mnew = fmaxf(mrow[half], mt);
            float scale = __expf(mrow[half] - mnew);
            mrow[half] = mnew;
            float sum = 0.f;
            #pragma unroll
            for (int ni = 0; ni < 8; ni++) {
                float e0 = __expf(acc[ni][half*2+0] - mnew);
                float e1 = __expf(acc[ni][half*2+1] - mnew);
                acc[ni][half*2+0] = e0;
                acc[ni][half*2+1] = e1;
                sum += e0 + e1;
            }
            sum += __shfl_xor_sync(0xffffffffu, sum, 1);
            sum += __shfl_xor_sync(0xffffffffu, sum, 2);
            lrow[half] = lrow[half] * scale + sum;
            #pragma unroll
            for (int ni = 0; ni < 8; ni++) {
                oacc[ni][half*2+0] *= scale;
                oacc[ni][half*2+1] *= scale;
            }
        }

        #pragma unroll
        for (int kk = 0; kk < 4; kk++) {
            uint32_t aH[4], aL[4];
            aH[0] = pack_split(acc[2*kk][0],   acc[2*kk][1],   aL[0]);
            aH[1] = pack_split(acc[2*kk][2],   acc[2*kk][3],   aL[1]);
            aH[2] = pack_split(acc[2*kk+1][0], acc[2*kk+1][1], aL[2]);
            aH[3] = pack_split(acc[2*kk+1][2], acc[2*kk+1][3], aL[3]);
            const int colOff = kk * 16 + ((lane >> 4) << 3);
            uint32_t bH[4][4], bL[4][4];
            #pragma unroll
            for (int nj = 0; nj < 4; nj++) {
                uint32_t boff = (uint32_t)(((nj * 16 + (lane & 15)) * LDF + colOff) * 2);
                ldsm4(bH[nj], vHb + boff);
                ldsm4(bL[nj], vLb + boff);
            }
            #pragma unroll
            for (int nj = 0; nj < 4; nj++) {
                mma_bf16(oacc[2*nj],   aH, bH[nj][0], bH[nj][2]);
                mma_bf16(oacc[2*nj+1], aH, bH[nj][1], bH[nj][3]);
                mma_bf16(oacc[2*nj],   aH, bL[nj][0], bL[nj][2]);
                mma_bf16(oacc[2*nj+1], aH, bL[nj][1], bL[nj][3]);
                mma_bf16(oacc[2*nj],   aL, bH[nj][0], bH[nj][2]);
                mma_bf16(oacc[2*nj+1], aL, bH[nj][1], bH[nj][3]);
            }
        }
    }

    const int b = bh >> 4, h = bh & 15;
    float inv0 = 1.f / lrow[0], inv1 = 1.f / lrow[1];
    #pragma unroll
    for (int ni = 0; ni < 8; ni++) {
        int d = ni * 8 + t4 * 2;
        #pragma unroll
        for (int half = 0; half < 2; half++) {
            int trow = m0 + wid * 16 + g + half * 8;
            float inv = half ? inv1 : inv0;
            size_t base = ((size_t)b * TT + trow) * CC + h * HD + d;
            uint32_t lw;
            uint32_t hw = pack_split(oacc[ni][half*2+0] * inv,
                                     oacc[ni][half*2+1] * inv, lw);
            *(uint32_t*)(oh + base) = hw;
            *(uint32_t*)(ol + base) = lw;
        }
    }
}

// ---------------- block reductions ----------------
__device__ __forceinline__ float blockReduceSum256(float v, float* sh) {
    #pragma unroll
    for (int o = 16; o > 0; o >>= 1) v += __shfl_xor_sync(0xffffffffu, v, o);
    int w = threadIdx.x >> 5;
    if ((threadIdx.x & 31) == 0) sh[w] = v;
    __syncthreads();
    if (threadIdx.x < 8) {
        v = sh[threadIdx.x];
        #pragma unroll
        for (int o = 4; o > 0; o >>= 1) v += __shfl_xor_sync(0xffu, v, o);
        if (threadIdx.x == 0) sh[0] = v;
    }
    __syncthreads();
    float r = sh[0]; __syncthreads(); return r;
}

__device__ __forceinline__ void split_store(bf16* H, bf16* L, size_t i, float v) {
    bf16 h = __float2bfloat16(v);
    H[i] = h;
    L[i] = __float2bfloat16(v - __bfloat162float(h));
}

// ---------------- layernorm -> split bf16 ----------------
__global__ __launch_bounds__(256)
void layernorm_split_k(const float* __restrict__ x, const float* __restrict__ g,
                       const float* __restrict__ b, bf16* __restrict__ oh, bf16* __restrict__ ol)
{
    __shared__ float sh[8];
    const size_t row = blockIdx.x;
    const float* xr = x + row * CC;
    const int c = threadIdx.x * 4;
    float4 xv = *(const float4*)(xr + c);
    float s  = xv.x + xv.y + xv.z + xv.w;
    float ss = xv.x*xv.x + xv.y*xv.y + xv.z*xv.z + xv.w*xv.w;
    s = blockReduceSum256(s, sh);
    ss = blockReduceSum256(ss, sh);
    float mean = s * (1.f / CC);
    float var = ss * (1.f / CC) - mean * mean;
    float inv = rsqrtf(var + 1e-5f);
    float4 gv = *(const float4*)(g + c);
    float4 bv = *(const float4*)(b + c);
    size_t base = row * CC + c;
    split_store(oh, ol, base + 0, (xv.x - mean) * inv * gv.x + bv.x);
    split_store(oh, ol, base + 1, (xv.y - mean) * inv * gv.y + bv.y);
    split_store(oh, ol, base + 2, (xv.z - mean) * inv * gv.z + bv.z);
    split_store(oh, ol, base + 3, (xv.w - mean) * inv * gv.w + bv.w);
}

// ---------------- fused embed + layer0 LN1 -> x and split bf16 ----------------
__global__ __launch_bounds__(256)
void embed_ln_k(const int* __restrict__ toks, const float* __restrict__ tok_emb,
                const float* __restrict__ txt_pos, const float* __restrict__ img_pos,
                const float* __restrict__ p, const float* __restrict__ g,
                const float* __restrict__ b,
                float* __restrict__ x, bf16* __restrict__ oh, bf16* __restrict__ ol)
{
    __shared__ float sh[8];
    const int bt = blockIdx.x;
    const int bb = bt >> 10;
    const int t = bt & 1023;
    const int c = threadIdx.x * 4;
    const float* src;
    const float* extra = nullptr;
    if (t == 0)      src = tok_emb + 1 * CC;
    else if (t == 1) src = tok_emb + 8 * CC;
    else if (t < 443) {
        int n = t - 2;
        src = p + ((size_t)(bb * NPATCH + n)) * CC;
        extra = img_pos + (size_t)n * CC;
    }
    else if (t == 443) src = tok_emb + 9 * CC;
    else {
        int tok = toks[bb * TTXT + (t - 444)];
        src = tok_emb + (size_t)tok * CC;
    }
    float4 v = *(const float4*)(src + c);
    float4 tp = *(const float4*)(txt_pos + (size_t)t * CC + c);
    v.x += tp.x; v.y += tp.y; v.z += tp.z; v.w += tp.w;
    if (extra) {
        float4 e = *(const float4*)(extra + c);
        v.x += e.x; v.y += e.y; v.z += e.z; v.w += e.w;
    }
    size_t base = (size_t)bt * CC + c;
    *(float4*)(x + base) = v;

    float s  = v.x + v.y + v.z + v.w;
    float ss = v.x*v.x + v.y*v.y + v.z*v.z + v.w*v.w;
    s = blockReduceSum256(s, sh);
    ss = blockReduceSum256(ss, sh);
    float mean = s * (1.f / CC);
    float var = ss * (1.f / CC) - mean * mean;
    float inv = rsqrtf(var + 1e-5f);
    float4 gv = *(const float4*)(g + c);
    float4 bv = *(const float4*)(b + c);
    split_store(oh, ol, base + 0, (v.x - mean) * inv * gv.x + bv.x);
    split_store(oh, ol, base + 1, (v.y - mean) * inv * gv.y + bv.y);
    split_store(oh, ol, base + 2, (v.z - mean) * inv * gv.z + bv.z);
    split_store(oh, ol, base + 3, (v.w - mean) * inv * gv.w + bv.w);
}

// ---------------- fused weight prep + im2col in ONE launch ----------------
__device__ __forceinline__ void transpose_tile(const float* __restrict__ W,
                                               bf16* __restrict__ hi, bf16* __restrict__ lo,
                                               int K, int N, int k0, int n0,
                                               float tbuf[32][33])
{
    int tx = threadIdx.x, ty = threadIdx.y;
    #pragma unroll
    for (int i = 0; i < 32; i += 8)
        tbuf[ty + i][tx] = W[(size_t)(k0 + ty + i) * N + n0 + tx];
    __syncthreads();
    #pragma unroll
    for (int i = 0; i < 32; i += 8)
        split_store(hi, lo, (size_t)(n0 + ty + i) * K + k0 + tx, tbuf[tx][ty + i]);
}

#define TPM_CC  1024
#define T_QKV   (LL*TPM_CC)
#define T_W1    (LL*(32*128))
#define T_LM    (32*500)
#define T_PATCH 768
#define T_IM2C  ((BB*NPATCH*KIM)/1024)   // 1323

__global__ void prep_weights_k(const float* __restrict__ wq, const float* __restrict__ wk,
                               const float* __restrict__ wv, const float* __restrict__ wo,
                               const float* __restrict__ w1, const float* __restrict__ w2,
                               const float* __restrict__ lm_w, const float* __restrict__ patch_w,
                               const float* __restrict__ images,
                               bf16* qkvh, bf16* qkvl, bf16* woh, bf16* wol,
                               bf16* w1h, bf16* w1l, bf16* w2h, bf16* w2l,
                               bf16* lmh, bf16* lml, bf16* pwh, bf16* pwl,
                               bf16* imh, bf16* iml)
{
    __shared__ float tbuf[32][33];
    int t = blockIdx.x;
    const long long QKV_Z = (long long)3 * CC * CC;

    if (t < 3 * T_QKV) {
        int which = t / T_QKV;
        int r = t % T_QKV;
        int l = r / TPM_CC;
        int loc = r % TPM_CC;
        int n0 = (loc & 31) * 32, k0 = (loc >> 5) * 32;
        const float* W = (which == 0 ? wq : which == 1 ? wk : wv) + (size_t)l * CC * CC;
        bf16* hi = qkvh + (size_t)l * QKV_Z + (size_t)which * CC * CC;
        bf16* lo = qkvl + (size_t)l * QKV_Z + (size_t)which * CC * CC;
        transpose_tile(W, hi, lo, CC, CC, k0, n0, tbuf);
        return;
    }
    t -= 3 * T_QKV;
    if (t < T_QKV) {
        int l = t / TPM_CC, loc = t % TPM_CC;
        int n0 = (loc & 31) * 32, k0 = (loc >> 5) * 32;
        transpose_tile(wo + (size_t)l * CC * CC, woh + (size_t)l * CC * CC,
                       wol + (size_t)l * CC * CC, CC, CC, k0, n0, tbuf);
        return;
    }
    t -= T_QKV;
    if (t < T_W1) {
        int l = t / (32 * 128), loc = t % (32 * 128);
        int n0 = (loc % 128) * 32, k0 = (loc / 128) * 32;
        transpose_tile(w1 + (size_t)l * CC * FF_, w1h + (size_t)l * CC * FF_,
                       w1l + (size_t)l * CC * FF_, CC, FF_, k0, n0, tbuf);
        return;
    }
    t -= T_W1;
    if (t < T_W1) {
        int l = t / (128 * 32), loc = t % (128 * 32);
        int n0 = (loc & 31) * 32, k0 = (loc >> 5) * 32;
        transpose_tile(w2 + (size_t)l * CC * FF_, w2h + (size_t)l * CC * FF_,
                       w2l + (size_t)l * CC * FF_, FF_, CC, k0, n0, tbuf);
        return;
    }
    t -= T_W1;
    if (t < T_LM) {
        int n0 = (t % 500) * 32, k0 = (t / 500) * 32;
        transpose_tile(lm_w, lmh, lml, CC, VV, k0, n0, tbuf);
        return;
    }
    t -= T_LM;
    if (t < T_PATCH) {
        int base = t * 1024;
        int tid = threadIdx.y * 32 + threadIdx.x;
        #pragma unroll
        for (int i = 0; i < 4; i++) {
            int idx = base + tid + i * 256;
            split_store(pwh, pwl, idx, patch_w[idx]);
        }
        return;
    }
    t -= T_PATCH;
    {
        int tid = threadIdx.y * 32 + threadIdx.x;
        #pragma unroll
        for (int i = 0; i < 4; i++) {
            int idx = t * 1024 + tid + i * 256;
            int k = idx % KIM;
            int bn = idx / KIM;
            int n = bn % NPATCH;
            int b = bn / NPATCH;
            int ci = k >> 8;
            int rr = k & 255;
            int kh = rr >> 4;
            int kw = rr & 15;
            int ph = n / 21, pw = n % 21;
            float v = images[(((size_t)b * 3 + ci) * IMG + ph * PATCH + kh) * IMG + pw * PATCH + kw];
            split_store(imh, iml, idx, v);
        }
    }
}

// ---------------- host-side GEMM launcher ----------------
#define SMEM_GEMM  ((4 * 128 * LDS + 4 * 128 * LDS) * 2)

static inline void tc(const bf16* Ah, const bf16* Al, const bf16* Bh, const bf16* Bl,
                      const float* bias, const float* res,
                      float* outF, bf16* outH, bf16* outL,
                      int M, int N, int K, int ldc,
                      float alpha = 1.f, int relu = 0, int outMode = 0,
                      bf16* okh = nullptr, bf16* okl = nullptr,
                      bf16* ovh = nullptr, bf16* ovl = nullptr)
{
    dim3 grid((N + 127) / 128, (M + 127) / 128, 1);
    gemm_mma<<<grid, 256, SMEM_GEMM>>>(Ah, Al, Bh, Bl, bias, res,
        outF, outH, outL, okh, okl, ovh, ovl, M, N, K, ldc, alpha, relu, outMode);
}

#define SYM(name) ({ void* _p; cudaGetSymbolAddress(&_p, name); _p; })

extern "C" void kernel_launch(void* const* d_in, const int* in_sizes, int n_in,
                              void* d_out, int out_size)
{
    const int*   text_tokens = (const int*)  d_in[0];
    const float* images      = (const float*)d_in[1];
    const float* tok_emb     = (const float*)d_in[2];
    const float* txt_pos     = (const float*)d_in[3];
    const float* img_pos     = (const float*)d_in[4];
    const float* patch_w     = (const float*)d_in[5];
    const float* patch_b     = (const float*)d_in[6];
    const float* ln1_g       = (const float*)d_in[7];
    const float* ln1_b       = (const float*)d_in[8];
    const float* wq          = (const float*)d_in[9];
    const float* wk          = (const float*)d_in[10];
    const float* wv          = (const float*)d_in[11];
    const float* wo          = (const float*)d_in[12];
    const float* bo          = (const float*)d_in[13];
    const float* ln2_g       = (const float*)d_in[14];
    const float* ln2_b       = (const float*)d_in[15];
    const float* w1          = (const float*)d_in[16];
    const float* b1          = (const float*)d_in[17];
    const float* w2          = (const float*)d_in[18];
    const float* b2          = (const float*)d_in[19];
    const float* lnf_g       = (const float*)d_in[20];
    const float* lnf_b       = (const float*)d_in[21];
    const float* lm_w        = (const float*)d_in[22];
    const float* lm_b        = (const float*)d_in[23];
    float* out = (float*)d_out;

    cudaFuncSetAttribute(gemm_mma, cudaFuncAttributeMaxDynamicSharedMemorySize, SMEM_GEMM);
    const int FLASH_SMEM = (2 * 128 * LDF + 2 * 4 * 64 * LDF) * 2;
    cudaFuncSetAttribute(flash_attn_k, cudaFuncAttributeMaxDynamicSharedMemorySize, FLASH_SMEM);

    float* px   = (float*)SYM(g_x);
    float* ppp  = (float*)SYM(g_pp);
    bf16 *pqh = (bf16*)SYM(g_qh), *pql = (bf16*)SYM(g_ql);
    bf16 *pkh = (bf16*)SYM(g_kh), *pkl = (bf16*)SYM(g_kl);
    bf16 *pvth = (bf16*)SYM(g_vth), *pvtl = (bf16*)SYM(g_vtl);
    bf16 *pah = (bf16*)SYM(g_ah), *pal = (bf16*)SYM(g_al);
    bf16 *pfh = (bf16*)SYM(g_fh), *pfl = (bf16*)SYM(g_fl);
    bf16 *pwqkvh = (bf16*)SYM(g_wqkvh), *pwqkvl = (bf16*)SYM(g_wqkvl);
    bf16 *pwoh = (bf16*)SYM(g_woh), *pwol = (bf16*)SYM(g_wol);
    bf16 *pw1h = (bf16*)SYM(g_w1h), *pw1l = (bf16*)SYM(g_w1l);
    bf16 *pw2h = (bf16*)SYM(g_w2h), *pw2l = (bf16*)SYM(g_w2l);
    bf16 *plmh = (bf16*)SYM(g_lmh), *plml = (bf16*)SYM(g_lml);
    bf16 *ppwh = (bf16*)SYM(g_pwh), *ppwl = (bf16*)SYM(g_pwl);
    bf16 *pimh = (bf16*)SYM(g_imh), *piml = (bf16*)SYM(g_iml);

    // ---- [1] all weight prep + im2col in one launch ----
    const int nPrep = 4 * T_QKV + 2 * T_W1 + T_LM + T_PATCH + T_IM2C;
    prep_weights_k<<<nPrep, dim3(32, 8)>>>(wq, wk, wv, wo, w1, w2, lm_w, patch_w, images,
        pwqkvh, pwqkvl, pwoh, pwol, pw1h, pw1l, pw2h, pw2l, plmh, plml, ppwh, ppwl,
        pimh, piml);

    // ---- [2] patch GEMM  [3] fused embed+LN1(l=0) ----
    tc(pimh, piml, ppwh, ppwl, patch_b, nullptr, ppp, nullptr, nullptr,
       BB*NPATCH, CC, KIM, CC);
    embed_ln_k<<<BB*TT, 256>>>(text_tokens, tok_emb, txt_pos, img_pos, ppp,
                               ln1_g, ln1_b, px, pah, pal);

    const int M = MTOK;
    for (int l = 0; l < LL; l++) {
        size_t wOff = (size_t)l * CC * CC, w1Off = (size_t)l * CC * FF_;
        size_t qkvOff = (size_t)l * 3 * CC * CC;

        if (l > 0)
            layernorm_split_k<<<M, 256>>>(px, ln1_g + l*CC, ln1_b + l*CC, pah, pal);

        // fused q|k|v projection with direct split scatter
        tc(pah, pal, pwqkvh + qkvOff, pwqkvl + qkvOff, nullptr, nullptr,
           nullptr, pqh, pql, M, 3*CC, CC, 0, 1.f, 0, /*outMode*/1,
           pkh, pkl, pvth, pvtl);

        flash_attn_k<<<BB*HH*8, 256, FLASH_SMEM>>>(
            pqh, pql, pkh, pkl, pvth, pvtl, pah, pal);

        tc(pah, pal, pwoh + wOff, pwol + wOff, bo + l*CC, px, px, nullptr, nullptr,
           M, CC, CC, CC);

        layernorm_split_k<<<M, 256>>>(px, ln2_g + l*CC, ln2_b + l*CC, pah, pal);

        tc(pah, pal, pw1h + w1Off, pw1l + w1Off, b1 + l*FF_, nullptr,
           nullptr, pfh, pfl, M, FF_, CC, FF_, 1.f, /*relu*/1);
        tc(pfh, pfl, pw2h + w1Off, pw2l + w1Off, b2 + l*CC, px, px, nullptr, nullptr,
           M, CC, FF_, CC);
    }

    layernorm_split_k<<<M, 256>>>(px, lnf_g, lnf_b, pah, pal);
    tc(pah, pal, plmh, plml, lm_b, nullptr, out, nullptr, nullptr,
       M, VV, CC, VV);
}

// round 15
// speedup vs baseline: 2.2364x; 1.0424x over previous
#include <cuda_runtime.h>
#include <cuda_bf16.h>
#include <cuda_fp16.h>
#include <cstdint>

typedef __nv_bfloat16 bf16;
typedef __half h16;

// ---------------- problem constants ----------------
#define BB    4
#define TT    1024
#define CC    1024
#define HH    16
#define HD    64
#define LL    6
#define VV    16000
#define TTXT  580
#define FF_   4096
#define NPATCH 441
#define KIM   768
#define IMG   336
#define PATCH 16
#define MTOK  (BB*TT)          // 4096

// ---------------- scratch (device globals; no allocation) ----------------
__device__ float g_x  [(size_t)MTOK*CC];
__device__ float g_pp [(size_t)BB*NPATCH*CC];

__device__ bf16 g_qh[(size_t)MTOK*CC], g_ql[(size_t)MTOK*CC];
__device__ bf16 g_kh[(size_t)MTOK*CC], g_kl[(size_t)MTOK*CC];
__device__ bf16 g_vth[(size_t)MTOK*CC], g_vtl[(size_t)MTOK*CC];
__device__ bf16 g_ah[(size_t)MTOK*CC], g_al[(size_t)MTOK*CC];
__device__ bf16 g_fh[(size_t)MTOK*FF_], g_fl[(size_t)MTOK*FF_];

__device__ bf16 g_wqkvh[(size_t)LL*3*CC*CC], g_wqkvl[(size_t)LL*3*CC*CC];
__device__ bf16 g_woh[(size_t)LL*CC*CC], g_wol[(size_t)LL*CC*CC];
__device__ bf16 g_w1h[(size_t)LL*CC*FF_], g_w1l[(size_t)LL*CC*FF_];
__device__ bf16 g_w2h[(size_t)LL*CC*FF_], g_w2l[(size_t)LL*CC*FF_];
__device__ h16  g_lmh[(size_t)CC*VV],    g_lml[(size_t)CC*VV];     // fp16 split LM weights
__device__ bf16 g_pwh[(size_t)CC*KIM],   g_pwl[(size_t)CC*KIM];
__device__ bf16 g_imh[(size_t)BB*NPATCH*KIM], g_iml[(size_t)BB*NPATCH*KIM];

// ---------------- low-level helpers ----------------
__device__ __forceinline__ uint32_t smem_u32(const void* p) {
    uint32_t a;
    asm("{ .reg .u64 t; cvta.to.shared.u64 t, %1; cvt.u32.u64 %0, t; }" : "=r"(a) : "l"(p));
    return a;
}
__device__ __forceinline__ void cpa16(uint32_t dst, const void* src, int szbytes) {
    asm volatile("cp.async.cg.shared.global [%0], [%1], 16, %2;"
                 :: "r"(dst), "l"(src), "r"(szbytes) : "memory");
}
__device__ __forceinline__ void ldsm4(uint32_t (&r)[4], uint32_t addr) {
    asm volatile("ldmatrix.sync.aligned.m8n8.x4.shared.b16 {%0,%1,%2,%3}, [%4];"
                 : "=r"(r[0]), "=r"(r[1]), "=r"(r[2]), "=r"(r[3]) : "r"(addr));
}
__device__ __forceinline__ void mma_bf16(float (&d)[4], const uint32_t (&a)[4],
                                         uint32_t b0, uint32_t b1) {
    asm volatile("mma.sync.aligned.m16n8k16.row.col.f32.bf16.bf16.f32 "
                 "{%0,%1,%2,%3}, {%4,%5,%6,%7}, {%8,%9}, {%0,%1,%2,%3};"
                 : "+f"(d[0]), "+f"(d[1]), "+f"(d[2]), "+f"(d[3])
                 : "r"(a[0]), "r"(a[1]), "r"(a[2]), "r"(a[3]), "r"(b0), "r"(b1));
}
__device__ __forceinline__ void mma_f16(float (&d)[4], const uint32_t (&a)[4],
                                        uint32_t b0, uint32_t b1) {
    asm volatile("mma.sync.aligned.m16n8k16.row.col.f32.f16.f16.f32 "
                 "{%0,%1,%2,%3}, {%4,%5,%6,%7}, {%8,%9}, {%0,%1,%2,%3};"
                 : "+f"(d[0]), "+f"(d[1]), "+f"(d[2]), "+f"(d[3])
                 : "r"(a[0]), "r"(a[1]), "r"(a[2]), "r"(a[3]), "r"(b0), "r"(b1));
}
__device__ __forceinline__ uint32_t pack_split(float v0, float v1, uint32_t& lw) {
    bf16 h0 = __float2bfloat16(v0), h1 = __float2bfloat16(v1);
    float r0 = v0 - __bfloat162float(h0), r1 = v1 - __bfloat162float(h1);
    bf16 l0 = __float2bfloat16(r0), l1 = __float2bfloat16(r1);
    lw = (uint32_t)__bfloat16_as_ushort(l0) | ((uint32_t)__bfloat16_as_ushort(l1) << 16);
    return (uint32_t)__bfloat16_as_ushort(h0) | ((uint32_t)__bfloat16_as_ushort(h1) << 16);
}

// ---------------- split-bf16 tensor-core GEMM (mma.sync, 3-pass) ----------------
#define LDS 40
#define BM  128
#define BN_ 128

// outMode: 0 = normal; 1 = QKV scatter (split q,k at [b,h,t,d], vt at [b,h,d,t])
__global__ __launch_bounds__(256, 2)
void gemm_mma(const bf16* __restrict__ Ah, const bf16* __restrict__ Al,
              const bf16* __restrict__ Bh, const bf16* __restrict__ Bl,
              const float* __restrict__ bias, const float* __restrict__ res,
              float* __restrict__ outF, bf16* __restrict__ outH, bf16* __restrict__ outL,
              bf16* __restrict__ okh, bf16* __restrict__ okl,
              bf16* __restrict__ ovh, bf16* __restrict__ ovl,
              int M, int Nfull, int K, int ldc,
              float alpha, int relu, int outMode)
{
    constexpr int MI = 2;
    constexpr int NI = 8;
    constexpr int ASZ = BM * LDS;
    constexpr int BSZ = BN_ * LDS;

    const int m0 = blockIdx.y * BM;
    const int n0 = blockIdx.x * BN_;

    extern __shared__ bf16 sm[];
    const uint32_t sbase = smem_u32(sm);

    const int tid = threadIdx.x;
    const int nch = K >> 5;

    auto load_stage = [&](int st, int k0) {
        #pragma unroll
        for (int i = tid; i < BM * 4; i += 256) {
            int r = i >> 2, c8 = (i & 3) << 3;
            int gr = m0 + r;
            int ok = (gr < M) ? 16 : 0;
            if (gr >= M) gr = m0;
            size_t go = (size_t)gr * K + k0 + c8;
            uint32_t so = (uint32_t)((st * ASZ + r * LDS + c8) * 2);
            cpa16(sbase + so, Ah + go, ok);
            cpa16(sbase + so + 2 * ASZ * 2, Al + go, ok);
        }
        #pragma unroll
        for (int i = tid; i < BN_ * 4; i += 256) {
            int r = i >> 2, c8 = (i & 3) << 3;
            int gn = n0 + r;
            int ok = (gn < Nfull) ? 16 : 0;
            if (gn >= Nfull) gn = n0;
            size_t go = (size_t)gn * K + k0 + c8;
            uint32_t so = (uint32_t)((4 * ASZ + st * BSZ + r * LDS + c8) * 2);
            cpa16(sbase + so, Bh + go, ok);
            cpa16(sbase + so + 2 * BSZ * 2, Bl + go, ok);
        }
        asm volatile("cp.async.commit_group;" ::: "memory");
    };

    const int wid = tid >> 5, lane = tid & 31;
    const int wr = wid & 3, wc = wid >> 2;
    const int wmBase = wr * 32, wnBase = wc * 64;

    float acc[MI][NI][4];
    #pragma unroll
    for (int mi = 0; mi < MI; mi++)
        #pragma unroll
        for (int ni = 0; ni < NI; ni++)
            #pragma unroll
            for (int j = 0; j < 4; j++) acc[mi][ni][j] = 0.f;

    load_stage(0, 0);

    for (int ch = 0; ch < nch; ch++) {
        asm volatile("cp.async.wait_group 0;" ::: "memory");
        __syncthreads();
        if (ch + 1 < nch) load_stage((ch + 1) & 1, (ch + 1) << 5);

        const int st = ch & 1;
        const uint32_t aHb = sbase + (uint32_t)(st * ASZ * 2);
        const uint32_t aLb = aHb + (uint32_t)(2 * ASZ * 2);
        const uint32_t bHb = sbase + (uint32_t)((4 * ASZ + st * BSZ) * 2);
        const uint32_t bLb = bHb + (uint32_t)(2 * BSZ * 2);

        #pragma unroll
        for (int kk = 0; kk < 2; kk++) {
            const int colOff = kk * 16 + ((lane >> 4) << 3);
            uint32_t afH[MI][4], afL[MI][4];
            #pragma unroll
            for (int mi = 0; mi < MI; mi++) {
                uint32_t off = (uint32_t)(((wmBase + mi * 16 + (lane & 15)) * LDS + colOff) * 2);
                ldsm4(afH[mi], aHb + off);
                ldsm4(afL[mi], aLb + off);
            }
            uint32_t bfH[4][4], bfL[4][4];
            #pragma unroll
            for (int nj = 0; nj < 4; nj++) {
                uint32_t off = (uint32_t)(((wnBase + nj * 16 + (lane & 15)) * LDS + colOff) * 2);
                ldsm4(bfH[nj], bHb + off);
                ldsm4(bfL[nj], bLb + off);
            }
            #pragma unroll
            for (int nj = 0; nj < 4; nj++) {
                #pragma unroll
                for (int mi = 0; mi < MI; mi++) {
                    mma_bf16(acc[mi][2*nj],   afH[mi], bfH[nj][0], bfH[nj][2]);
                    mma_bf16(acc[mi][2*nj+1], afH[mi], bfH[nj][1], bfH[nj][3]);
                }
                #pragma unroll
                for (int mi = 0; mi < MI; mi++) {
                    mma_bf16(acc[mi][2*nj],   afH[mi], bfL[nj][0], bfL[nj][2]);
                    mma_bf16(acc[mi][2*nj+1], afH[mi], bfL[nj][1], bfL[nj][3]);
                }
                #pragma unroll
                for (int mi = 0; mi < MI; mi++) {
                    mma_bf16(acc[mi][2*nj],   afL[mi], bfH[nj][0], bfH[nj][2]);
                    mma_bf16(acc[mi][2*nj+1], afL[mi], bfH[nj][1], bfH[nj][3]);
                }
            }
        }
    }

    // epilogue
    const int g = lane >> 2, t4 = lane & 3;
    #pragma unroll
    for (int mi = 0; mi < MI; mi++) {
        #pragma unroll
        for (int ni = 0; ni < NI; ni++) {
            int col = n0 + wnBase + ni * 8 + t4 * 2;
            if (col >= Nfull) continue;
            #pragma unroll
            for (int half = 0; half < 2; half++) {
                int row = m0 + wmBase + mi * 16 + g + half * 8;
                if (row >= M) continue;
                float v0 = acc[mi][ni][half * 2 + 0] * alpha;
                float v1 = acc[mi][ni][half * 2 + 1] * alpha;
                if (outMode == 1) {
                    int which = col >> 10;
                    int c = col & 1023;
                    int h = c >> 6, d = c & 63;
                    int b = row >> 10, t = row & 1023;
                    uint32_t lw;
                    uint32_t hw = pack_split(v0, v1, lw);
                    if (which < 2) {
                        size_t base = (((size_t)(b * HH + h)) * TT + t) * HD + d;
                        bf16* H = which ? okh : outH;
                        bf16* L = which ? okl : outL;
                        *(uint32_t*)(H + base) = hw;
                        *(uint32_t*)(L + base) = lw;
                    } else {
                        size_t vb = (((size_t)(b * HH + h)) * HD + d) * TT + t;
                        ovh[vb]      = __ushort_as_bfloat16((unsigned short)(hw & 0xffff));
                        ovh[vb + TT] = __ushort_as_bfloat16((unsigned short)(hw >> 16));
                        ovl[vb]      = __ushort_as_bfloat16((unsigned short)(lw & 0xffff));
                        ovl[vb + TT] = __ushort_as_bfloat16((unsigned short)(lw >> 16));
                    }
                } else {
                    long long base = (long long)row * ldc + col;
                    if (bias) { v0 += bias[col]; v1 += bias[col + 1]; }
                    if (res)  { v0 += res[base]; v1 += res[base + 1]; }
                    if (relu) { v0 = fmaxf(v0, 0.f); v1 = fmaxf(v1, 0.f); }
                    if (outF) *(float2*)(outF + base) = make_float2(v0, v1);
                    if (outH) {
                        uint32_t lw;
                        uint32_t hw = pack_split(v0, v1, lw);
                        *(uint32_t*)(outH + base) = hw;
                        *(uint32_t*)(outL + base) = lw;
                    }
                }
            }
        }
    }
}

// ---------------- 2-pass fp16 GEMM for LM head ----------------
// A: [M,K] fp16 single; B: [N,K] fp16 hi/lo. C = A@(Bh+Bl)^T + bias. M,N,K % 128 == 0.
__global__ __launch_bounds__(256, 2)
void gemm_lm(const h16* __restrict__ A,
             const h16* __restrict__ Bh, const h16* __restrict__ Bl,
             const float* __restrict__ bias, float* __restrict__ outF,
             int M, int N, int K)
{
    constexpr int MI = 2;
    constexpr int NI = 8;
    constexpr int ASZ = BM * LDS;
    constexpr int BSZ = BN_ * LDS;

    const int m0 = blockIdx.y * BM;
    const int n0 = blockIdx.x * BN_;

    extern __shared__ h16 smh[];
    const uint32_t sbase = smem_u32(smh);

    const int tid = threadIdx.x;
    const int nch = K >> 5;

    // layout: A[2 stages] | Bh[2 stages] | Bl[2 stages]
    auto load_stage = [&](int st, int k0) {
        #pragma unroll
        for (int i = tid; i < BM * 4; i += 256) {
            int r = i >> 2, c8 = (i & 3) << 3;
            size_t go = (size_t)(m0 + r) * K + k0 + c8;
            uint32_t so = (uint32_t)((st * ASZ + r * LDS + c8) * 2);
            cpa16(sbase + so, A + go, 16);
        }
        #pragma unroll
        for (int i = tid; i < BN_ * 4; i += 256) {
            int r = i >> 2, c8 = (i & 3) << 3;
            size_t go = (size_t)(n0 + r) * K + k0 + c8;
            uint32_t so = (uint32_t)((2 * ASZ + st * BSZ + r * LDS + c8) * 2);
            cpa16(sbase + so, Bh + go, 16);
            cpa16(sbase + so + 2 * BSZ * 2, Bl + go, 16);
        }
        asm volatile("cp.async.commit_group;" ::: "memory");
    };

    const int wid = tid >> 5, lane = tid & 31;
    const int wr = wid & 3, wc = wid >> 2;
    const int wmBase = wr * 32, wnBase = wc * 64;

    float acc[MI][NI][4];
    #pragma unroll
    for (int mi = 0; mi < MI; mi++)
        #pragma unroll
        for (int ni = 0; ni < NI; ni++)
            #pragma unroll
            for (int j = 0; j < 4; j++) acc[mi][ni][j] = 0.f;

    load_stage(0, 0);

    for (int ch = 0; ch < nch; ch++) {
        asm volatile("cp.async.wait_group 0;" ::: "memory");
        __syncthreads();
        if (ch + 1 < nch) load_stage((ch + 1) & 1, (ch + 1) << 5);

        const int st = ch & 1;
        const uint32_t aB  = sbase + (uint32_t)(st * ASZ * 2);
        const uint32_t bHb = sbase + (uint32_t)((2 * ASZ + st * BSZ) * 2);
        const uint32_t bLb = bHb + (uint32_t)(2 * BSZ * 2);

        #pragma unroll
        for (int kk = 0; kk < 2; kk++) {
            const int colOff = kk * 16 + ((lane >> 4) << 3);
            uint32_t af[MI][4];
            #pragma unroll
            for (int mi = 0; mi < MI; mi++) {
                uint32_t off = (uint32_t)(((wmBase + mi * 16 + (lane & 15)) * LDS + colOff) * 2);
                ldsm4(af[mi], aB + off);
            }
            uint32_t bfH[4][4], bfL[4][4];
            #pragma unroll
            for (int nj = 0; nj < 4; nj++) {
                uint32_t off = (uint32_t)(((wnBase + nj * 16 + (lane & 15)) * LDS + colOff) * 2);
                ldsm4(bfH[nj], bHb + off);
                ldsm4(bfL[nj], bLb + off);
            }
            #pragma unroll
            for (int nj = 0; nj < 4; nj++) {
                #pragma unroll
                for (int mi = 0; mi < MI; mi++) {
                    mma_f16(acc[mi][2*nj],   af[mi], bfH[nj][0], bfH[nj][2]);
                    mma_f16(acc[mi][2*nj+1], af[mi], bfH[nj][1], bfH[nj][3]);
                }
                #pragma unroll
                for (int mi = 0; mi < MI; mi++) {
                    mma_f16(acc[mi][2*nj],   af[mi], bfL[nj][0], bfL[nj][2]);
                    mma_f16(acc[mi][2*nj+1], af[mi], bfL[nj][1], bfL[nj][3]);
                }
            }
        }
    }

    const int g = lane >> 2, t4 = lane & 3;
    #pragma unroll
    for (int mi = 0; mi < MI; mi++) {
        #pragma unroll
        for (int ni = 0; ni < NI; ni++) {
            int col = n0 + wnBase + ni * 8 + t4 * 2;
            #pragma unroll
            for (int half = 0; half < 2; half++) {
                int row = m0 + wmBase + mi * 16 + g + half * 8;
                float v0 = acc[mi][ni][half * 2 + 0] + bias[col];
                float v1 = acc[mi][ni][half * 2 + 1] + bias[col + 1];
                *(float2*)(outF + (long long)row * N + col) = make_float2(v0, v1);
            }
        }
    }
}

// ---------------- fused flash attention (register-P, 2 CTA/SM, longest-first) ----------------
#define LDF 72
__global__ __launch_bounds__(256, 2)
void flash_attn_k(const bf16* __restrict__ qh, const bf16* __restrict__ ql,
                  const bf16* __restrict__ kh, const bf16* __restrict__ kl,
                  const bf16* __restrict__ vth, const bf16* __restrict__ vtl,
                  bf16* __restrict__ oh, bf16* __restrict__ ol)
{
    extern __shared__ bf16 sm[];
    const uint32_t sbase = smem_u32(sm);
    const int id = blockIdx.x;
    const int rb = 7 - (id >> 6);
    const int bh = id & 63;
    const int m0 = rb * 128;
    const int tid = threadIdx.x, wid = tid >> 5, lane = tid & 31;
    const int g = lane >> 2, t4 = lane & 3;

    const uint32_t OQH = 0, OQL = 128*LDF;
    const uint32_t OKV = 2*128*LDF;
    const uint32_t KVS = 4*64*LDF;

    for (int i = tid; i < 128 * 8; i += 256) {
        int r = i >> 3, c = (i & 7) << 3;
        size_t go = ((size_t)bh * TT + m0 + r) * HD + c;
        cpa16(sbase + (OQH + r * LDF + c) * 2, qh + go, 16);
        cpa16(sbase + (OQL + r * LDF + c) * 2, ql + go, 16);
    }
    asm volatile("cp.async.commit_group;" ::: "memory");

    auto load_kv = [&](int st, int j0) {
        uint32_t base = OKV + (uint32_t)st * KVS;
        for (int i = tid; i < 64 * 8; i += 256) {
            int r = i >> 3, c = (i & 7) << 3;
            size_t gk = ((size_t)bh * TT + j0 + r) * HD + c;
            size_t gv = ((size_t)bh * HD + r) * TT + j0 + c;
            cpa16(sbase + (base            + r * LDF + c) * 2, kh  + gk, 16);
            cpa16(sbase + (base +   64*LDF + r * LDF + c) * 2, kl  + gk, 16);
            cpa16(sbase + (base + 2*64*LDF + r * LDF + c) * 2, vth + gv, 16);
            cpa16(sbase + (base + 3*64*LDF + r * LDF + c) * 2, vtl + gv, 16);
        }
        asm volatile("cp.async.commit_group;" ::: "memory");
    };

    const int ntiles = 2 * rb + 2;
    load_kv(0, 0);

    float oacc[8][4];
    #pragma unroll
    for (int ni = 0; ni < 8; ni++)
        #pragma unroll
        for (int j = 0; j < 4; j++) oacc[ni][j] = 0.f;
    float mrow[2] = { -1e30f, -1e30f };
    float lrow[2] = { 0.f, 0.f };

    const int row0 = m0 + wid * 16 + g;

    for (int t = 0; t < ntiles; t++) {
        const int j0 = t << 6;
        asm volatile("cp.async.wait_group 0;" ::: "memory");
        __syncthreads();
        if (t + 1 < ntiles) load_kv((t + 1) & 1, j0 + 64);

        const uint32_t kvb = OKV + (uint32_t)(t & 1) * KVS;
        const uint32_t kHb = sbase + kvb * 2;
        const uint32_t kLb = sbase + (kvb + 64*LDF) * 2;
        const uint32_t vHb = sbase + (kvb + 2*64*LDF) * 2;
        const uint32_t vLb = sbase + (kvb + 3*64*LDF) * 2;

        float acc[8][4];
        #pragma unroll
        for (int ni = 0; ni < 8; ni++)
            #pragma unroll
            for (int j = 0; j < 4; j++) acc[ni][j] = 0.f;

        #pragma unroll
        for (int kk = 0; kk < 4; kk++) {
            const int colOff = kk * 16 + ((lane >> 4) << 3);
            uint32_t aH[4], aL[4];
            uint32_t aoff = (uint32_t)(((wid * 16 + (lane & 15)) * LDF + colOff) * 2);
            ldsm4(aH, sbase + (OQH * 2) + aoff);
            ldsm4(aL, sbase + (OQL * 2) + aoff);
            uint32_t bH[4][4], bL[4][4];
            #pragma unroll
            for (int nj = 0; nj < 4; nj++) {
                uint32_t boff = (uint32_t)(((nj * 16 + (lane & 15)) * LDF + colOff) * 2);
                ldsm4(bH[nj], kHb + boff);
                ldsm4(bL[nj], kLb + boff);
            }
            #pragma unroll
            for (int nj = 0; nj < 4; nj++) {
                mma_bf16(acc[2*nj],   aH, bH[nj][0], bH[nj][2]);
                mma_bf16(acc[2*nj+1], aH, bH[nj][1], bH[nj][3]);
                mma_bf16(acc[2*nj],   aH, bL[nj][0], bL[nj][2]);
                mma_bf16(acc[2*nj+1], aH, bL[nj][1], bL[nj][3]);
                mma_bf16(acc[2*nj],   aL, bH[nj][0], bH[nj][2]);
                mma_bf16(acc[2*nj+1], aL, bH[nj][1], bH[nj][3]);
            }
        }

        #pragma unroll
        for (int ni = 0; ni < 8; ni++) {
            int colBase = j0 + ni * 8 + t4 * 2;
            #pragma unroll
            for (int j = 0; j < 4; j++) {
                int row = row0 + ((j >> 1) << 3);
                int col = colBase + (j & 1);
                float v = acc[ni][j] * 0.125f;
                acc[ni][j] = (col <= row) ? v : -1e30f;
            }
        }

        #pragma unroll
        for (int half = 0; half < 2; half++) {
            float mt = -1e30f;
            #pragma unroll
            for (int ni = 0; ni < 8; ni++) {
                mt = fmaxf(mt, acc[ni][half*2+0]);
                mt = fmaxf(mt, acc[ni][half*2+1]);
            }
            mt = fmaxf(mt, __shfl_xor_sync(0xffffffffu, mt, 1));
            mt = fmaxf(mt, __shfl_xor_sync(0xffffffffu, mt, 2));
            float mnew = fmaxf(mrow[half], mt);
            float scale = __expf(mrow[half] - mnew);
            mrow[half] = mnew;
            float sum = 0.f;
            #pragma unroll
            for (int ni = 0; ni < 8; ni++) {
                float e0 = __expf(acc[ni][half*2+0] - mnew);
                float e1 = __expf(acc[ni][half*2+1] - mnew);
                acc[ni][half*2+0] = e0;
                acc[ni][half*2+1] = e1;
                sum += e0 + e1;
            }
            sum += __shfl_xor_sync(0xffffffffu, sum, 1);
            sum += __shfl_xor_sync(0xffffffffu, sum, 2);
            lrow[half] = lrow[half] * scale + sum;
            #pragma unroll
            for (int ni = 0; ni < 8; ni++) {
                oacc[ni][half*2+0] *= scale;
                oacc[ni][half*2+1] *= scale;
            }
        }

        #pragma unroll
        for (int kk = 0; kk < 4; kk++) {
            uint32_t aH[4], aL[4];
            aH[0] = pack_split(acc[2*kk][0],   acc[2*kk][1],   aL[0]);
            aH[1] = pack_split(acc[2*kk][2],   acc[2*kk][3],   aL[1]);
            aH[2] = pack_split(acc[2*kk+1][0], acc[2*kk+1][1], aL[2]);
            aH[3] = pack_split(acc[2*kk+1][2], acc[2*kk+1][3], aL[3]);
            const int colOff = kk * 16 + ((lane >> 4) << 3);
            uint32_t bH[4][4], bL[4][4];
            #pragma unroll
            for (int nj = 0; nj < 4; nj++) {
                uint32_t boff = (uint32_t)(((nj * 16 + (lane & 15)) * LDF + colOff) * 2);
                ldsm4(bH[nj], vHb + boff);
                ldsm4(bL[nj], vLb + boff);
            }
            #pragma unroll
            for (int nj = 0; nj < 4; nj++) {
                mma_bf16(oacc[2*nj],   aH, bH[nj][0], bH[nj][2]);
                mma_bf16(oacc[2*nj+1], aH, bH[nj][1], bH[nj][3]);
                mma_bf16(oacc[2*nj],   aH, bL[nj][0], bL[nj][2]);
                mma_bf16(oacc[2*nj+1], aH, bL[nj][1], bL[nj][3]);
                mma_bf16(oacc[2*nj],   aL, bH[nj][0], bH[nj][2]);
                mma_bf16(oacc[2*nj+1], aL, bH[nj][1], bH[nj][3]);
            }
        }
    }

    const int b = bh >> 4, h = bh & 15;
    float inv0 = 1.f / lrow[0], inv1 = 1.f / lrow[1];
    #pragma unroll
    for (int ni = 0; ni < 8; ni++) {
        int d = ni * 8 + t4 * 2;
        #pragma unroll
        for (int half = 0; half < 2; half++) {
            int trow = m0 + wid * 16 + g + half * 8;
            float inv = half ? inv1 : inv0;
            size_t base = ((size_t)b * TT + trow) * CC + h * HD + d;
            uint32_t lw;
            uint32_t hw = pack_split(oacc[ni][half*2+0] * inv,
                                     oacc[ni][half*2+1] * inv, lw);
            *(uint32_t*)(oh + base) = hw;
            *(uint32_t*)(ol + base) = lw;
        }
    }
}

// ---------------- block reductions ----------------
__device__ __forceinline__ float blockReduceSum256(float v, float* sh) {
    #pragma unroll
    for (int o = 16; o > 0; o >>= 1) v += __shfl_xor_sync(0xffffffffu, v, o);
    int w = threadIdx.x >> 5;
    if ((threadIdx.x & 31) == 0) sh[w] = v;
    __syncthreads();
    if (threadIdx.x < 8) {
        v = sh[threadIdx.x];
        #pragma unroll
        for (int o = 4; o > 0; o >>= 1) v += __shfl_xor_sync(0xffu, v, o);
        if (threadIdx.x == 0) sh[0] = v;
    }
    __syncthreads();
    float r = sh[0]; __syncthreads(); return r;
}

__device__ __forceinline__ void split_store(bf16* H, bf16* L, size_t i, float v) {
    bf16 h = __float2bfloat16(v);
    H[i] = h;
    L[i] = __float2bfloat16(v - __bfloat162float(h));
}
__device__ __forceinline__ void split_store_h(h16* H, h16* L, size_t i, float v) {
    h16 h = __float2half(v);
    H[i] = h;
    L[i] = __float2half(v - __half2float(h));
}

// ---------------- layernorm -> split bf16 ----------------
__global__ __launch_bounds__(256)
void layernorm_split_k(const float* __restrict__ x, const float* __restrict__ g,
                       const float* __restrict__ b, bf16* __restrict__ oh, bf16* __restrict__ ol)
{
    __shared__ float sh[8];
    const size_t row = blockIdx.x;
    const float* xr = x + row * CC;
    const int c = threadIdx.x * 4;
    float4 xv = *(const float4*)(xr + c);
    float s  = xv.x + xv.y + xv.z + xv.w;
    float ss = xv.x*xv.x + xv.y*xv.y + xv.z*xv.z + xv.w*xv.w;
    s = blockReduceSum256(s, sh);
    ss = blockReduceSum256(ss, sh);
    float mean = s * (1.f / CC);
    float var = ss * (1.f / CC) - mean * mean;
    float inv = rsqrtf(var + 1e-5f);
    float4 gv = *(const float4*)(g + c);
    float4 bv = *(const float4*)(b + c);
    size_t base = row * CC + c;
    split_store(oh, ol, base + 0, (xv.x - mean) * inv * gv.x + bv.x);
    split_store(oh, ol, base + 1, (xv.y - mean) * inv * gv.y + bv.y);
    split_store(oh, ol, base + 2, (xv.z - mean) * inv * gv.z + bv.z);
    split_store(oh, ol, base + 3, (xv.w - mean) * inv * gv.w + bv.w);
}

// ---------------- final layernorm -> single fp16 ----------------
__global__ __launch_bounds__(256)
void layernorm_h16_k(const float* __restrict__ x, const float* __restrict__ g,
                     const float* __restrict__ b, h16* __restrict__ o)
{
    __shared__ float sh[8];
    const size_t row = blockIdx.x;
    const float* xr = x + row * CC;
    const int c = threadIdx.x * 4;
    float4 xv = *(const float4*)(xr + c);
    float s  = xv.x + xv.y + xv.z + xv.w;
    float ss = xv.x*xv.x + xv.y*xv.y + xv.z*xv.z + xv.w*xv.w;
    s = blockReduceSum256(s, sh);
    ss = blockReduceSum256(ss, sh);
    float mean = s * (1.f / CC);
    float var = ss * (1.f / CC) - mean * mean;
    float inv = rsqrtf(var + 1e-5f);
    float4 gv = *(const float4*)(g + c);
    float4 bv = *(const float4*)(b + c);
    size_t base = row * CC + c;
    o[base + 0] = __float2half((xv.x - mean) * inv * gv.x + bv.x);
    o[base + 1] = __float2half((xv.y - mean) * inv * gv.y + bv.y);
    o[base + 2] = __float2half((xv.z - mean) * inv * gv.z + bv.z);
    o[base + 3] = __float2half((xv.w - mean) * inv * gv.w + bv.w);
}

// ---------------- fused embed + layer0 LN1 -> x and split bf16 ----------------
__global__ __launch_bounds__(256)
void embed_ln_k(const int* __restrict__ toks, const float* __restrict__ tok_emb,
                const float* __restrict__ txt_pos, const float* __restrict__ img_pos,
                const float* __restrict__ p, const float* __restrict__ g,
                const float* __restrict__ b,
                float* __restrict__ x, bf16* __restrict__ oh, bf16* __restrict__ ol)
{
    __shared__ float sh[8];
    const int bt = blockIdx.x;
    const int bb = bt >> 10;
    const int t = bt & 1023;
    const int c = threadIdx.x * 4;
    const float* src;
    const float* extra = nullptr;
    if (t == 0)      src = tok_emb + 1 * CC;
    else if (t == 1) src = tok_emb + 8 * CC;
    else if (t < 443) {
        int n = t - 2;
        src = p + ((size_t)(bb * NPATCH + n)) * CC;
        extra = img_pos + (size_t)n * CC;
    }
    else if (t == 443) src = tok_emb + 9 * CC;
    else {
        int tok = toks[bb * TTXT + (t - 444)];
        src = tok_emb + (size_t)tok * CC;
    }
    float4 v = *(const float4*)(src + c);
    float4 tp = *(const float4*)(txt_pos + (size_t)t * CC + c);
    v.x += tp.x; v.y += tp.y; v.z += tp.z; v.w += tp.w;
    if (extra) {
        float4 e = *(const float4*)(extra + c);
        v.x += e.x; v.y += e.y; v.z += e.z; v.w += e.w;
    }
    size_t base = (size_t)bt * CC + c;
    *(float4*)(x + base) = v;

    float s  = v.x + v.y + v.z + v.w;
    float ss = v.x*v.x + v.y*v.y + v.z*v.z + v.w*v.w;
    s = blockReduceSum256(s, sh);
    ss = blockReduceSum256(ss, sh);
    float mean = s * (1.f / CC);
    float var = ss * (1.f / CC) - mean * mean;
    float inv = rsqrtf(var + 1e-5f);
    float4 gv = *(const float4*)(g + c);
    float4 bv = *(const float4*)(b + c);
    split_store(oh, ol, base + 0, (v.x - mean) * inv * gv.x + bv.x);
    split_store(oh, ol, base + 1, (v.y - mean) * inv * gv.y + bv.y);
    split_store(oh, ol, base + 2, (v.z - mean) * inv * gv.z + bv.z);
    split_store(oh, ol, base + 3, (v.w - mean) * inv * gv.w + bv.w);
}

// ---------------- fused weight prep + im2col in ONE launch ----------------
__device__ __forceinline__ void transpose_tile(const float* __restrict__ W,
                                               bf16* __restrict__ hi, bf16* __restrict__ lo,
                                               int K, int N, int k0, int n0,
                                               float tbuf[32][33])
{
    int tx = threadIdx.x, ty = threadIdx.y;
    #pragma unroll
    for (int i = 0; i < 32; i += 8)
        tbuf[ty + i][tx] = W[(size_t)(k0 + ty + i) * N + n0 + tx];
    __syncthreads();
    #pragma unroll
    for (int i = 0; i < 32; i += 8)
        split_store(hi, lo, (size_t)(n0 + ty + i) * K + k0 + tx, tbuf[tx][ty + i]);
}
__device__ __forceinline__ void transpose_tile_h(const float* __restrict__ W,
                                                 h16* __restrict__ hi, h16* __restrict__ lo,
                                                 int K, int N, int k0, int n0,
                                                 float tbuf[32][33])
{
    int tx = threadIdx.x, ty = threadIdx.y;
    #pragma unroll
    for (int i = 0; i < 32; i += 8)
        tbuf[ty + i][tx] = W[(size_t)(k0 + ty + i) * N + n0 + tx];
    __syncthreads();
    #pragma unroll
    for (int i = 0; i < 32; i += 8)
        split_store_h(hi, lo, (size_t)(n0 + ty + i) * K + k0 + tx, tbuf[tx][ty + i]);
}

#define TPM_CC  1024
#define T_QKV   (LL*TPM_CC)
#define T_W1    (LL*(32*128))
#define T_LM    (32*500)
#define T_PATCH 768
#define T_IM2C  ((BB*NPATCH*KIM)/1024)   // 1323

__global__ void prep_weights_k(const float* __restrict__ wq, const float* __restrict__ wk,
                               const float* __restrict__ wv, const float* __restrict__ wo,
                               const float* __restrict__ w1, const float* __restrict__ w2,
                               const float* __restrict__ lm_w, const float* __restrict__ patch_w,
                               const float* __restrict__ images,
                               bf16* qkvh, bf16* qkvl, bf16* woh, bf16* wol,
                               bf16* w1h, bf16* w1l, bf16* w2h, bf16* w2l,
                               h16* lmh, h16* lml, bf16* pwh, bf16* pwl,
                               bf16* imh, bf16* iml)
{
    __shared__ float tbuf[32][33];
    int t = blockIdx.x;
    const long long QKV_Z = (long long)3 * CC * CC;

    if (t < 3 * T_QKV) {
        int which = t / T_QKV;
        int r = t % T_QKV;
        int l = r / TPM_CC;
        int loc = r % TPM_CC;
        int n0 = (loc & 31) * 32, k0 = (loc >> 5) * 32;
        const float* W = (which == 0 ? wq : which == 1 ? wk : wv) + (size_t)l * CC * CC;
        bf16* hi = qkvh + (size_t)l * QKV_Z + (size_t)which * CC * CC;
        bf16* lo = qkvl + (size_t)l * QKV_Z + (size_t)which * CC * CC;
        transpose_tile(W, hi, lo, CC, CC, k0, n0, tbuf);
        return;
    }
    t -= 3 * T_QKV;
    if (t < T_QKV) {
        int l = t / TPM_CC, loc = t % TPM_CC;
        int n0 = (loc & 31) * 32, k0 = (loc >> 5) * 32;
        transpose_tile(wo + (size_t)l * CC * CC, woh + (size_t)l * CC * CC,
                       wol + (size_t)l * CC * CC, CC, CC, k0, n0, tbuf);
        return;
    }
    t -= T_QKV;
    if (t < T_W1) {
        int l = t / (32 * 128), loc = t % (32 * 128);
        int n0 = (loc % 128) * 32, k0 = (loc / 128) * 32;
        transpose_tile(w1 + (size_t)l * CC * FF_, w1h + (size_t)l * CC * FF_,
                       w1l + (size_t)l * CC * FF_, CC, FF_, k0, n0, tbuf);
        return;
    }
    t -= T_W1;
    if (t < T_W1) {
        int l = t / (128 * 32), loc = t % (128 * 32);
        int n0 = (loc & 31) * 32, k0 = (loc >> 5) * 32;
        transpose_tile(w2 + (size_t)l * CC * FF_, w2h + (size_t)l * CC * FF_,
                       w2l + (size_t)l * CC * FF_, FF_, CC, k0, n0, tbuf);
        return;
    }
    t -= T_W1;
    if (t < T_LM) {
        int n0 = (t % 500) * 32, k0 = (t / 500) * 32;
        transpose_tile_h(lm_w, lmh, lml, CC, VV, k0, n0, tbuf);
        return;
    }
    t -= T_LM;
    if (t < T_PATCH) {
        int base = t * 1024;
        int tid = threadIdx.y * 32 + threadIdx.x;
        #pragma unroll
        for (int i = 0; i < 4; i++) {
            int idx = base + tid + i * 256;
            split_store(pwh, pwl, idx, patch_w[idx]);
        }
        return;
    }
    t -= T_PATCH;
    {
        int tid = threadIdx.y * 32 + threadIdx.x;
        #pragma unroll
        for (int i = 0; i < 4; i++) {
            int idx = t * 1024 + tid + i * 256;
            int k = idx % KIM;
            int bn = idx / KIM;
            int n = bn % NPATCH;
            int b = bn / NPATCH;
            int ci = k >> 8;
            int rr = k & 255;
            int kh = rr >> 4;
            int kw = rr & 15;
            int ph = n / 21, pw = n % 21;
            float v = images[(((size_t)b * 3 + ci) * IMG + ph * PATCH + kh) * IMG + pw * PATCH + kw];
            split_store(imh, iml, idx, v);
        }
    }
}

// ---------------- host-side GEMM launcher ----------------
#define SMEM_GEMM  ((4 * 128 * LDS + 4 * 128 * LDS) * 2)
#define SMEM_LM    ((2 * 128 * LDS + 4 * 128 * LDS) * 2)

static inline void tc(const bf16* Ah, const bf16* Al, const bf16* Bh, const bf16* Bl,
                      const float* bias, const float* res,
                      float* outF, bf16* outH, bf16* outL,
                      int M, int N, int K, int ldc,
                      float alpha = 1.f, int relu = 0, int outMode = 0,
                      bf16* okh = nullptr, bf16* okl = nullptr,
                      bf16* ovh = nullptr, bf16* ovl = nullptr)
{
    dim3 grid((N + 127) / 128, (M + 127) / 128, 1);
    gemm_mma<<<grid, 256, SMEM_GEMM>>>(Ah, Al, Bh, Bl, bias, res,
        outF, outH, outL, okh, okl, ovh, ovl, M, N, K, ldc, alpha, relu, outMode);
}

#define SYM(name) ({ void* _p; cudaGetSymbolAddress(&_p, name); _p; })

extern "C" void kernel_launch(void* const* d_in, const int* in_sizes, int n_in,
                              void* d_out, int out_size)
{
    const int*   text_tokens = (const int*)  d_in[0];
    const float* images      = (const float*)d_in[1];
    const float* tok_emb     = (const float*)d_in[2];
    const float* txt_pos     = (const float*)d_in[3];
    const float* img_pos     = (const float*)d_in[4];
    const float* patch_w     = (const float*)d_in[5];
    const float* patch_b     = (const float*)d_in[6];
    const float* ln1_g       = (const float*)d_in[7];
    const float* ln1_b       = (const float*)d_in[8];
    const float* wq          = (const float*)d_in[9];
    const float* wk          = (const float*)d_in[10];
    const float* wv          = (const float*)d_in[11];
    const float* wo          = (const float*)d_in[12];
    const float* bo          = (const float*)d_in[13];
    const float* ln2_g       = (const float*)d_in[14];
    const float* ln2_b       = (const float*)d_in[15];
    const float* w1          = (const float*)d_in[16];
    const float* b1          = (const float*)d_in[17];
    const float* w2          = (const float*)d_in[18];
    const float* b2          = (const float*)d_in[19];
    const float* lnf_g       = (const float*)d_in[20];
    const float* lnf_b       = (const float*)d_in[21];
    const float* lm_w        = (const float*)d_in[22];
    const float* lm_b        = (const float*)d_in[23];
    float* out = (float*)d_out;

    cudaFuncSetAttribute(gemm_mma, cudaFuncAttributeMaxDynamicSharedMemorySize, SMEM_GEMM);
    cudaFuncSetAttribute(gemm_lm,  cudaFuncAttributeMaxDynamicSharedMemorySize, SMEM_LM);
    const int FLASH_SMEM = (2 * 128 * LDF + 2 * 4 * 64 * LDF) * 2;
    cudaFuncSetAttribute(flash_attn_k, cudaFuncAttributeMaxDynamicSharedMemorySize, FLASH_SMEM);

    float* px   = (float*)SYM(g_x);
    float* ppp  = (float*)SYM(g_pp);
    bf16 *pqh = (bf16*)SYM(g_qh), *pql = (bf16*)SYM(g_ql);
    bf16 *pkh = (bf16*)SYM(g_kh), *pkl = (bf16*)SYM(g_kl);
    bf16 *pvth = (bf16*)SYM(g_vth), *pvtl = (bf16*)SYM(g_vtl);
    bf16 *pah = (bf16*)SYM(g_ah), *pal = (bf16*)SYM(g_al);
    bf16 *pfh = (bf16*)SYM(g_fh), *pfl = (bf16*)SYM(g_fl);
    bf16 *pwqkvh = (bf16*)SYM(g_wqkvh), *pwqkvl = (bf16*)SYM(g_wqkvl);
    bf16 *pwoh = (bf16*)SYM(g_woh), *pwol = (bf16*)SYM(g_wol);
    bf16 *pw1h = (bf16*)SYM(g_w1h), *pw1l = (bf16*)SYM(g_w1l);
    bf16 *pw2h = (bf16*)SYM(g_w2h), *pw2l = (bf16*)SYM(g_w2l);
    h16  *plmh = (h16*)SYM(g_lmh),  *plml = (h16*)SYM(g_lml);
    bf16 *ppwh = (bf16*)SYM(g_pwh), *ppwl = (bf16*)SYM(g_pwl);
    bf16 *pimh = (bf16*)SYM(g_imh), *piml = (bf16*)SYM(g_iml);
    h16  *pah16 = (h16*)pah;                 // reuse activation buffer as fp16

    // ---- [1] all weight prep + im2col in one launch ----
    const int nPrep = 4 * T_QKV + 2 * T_W1 + T_LM + T_PATCH + T_IM2C;
    prep_weights_k<<<nPrep, dim3(32, 8)>>>(wq, wk, wv, wo, w1, w2, lm_w, patch_w, images,
        pwqkvh, pwqkvl, pwoh, pwol, pw1h, pw1l, pw2h, pw2l, plmh, plml, ppwh, ppwl,
        pimh, piml);

    // ---- [2] patch GEMM  [3] fused embed+LN1(l=0) ----
    tc(pimh, piml, ppwh, ppwl, patch_b, nullptr, ppp, nullptr, nullptr,
       BB*NPATCH, CC, KIM, CC);
    embed_ln_k<<<BB*TT, 256>>>(text_tokens, tok_emb, txt_pos, img_pos, ppp,
                               ln1_g, ln1_b, px, pah, pal);

    const int M = MTOK;
    for (int l = 0; l < LL; l++) {
        size_t wOff = (size_t)l * CC * CC, w1Off = (size_t)l * CC * FF_;
        size_t qkvOff = (size_t)l * 3 * CC * CC;

        if (l > 0)
            layernorm_split_k<<<M, 256>>>(px, ln1_g + l*CC, ln1_b + l*CC, pah, pal);

        tc(pah, pal, pwqkvh + qkvOff, pwqkvl + qkvOff, nullptr, nullptr,
           nullptr, pqh, pql, M, 3*CC, CC, 0, 1.f, 0, /*outMode*/1,
           pkh, pkl, pvth, pvtl);

        flash_attn_k<<<BB*HH*8, 256, FLASH_SMEM>>>(
            pqh, pql, pkh, pkl, pvth, pvtl, pah, pal);

        tc(pah, pal, pwoh + wOff, pwol + wOff, bo + l*CC, px, px, nullptr, nullptr,
           M, CC, CC, CC);

        layernorm_split_k<<<M, 256>>>(px, ln2_g + l*CC, ln2_b + l*CC, pah, pal);

        tc(pah, pal, pw1h + w1Off, pw1l + w1Off, b1 + l*FF_, nullptr,
           nullptr, pfh, pfl, M, FF_, CC, FF_, 1.f, /*relu*/1);
        tc(pfh, pfl, pw2h + w1Off, pw2l + w1Off, b2 + l*CC, px, px, nullptr, nullptr,
           M, CC, FF_, CC);
    }

    // ---- final LN (single fp16) + LM head (2-pass fp16) ----
    layernorm_h16_k<<<M, 256>>>(px, lnf_g, lnf_b, pah16);
    {
        dim3 grid(VV / 128, M / 128);
        gemm_lm<<<grid, 256, SMEM_LM>>>(pah16, plmh, plml, lm_b, out, M, VV, CC);
    }
}

// round 16
// speedup vs baseline: 2.6739x; 1.1956x over previous
#include <cuda_runtime.h>
#include <cuda_bf16.h>
#include <cuda_fp16.h>
#include <cstdint>

typedef __nv_bfloat16 bf16;
typedef __half h16;

// ---------------- problem constants ----------------
#define BB    4
#define TT    1024
#define CC    1024
#define HH    16
#define HD    64
#define LL    6
#define VV    16000
#define TTXT  580
#define FF_   4096
#define NPATCH 441
#define KIM   768
#define IMG   336
#define PATCH 16
#define MTOK  (BB*TT)          // 4096

// ---------------- scratch (device globals; no allocation) ----------------
__device__ float g_x  [(size_t)MTOK*CC];
__device__ float g_pp [(size_t)BB*NPATCH*CC];

__device__ bf16 g_qh[(size_t)MTOK*CC], g_ql[(size_t)MTOK*CC];
__device__ bf16 g_kh[(size_t)MTOK*CC], g_kl[(size_t)MTOK*CC];
__device__ bf16 g_vth[(size_t)MTOK*CC], g_vtl[(size_t)MTOK*CC];
__device__ bf16 g_ah[(size_t)MTOK*CC], g_al[(size_t)MTOK*CC];
__device__ h16  g_f16[(size_t)MTOK*FF_];        // fp16 FFN intermediate

__device__ bf16 g_wqkvh[(size_t)LL*3*CC*CC], g_wqkvl[(size_t)LL*3*CC*CC];
__device__ bf16 g_woh[(size_t)LL*CC*CC], g_wol[(size_t)LL*CC*CC];
__device__ h16  g_w1h[(size_t)LL*CC*FF_], g_w1l[(size_t)LL*CC*FF_];   // fp16 split
__device__ h16  g_w2h[(size_t)LL*CC*FF_], g_w2l[(size_t)LL*CC*FF_];   // fp16 split
__device__ h16  g_lmh[(size_t)CC*VV],    g_lml[(size_t)CC*VV];        // fp16 split
__device__ bf16 g_pwh[(size_t)CC*KIM],   g_pwl[(size_t)CC*KIM];
__device__ bf16 g_imh[(size_t)BB*NPATCH*KIM], g_iml[(size_t)BB*NPATCH*KIM];

// ---------------- low-level helpers ----------------
__device__ __forceinline__ uint32_t smem_u32(const void* p) {
    uint32_t a;
    asm("{ .reg .u64 t; cvta.to.shared.u64 t, %1; cvt.u32.u64 %0, t; }" : "=r"(a) : "l"(p));
    return a;
}
__device__ __forceinline__ void cpa16(uint32_t dst, const void* src, int szbytes) {
    asm volatile("cp.async.cg.shared.global [%0], [%1], 16, %2;"
                 :: "r"(dst), "l"(src), "r"(szbytes) : "memory");
}
__device__ __forceinline__ void ldsm4(uint32_t (&r)[4], uint32_t addr) {
    asm volatile("ldmatrix.sync.aligned.m8n8.x4.shared.b16 {%0,%1,%2,%3}, [%4];"
                 : "=r"(r[0]), "=r"(r[1]), "=r"(r[2]), "=r"(r[3]) : "r"(addr));
}
__device__ __forceinline__ void mma_bf16(float (&d)[4], const uint32_t (&a)[4],
                                         uint32_t b0, uint32_t b1) {
    asm volatile("mma.sync.aligned.m16n8k16.row.col.f32.bf16.bf16.f32 "
                 "{%0,%1,%2,%3}, {%4,%5,%6,%7}, {%8,%9}, {%0,%1,%2,%3};"
                 : "+f"(d[0]), "+f"(d[1]), "+f"(d[2]), "+f"(d[3])
                 : "r"(a[0]), "r"(a[1]), "r"(a[2]), "r"(a[3]), "r"(b0), "r"(b1));
}
__device__ __forceinline__ void mma_f16(float (&d)[4], const uint32_t (&a)[4],
                                        uint32_t b0, uint32_t b1) {
    asm volatile("mma.sync.aligned.m16n8k16.row.col.f32.f16.f16.f32 "
                 "{%0,%1,%2,%3}, {%4,%5,%6,%7}, {%8,%9}, {%0,%1,%2,%3};"
                 : "+f"(d[0]), "+f"(d[1]), "+f"(d[2]), "+f"(d[3])
                 : "r"(a[0]), "r"(a[1]), "r"(a[2]), "r"(a[3]), "r"(b0), "r"(b1));
}
__device__ __forceinline__ uint32_t pack_split(float v0, float v1, uint32_t& lw) {
    bf16 h0 = __float2bfloat16(v0), h1 = __float2bfloat16(v1);
    float r0 = v0 - __bfloat162float(h0), r1 = v1 - __bfloat162float(h1);
    bf16 l0 = __float2bfloat16(r0), l1 = __float2bfloat16(r1);
    lw = (uint32_t)__bfloat16_as_ushort(l0) | ((uint32_t)__bfloat16_as_ushort(l1) << 16);
    return (uint32_t)__bfloat16_as_ushort(h0) | ((uint32_t)__bfloat16_as_ushort(h1) << 16);
}

// ---------------- split-bf16 tensor-core GEMM (mma.sync, 3-pass) ----------------
#define LDS 40
#define BM  128
#define BN_ 128

// outMode: 0 = normal; 1 = QKV scatter (split q,k at [b,h,t,d], vt at [b,h,d,t])
__global__ __launch_bounds__(256, 2)
void gemm_mma(const bf16* __restrict__ Ah, const bf16* __restrict__ Al,
              const bf16* __restrict__ Bh, const bf16* __restrict__ Bl,
              const float* __restrict__ bias, const float* __restrict__ res,
              float* __restrict__ outF, bf16* __restrict__ outH, bf16* __restrict__ outL,
              bf16* __restrict__ okh, bf16* __restrict__ okl,
              bf16* __restrict__ ovh, bf16* __restrict__ ovl,
              int M, int Nfull, int K, int ldc,
              float alpha, int relu, int outMode)
{
    constexpr int MI = 2;
    constexpr int NI = 8;
    constexpr int ASZ = BM * LDS;
    constexpr int BSZ = BN_ * LDS;

    const int m0 = blockIdx.y * BM;
    const int n0 = blockIdx.x * BN_;

    extern __shared__ bf16 sm[];
    const uint32_t sbase = smem_u32(sm);

    const int tid = threadIdx.x;
    const int nch = K >> 5;

    auto load_stage = [&](int st, int k0) {
        #pragma unroll
        for (int i = tid; i < BM * 4; i += 256) {
            int r = i >> 2, c8 = (i & 3) << 3;
            int gr = m0 + r;
            int ok = (gr < M) ? 16 : 0;
            if (gr >= M) gr = m0;
            size_t go = (size_t)gr * K + k0 + c8;
            uint32_t so = (uint32_t)((st * ASZ + r * LDS + c8) * 2);
            cpa16(sbase + so, Ah + go, ok);
            cpa16(sbase + so + 2 * ASZ * 2, Al + go, ok);
        }
        #pragma unroll
        for (int i = tid; i < BN_ * 4; i += 256) {
            int r = i >> 2, c8 = (i & 3) << 3;
            int gn = n0 + r;
            int ok = (gn < Nfull) ? 16 : 0;
            if (gn >= Nfull) gn = n0;
            size_t go = (size_t)gn * K + k0 + c8;
            uint32_t so = (uint32_t)((4 * ASZ + st * BSZ + r * LDS + c8) * 2);
            cpa16(sbase + so, Bh + go, ok);
            cpa16(sbase + so + 2 * BSZ * 2, Bl + go, ok);
        }
        asm volatile("cp.async.commit_group;" ::: "memory");
    };

    const int wid = tid >> 5, lane = tid & 31;
    const int wr = wid & 3, wc = wid >> 2;
    const int wmBase = wr * 32, wnBase = wc * 64;

    float acc[MI][NI][4];
    #pragma unroll
    for (int mi = 0; mi < MI; mi++)
        #pragma unroll
        for (int ni = 0; ni < NI; ni++)
            #pragma unroll
            for (int j = 0; j < 4; j++) acc[mi][ni][j] = 0.f;

    load_stage(0, 0);

    for (int ch = 0; ch < nch; ch++) {
        asm volatile("cp.async.wait_group 0;" ::: "memory");
        __syncthreads();
        if (ch + 1 < nch) load_stage((ch + 1) & 1, (ch + 1) << 5);

        const int st = ch & 1;
        const uint32_t aHb = sbase + (uint32_t)(st * ASZ * 2);
        const uint32_t aLb = aHb + (uint32_t)(2 * ASZ * 2);
        const uint32_t bHb = sbase + (uint32_t)((4 * ASZ + st * BSZ) * 2);
        const uint32_t bLb = bHb + (uint32_t)(2 * BSZ * 2);

        #pragma unroll
        for (int kk = 0; kk < 2; kk++) {
            const int colOff = kk * 16 + ((lane >> 4) << 3);
            uint32_t afH[MI][4], afL[MI][4];
            #pragma unroll
            for (int mi = 0; mi < MI; mi++) {
                uint32_t off = (uint32_t)(((wmBase + mi * 16 + (lane & 15)) * LDS + colOff) * 2);
                ldsm4(afH[mi], aHb + off);
                ldsm4(afL[mi], aLb + off);
            }
            uint32_t bfH[4][4], bfL[4][4];
            #pragma unroll
            for (int nj = 0; nj < 4; nj++) {
                uint32_t off = (uint32_t)(((wnBase + nj * 16 + (lane & 15)) * LDS + colOff) * 2);
                ldsm4(bfH[nj], bHb + off);
                ldsm4(bfL[nj], bLb + off);
            }
            #pragma unroll
            for (int nj = 0; nj < 4; nj++) {
                #pragma unroll
                for (int mi = 0; mi < MI; mi++) {
                    mma_bf16(acc[mi][2*nj],   afH[mi], bfH[nj][0], bfH[nj][2]);
                    mma_bf16(acc[mi][2*nj+1], afH[mi], bfH[nj][1], bfH[nj][3]);
                }
                #pragma unroll
                for (int mi = 0; mi < MI; mi++) {
                    mma_bf16(acc[mi][2*nj],   afH[mi], bfL[nj][0], bfL[nj][2]);
                    mma_bf16(acc[mi][2*nj+1], afH[mi], bfL[nj][1], bfL[nj][3]);
                }
                #pragma unroll
                for (int mi = 0; mi < MI; mi++) {
                    mma_bf16(acc[mi][2*nj],   afL[mi], bfH[nj][0], bfH[nj][2]);
                    mma_bf16(acc[mi][2*nj+1], afL[mi], bfH[nj][1], bfH[nj][3]);
                }
            }
        }
    }

    // epilogue
    const int g = lane >> 2, t4 = lane & 3;
    #pragma unroll
    for (int mi = 0; mi < MI; mi++) {
        #pragma unroll
        for (int ni = 0; ni < NI; ni++) {
            int col = n0 + wnBase + ni * 8 + t4 * 2;
            if (col >= Nfull) continue;
            #pragma unroll
            for (int half = 0; half < 2; half++) {
                int row = m0 + wmBase + mi * 16 + g + half * 8;
                if (row >= M) continue;
                float v0 = acc[mi][ni][half * 2 + 0] * alpha;
                float v1 = acc[mi][ni][half * 2 + 1] * alpha;
                if (outMode == 1) {
                    int which = col >> 10;
                    int c = col & 1023;
                    int h = c >> 6, d = c & 63;
                    int b = row >> 10, t = row & 1023;
                    uint32_t lw;
                    uint32_t hw = pack_split(v0, v1, lw);
                    if (which < 2) {
                        size_t base = (((size_t)(b * HH + h)) * TT + t) * HD + d;
                        bf16* H = which ? okh : outH;
                        bf16* L = which ? okl : outL;
                        *(uint32_t*)(H + base) = hw;
                        *(uint32_t*)(L + base) = lw;
                    } else {
                        size_t vb = (((size_t)(b * HH + h)) * HD + d) * TT + t;
                        ovh[vb]      = __ushort_as_bfloat16((unsigned short)(hw & 0xffff));
                        ovh[vb + TT] = __ushort_as_bfloat16((unsigned short)(hw >> 16));
                        ovl[vb]      = __ushort_as_bfloat16((unsigned short)(lw & 0xffff));
                        ovl[vb + TT] = __ushort_as_bfloat16((unsigned short)(lw >> 16));
                    }
                } else {
                    long long base = (long long)row * ldc + col;
                    if (bias) { v0 += bias[col]; v1 += bias[col + 1]; }
                    if (res)  { v0 += res[base]; v1 += res[base + 1]; }
                    if (relu) { v0 = fmaxf(v0, 0.f); v1 = fmaxf(v1, 0.f); }
                    if (outF) *(float2*)(outF + base) = make_float2(v0, v1);
                    if (outH) {
                        uint32_t lw;
                        uint32_t hw = pack_split(v0, v1, lw);
                        *(uint32_t*)(outH + base) = hw;
                        *(uint32_t*)(outL + base) = lw;
                    }
                }
            }
        }
    }
}

// ---------------- 2-pass fp16 GEMM (FFN1, FFN2, LM head) ----------------
// A: [M,K] fp16 single; B: [N,K] fp16 hi/lo. M,N,K % 128 == 0.
// C = A@(Bh+Bl)^T + bias (+res) (relu); out: fp32 and/or fp16 single.
__global__ __launch_bounds__(256, 2)
void gemm_2p(const h16* __restrict__ A,
             const h16* __restrict__ Bh, const h16* __restrict__ Bl,
             const float* __restrict__ bias, const float* __restrict__ res,
             float* __restrict__ outF, h16* __restrict__ outH16,
             int M, int N, int K, int relu)
{
    constexpr int MI = 2;
    constexpr int NI = 8;
    constexpr int ASZ = BM * LDS;
    constexpr int BSZ = BN_ * LDS;

    const int m0 = blockIdx.y * BM;
    const int n0 = blockIdx.x * BN_;

    extern __shared__ h16 smh[];
    const uint32_t sbase = smem_u32(smh);

    const int tid = threadIdx.x;
    const int nch = K >> 5;

    auto load_stage = [&](int st, int k0) {
        #pragma unroll
        for (int i = tid; i < BM * 4; i += 256) {
            int r = i >> 2, c8 = (i & 3) << 3;
            size_t go = (size_t)(m0 + r) * K + k0 + c8;
            uint32_t so = (uint32_t)((st * ASZ + r * LDS + c8) * 2);
            cpa16(sbase + so, A + go, 16);
        }
        #pragma unroll
        for (int i = tid; i < BN_ * 4; i += 256) {
            int r = i >> 2, c8 = (i & 3) << 3;
            size_t go = (size_t)(n0 + r) * K + k0 + c8;
            uint32_t so = (uint32_t)((2 * ASZ + st * BSZ + r * LDS + c8) * 2);
            cpa16(sbase + so, Bh + go, 16);
            cpa16(sbase + so + 2 * BSZ * 2, Bl + go, 16);
        }
        asm volatile("cp.async.commit_group;" ::: "memory");
    };

    const int wid = tid >> 5, lane = tid & 31;
    const int wr = wid & 3, wc = wid >> 2;
    const int wmBase = wr * 32, wnBase = wc * 64;

    float acc[MI][NI][4];
    #pragma unroll
    for (int mi = 0; mi < MI; mi++)
        #pragma unroll
        for (int ni = 0; ni < NI; ni++)
            #pragma unroll
            for (int j = 0; j < 4; j++) acc[mi][ni][j] = 0.f;

    load_stage(0, 0);

    for (int ch = 0; ch < nch; ch++) {
        asm volatile("cp.async.wait_group 0;" ::: "memory");
        __syncthreads();
        if (ch + 1 < nch) load_stage((ch + 1) & 1, (ch + 1) << 5);

        const int st = ch & 1;
        const uint32_t aB  = sbase + (uint32_t)(st * ASZ * 2);
        const uint32_t bHb = sbase + (uint32_t)((2 * ASZ + st * BSZ) * 2);
        const uint32_t bLb = bHb + (uint32_t)(2 * BSZ * 2);

        #pragma unroll
        for (int kk = 0; kk < 2; kk++) {
            const int colOff = kk * 16 + ((lane >> 4) << 3);
            uint32_t af[MI][4];
            #pragma unroll
            for (int mi = 0; mi < MI; mi++) {
                uint32_t off = (uint32_t)(((wmBase + mi * 16 + (lane & 15)) * LDS + colOff) * 2);
                ldsm4(af[mi], aB + off);
            }
            uint32_t bfH[4][4], bfL[4][4];
            #pragma unroll
            for (int nj = 0; nj < 4; nj++) {
                uint32_t off = (uint32_t)(((wnBase + nj * 16 + (lane & 15)) * LDS + colOff) * 2);
                ldsm4(bfH[nj], bHb + off);
                ldsm4(bfL[nj], bLb + off);
            }
            #pragma unroll
            for (int nj = 0; nj < 4; nj++) {
                #pragma unroll
                for (int mi = 0; mi < MI; mi++) {
                    mma_f16(acc[mi][2*nj],   af[mi], bfH[nj][0], bfH[nj][2]);
                    mma_f16(acc[mi][2*nj+1], af[mi], bfH[nj][1], bfH[nj][3]);
                }
                #pragma unroll
                for (int mi = 0; mi < MI; mi++) {
                    mma_f16(acc[mi][2*nj],   af[mi], bfL[nj][0], bfL[nj][2]);
                    mma_f16(acc[mi][2*nj+1], af[mi], bfL[nj][1], bfL[nj][3]);
                }
            }
        }
    }

    const int g = lane >> 2, t4 = lane & 3;
    #pragma unroll
    for (int mi = 0; mi < MI; mi++) {
        #pragma unroll
        for (int ni = 0; ni < NI; ni++) {
            int col = n0 + wnBase + ni * 8 + t4 * 2;
            #pragma unroll
            for (int half = 0; half < 2; half++) {
                int row = m0 + wmBase + mi * 16 + g + half * 8;
                long long base = (long long)row * N + col;
                float v0 = acc[mi][ni][half * 2 + 0] + bias[col];
                float v1 = acc[mi][ni][half * 2 + 1] + bias[col + 1];
                if (res) { v0 += res[base]; v1 += res[base + 1]; }
                if (relu) { v0 = fmaxf(v0, 0.f); v1 = fmaxf(v1, 0.f); }
                if (outF) *(float2*)(outF + base) = make_float2(v0, v1);
                if (outH16) {
                    __half2 hv = __floats2half2_rn(v0, v1);
                    *(__half2*)(outH16 + base) = hv;
                }
            }
        }
    }
}

// ---------------- fused flash attention (register-P, 2 CTA/SM, longest-first) ----------------
#define LDF 72
__global__ __launch_bounds__(256, 2)
void flash_attn_k(const bf16* __restrict__ qh, const bf16* __restrict__ ql,
                  const bf16* __restrict__ kh, const bf16* __restrict__ kl,
                  const bf16* __restrict__ vth, const bf16* __restrict__ vtl,
                  bf16* __restrict__ oh, bf16* __restrict__ ol)
{
    extern __shared__ bf16 sm[];
    const uint32_t sbase = smem_u32(sm);
    const int id = blockIdx.x;
    const int rb = 7 - (id >> 6);
    const int bh = id & 63;
    const int m0 = rb * 128;
    const int tid = threadIdx.x, wid = tid >> 5, lane = tid & 31;
    const int g = lane >> 2, t4 = lane & 3;

    const uint32_t OQH = 0, OQL = 128*LDF;
    const uint32_t OKV = 2*128*LDF;
    const uint32_t KVS = 4*64*LDF;

    for (int i = tid; i < 128 * 8; i += 256) {
        int r = i >> 3, c = (i & 7) << 3;
        size_t go = ((size_t)bh * TT + m0 + r) * HD + c;
        cpa16(sbase + (OQH + r * LDF + c) * 2, qh + go, 16);
        cpa16(sbase + (OQL + r * LDF + c) * 2, ql + go, 16);
    }
    asm volatile("cp.async.commit_group;" ::: "memory");

    auto load_kv = [&](int st, int j0) {
        uint32_t base = OKV + (uint32_t)st * KVS;
        for (int i = tid; i < 64 * 8; i += 256) {
            int r = i >> 3, c = (i & 7) << 3;
            size_t gk = ((size_t)bh * TT + j0 + r) * HD + c;
            size_t gv = ((size_t)bh * HD + r) * TT + j0 + c;
            cpa16(sbase + (base            + r * LDF + c) * 2, kh  + gk, 16);
            cpa16(sbase + (base +   64*LDF + r * LDF + c) * 2, kl  + gk, 16);
            cpa16(sbase + (base + 2*64*LDF + r * LDF + c) * 2, vth + gv, 16);
            cpa16(sbase + (base + 3*64*LDF + r * LDF + c) * 2, vtl + gv, 16);
        }
        asm volatile("cp.async.commit_group;" ::: "memory");
    };

    const int ntiles = 2 * rb + 2;
    load_kv(0, 0);

    float oacc[8][4];
    #pragma unroll
    for (int ni = 0; ni < 8; ni++)
        #pragma unroll
        for (int j = 0; j < 4; j++) oacc[ni][j] = 0.f;
    float mrow[2] = { -1e30f, -1e30f };
    float lrow[2] = { 0.f, 0.f };

    const int row0 = m0 + wid * 16 + g;

    for (int t = 0; t < ntiles; t++) {
        const int j0 = t << 6;
        asm volatile("cp.async.wait_group 0;" ::: "memory");
        __syncthreads();
        if (t + 1 < ntiles) load_kv((t + 1) & 1, j0 + 64);

        const uint32_t kvb = OKV + (uint32_t)(t & 1) * KVS;
        const uint32_t kHb = sbase + kvb * 2;
        const uint32_t kLb = sbase + (kvb + 64*LDF) * 2;
        const uint32_t vHb = sbase + (kvb + 2*64*LDF) * 2;
        const uint32_t vLb = sbase + (kvb + 3*64*LDF) * 2;

        float acc[8][4];
        #pragma unroll
        for (int ni = 0; ni < 8; ni++)
            #pragma unroll
            for (int j = 0; j < 4; j++) acc[ni][j] = 0.f;

        #pragma unroll
        for (int kk = 0; kk < 4; kk++) {
            const int colOff = kk * 16 + ((lane >> 4) << 3);
            uint32_t aH[4], aL[4];
            uint32_t aoff = (uint32_t)(((wid * 16 + (lane & 15)) * LDF + colOff) * 2);
            ldsm4(aH, sbase + (OQH * 2) + aoff);
            ldsm4(aL, sbase + (OQL * 2) + aoff);
            uint32_t bH[4][4], bL[4][4];
            #pragma unroll
            for (int nj = 0; nj < 4; nj++) {
                uint32_t boff = (uint32_t)(((nj * 16 + (lane & 15)) * LDF + colOff) * 2);
                ldsm4(bH[nj], kHb + boff);
                ldsm4(bL[nj], kLb + boff);
            }
            #pragma unroll
            for (int nj = 0; nj < 4; nj++) {
                mma_bf16(acc[2*nj],   aH, bH[nj][0], bH[nj][2]);
                mma_bf16(acc[2*nj+1], aH, bH[nj][1], bH[nj][3]);
                mma_bf16(acc[2*nj],   aH, bL[nj][0], bL[nj][2]);
                mma_bf16(acc[2*nj+1], aH, bL[nj][1], bL[nj][3]);
                mma_bf16(acc[2*nj],   aL, bH[nj][0], bH[nj][2]);
                mma_bf16(acc[2*nj+1], aL, bH[nj][1], bH[nj][3]);
            }
        }

        #pragma unroll
        for (int ni = 0; ni < 8; ni++) {
            int colBase = j0 + ni * 8 + t4 * 2;
            #pragma unroll
            for (int j = 0; j < 4; j++) {
                int row = row0 + ((j >> 1) << 3);
                int col = colBase + (j & 1);
                float v = acc[ni][j] * 0.125f;
                acc[ni][j] = (col <= row) ? v : -1e30f;
            }
        }

        #pragma unroll
        for (int half = 0; half < 2; half++) {
            float mt = -1e30f;
            #pragma unroll
            for (int ni = 0; ni < 8; ni++) {
                mt = fmaxf(mt, acc[ni][half*2+0]);
                mt = fmaxf(mt, acc[ni][half*2+1]);
            }
            mt = fmaxf(mt, __shfl_xor_sync(0xffffffffu, mt, 1));
            mt = fmaxf(mt, __shfl_xor_sync(0xffffffffu, mt, 2));
            float mnew = fmaxf(mrow[half], mt);
            float scale = __expf(mrow[half] - mnew);
            mrow[half] = mnew;
            float sum = 0.f;
            #pragma unroll
            for (int ni = 0; ni < 8; ni++) {
                float e0 = __expf(acc[ni][half*2+0] - mnew);
                float e1 = __expf(acc[ni][half*2+1] - mnew);
                acc[ni][half*2+0] = e0;
                acc[ni][half*2+1] = e1;
                sum += e0 + e1;
            }
            sum += __shfl_xor_sync(0xffffffffu, sum, 1);
            sum += __shfl_xor_sync(0xffffffffu, sum, 2);
            lrow[half] = lrow[half] * scale + sum;
            #pragma unroll
            for (int ni = 0; ni < 8; ni++) {
                oacc[ni][half*2+0] *= scale;
                oacc[ni][half*2+1] *= scale;
            }
        }

        #pragma unroll
        for (int kk = 0; kk < 4; kk++) {
            uint32_t aH[4], aL[4];
            aH[0] = pack_split(acc[2*kk][0],   acc[2*kk][1],   aL[0]);
            aH[1] = pack_split(acc[2*kk][2],   acc[2*kk][3],   aL[1]);
            aH[2] = pack_split(acc[2*kk+1][0], acc[2*kk+1][1], aL[2]);
            aH[3] = pack_split(acc[2*kk+1][2], acc[2*kk+1][3], aL[3]);
            const int colOff = kk * 16 + ((lane >> 4) << 3);
            uint32_t bH[4][4], bL[4][4];
            #pragma unroll
            for (int nj = 0; nj < 4; nj++) {
                uint32_t boff = (uint32_t)(((nj * 16 + (lane & 15)) * LDF + colOff) * 2);
                ldsm4(bH[nj], vHb + boff);
                ldsm4(bL[nj], vLb + boff);
            }
            #pragma unroll
            for (int nj = 0; nj < 4; nj++) {
                mma_bf16(oacc[2*nj],   aH, bH[nj][0], bH[nj][2]);
                mma_bf16(oacc[2*nj+1], aH, bH[nj][1], bH[nj][3]);
                mma_bf16(oacc[2*nj],   aH, bL[nj][0], bL[nj][2]);
                mma_bf16(oacc[2*nj+1], aH, bL[nj][1], bL[nj][3]);
                mma_bf16(oacc[2*nj],   aL, bH[nj][0], bH[nj][2]);
                mma_bf16(oacc[2*nj+1], aL, bH[nj][1], bH[nj][3]);
            }
        }
    }

    const int b = bh >> 4, h = bh & 15;
    float inv0 = 1.f / lrow[0], inv1 = 1.f / lrow[1];
    #pragma unroll
    for (int ni = 0; ni < 8; ni++) {
        int d = ni * 8 + t4 * 2;
        #pragma unroll
        for (int half = 0; half < 2; half++) {
            int trow = m0 + wid * 16 + g + half * 8;
            float inv = half ? inv1 : inv0;
            size_t base = ((size_t)b * TT + trow) * CC + h * HD + d;
            uint32_t lw;
            uint32_t hw = pack_split(oacc[ni][half*2+0] * inv,
                                     oacc[ni][half*2+1] * inv, lw);
            *(uint32_t*)(oh + base) = hw;
            *(uint32_t*)(ol + base) = lw;
        }
    }
}

// ---------------- block reductions ----------------
__device__ __forceinline__ float blockReduceSum256(float v, float* sh) {
    #pragma unroll
    for (int o = 16; o > 0; o >>= 1) v += __shfl_xor_sync(0xffffffffu, v, o);
    int w = threadIdx.x >> 5;
    if ((threadIdx.x & 31) == 0) sh[w] = v;
    __syncthreads();
    if (threadIdx.x < 8) {
        v = sh[threadIdx.x];
        #pragma unroll
        for (int o = 4; o > 0; o >>= 1) v += __shfl_xor_sync(0xffu, v, o);
        if (threadIdx.x == 0) sh[0] = v;
    }
    __syncthreads();
    float r = sh[0]; __syncthreads(); return r;
}

__device__ __forceinline__ void split_store(bf16* H, bf16* L, size_t i, float v) {
    bf16 h = __float2bfloat16(v);
    H[i] = h;
    L[i] = __float2bfloat16(v - __bfloat162float(h));
}
__device__ __forceinline__ void split_store_h(h16* H, h16* L, size_t i, float v) {
    h16 h = __float2half(v);
    H[i] = h;
    L[i] = __float2half(v - __half2float(h));
}

// ---------------- layernorm -> split bf16 ----------------
__global__ __launch_bounds__(256)
void layernorm_split_k(const float* __restrict__ x, const float* __restrict__ g,
                       const float* __restrict__ b, bf16* __restrict__ oh, bf16* __restrict__ ol)
{
    __shared__ float sh[8];
    const size_t row = blockIdx.x;
    const float* xr = x + row * CC;
    const int c = threadIdx.x * 4;
    float4 xv = *(const float4*)(xr + c);
    float s  = xv.x + xv.y + xv.z + xv.w;
    float ss = xv.x*xv.x + xv.y*xv.y + xv.z*xv.z + xv.w*xv.w;
    s = blockReduceSum256(s, sh);
    ss = blockReduceSum256(ss, sh);
    float mean = s * (1.f / CC);
    float var = ss * (1.f / CC) - mean * mean;
    float inv = rsqrtf(var + 1e-5f);
    float4 gv = *(const float4*)(g + c);
    float4 bv = *(const float4*)(b + c);
    size_t base = row * CC + c;
    split_store(oh, ol, base + 0, (xv.x - mean) * inv * gv.x + bv.x);
    split_store(oh, ol, base + 1, (xv.y - mean) * inv * gv.y + bv.y);
    split_store(oh, ol, base + 2, (xv.z - mean) * inv * gv.z + bv.z);
    split_store(oh, ol, base + 3, (xv.w - mean) * inv * gv.w + bv.w);
}

// ---------------- layernorm -> single fp16 ----------------
__global__ __launch_bounds__(256)
void layernorm_h16_k(const float* __restrict__ x, const float* __restrict__ g,
                     const float* __restrict__ b, h16* __restrict__ o)
{
    __shared__ float sh[8];
    const size_t row = blockIdx.x;
    const float* xr = x + row * CC;
    const int c = threadIdx.x * 4;
    float4 xv = *(const float4*)(xr + c);
    float s  = xv.x + xv.y + xv.z + xv.w;
    float ss = xv.x*xv.x + xv.y*xv.y + xv.z*xv.z + xv.w*xv.w;
    s = blockReduceSum256(s, sh);
    ss = blockReduceSum256(ss, sh);
    float mean = s * (1.f / CC);
    float var = ss * (1.f / CC) - mean * mean;
    float inv = rsqrtf(var + 1e-5f);
    float4 gv = *(const float4*)(g + c);
    float4 bv = *(const float4*)(b + c);
    size_t base = row * CC + c;
    o[base + 0] = __float2half((xv.x - mean) * inv * gv.x + bv.x);
    o[base + 1] = __float2half((xv.y - mean) * inv * gv.y + bv.y);
    o[base + 2] = __float2half((xv.z - mean) * inv * gv.z + bv.z);
    o[base + 3] = __float2half((xv.w - mean) * inv * gv.w + bv.w);
}

// ---------------- fused embed + layer0 LN1 -> x and split bf16 ----------------
__global__ __launch_bounds__(256)
void embed_ln_k(const int* __restrict__ toks, const float* __restrict__ tok_emb,
                const float* __restrict__ txt_pos, const float* __restrict__ img_pos,
                const float* __restrict__ p, const float* __restrict__ g,
                const float* __restrict__ b,
                float* __restrict__ x, bf16* __restrict__ oh, bf16* __restrict__ ol)
{
    __shared__ float sh[8];
    const int bt = blockIdx.x;
    const int bb = bt >> 10;
    const int t = bt & 1023;
    const int c = threadIdx.x * 4;
    const float* src;
    const float* extra = nullptr;
    if (t == 0)      src = tok_emb + 1 * CC;
    else if (t == 1) src = tok_emb + 8 * CC;
    else if (t < 443) {
        int n = t - 2;
        src = p + ((size_t)(bb * NPATCH + n)) * CC;
        extra = img_pos + (size_t)n * CC;
    }
    else if (t == 443) src = tok_emb + 9 * CC;
    else {
        int tok = toks[bb * TTXT + (t - 444)];
        src = tok_emb + (size_t)tok * CC;
    }
    float4 v = *(const float4*)(src + c);
    float4 tp = *(const float4*)(txt_pos + (size_t)t * CC + c);
    v.x += tp.x; v.y += tp.y; v.z += tp.z; v.w += tp.w;
    if (extra) {
        float4 e = *(const float4*)(extra + c);
        v.x += e.x; v.y += e.y; v.z += e.z; v.w += e.w;
    }
    size_t base = (size_t)bt * CC + c;
    *(float4*)(x + base) = v;

    float s  = v.x + v.y + v.z + v.w;
    float ss = v.x*v.x + v.y*v.y + v.z*v.z + v.w*v.w;
    s = blockReduceSum256(s, sh);
    ss = blockReduceSum256(ss, sh);
    float mean = s * (1.f / CC);
    float var = ss * (1.f / CC) - mean * mean;
    float inv = rsqrtf(var + 1e-5f);
    float4 gv = *(const float4*)(g + c);
    float4 bv = *(const float4*)(b + c);
    split_store(oh, ol, base + 0, (v.x - mean) * inv * gv.x + bv.x);
    split_store(oh, ol, base + 1, (v.y - mean) * inv * gv.y + bv.y);
    split_store(oh, ol, base + 2, (v.z - mean) * inv * gv.z + bv.z);
    split_store(oh, ol, base + 3, (v.w - mean) * inv * gv.w + bv.w);
}

// ---------------- fused weight prep + im2col in ONE launch ----------------
__device__ __forceinline__ void transpose_tile(const float* __restrict__ W,
                                               bf16* __restrict__ hi, bf16* __restrict__ lo,
                                               int K, int N, int k0, int n0,
                                               float tbuf[32][33])
{
    int tx = threadIdx.x, ty = threadIdx.y;
    #pragma unroll
    for (int i = 0; i < 32; i += 8)
        tbuf[ty + i][tx] = W[(size_t)(k0 + ty + i) * N + n0 + tx];
    __syncthreads();
    #pragma unroll
    for (int i = 0; i < 32; i += 8)
        split_store(hi, lo, (size_t)(n0 + ty + i) * K + k0 + tx, tbuf[tx][ty + i]);
}
__device__ __forceinline__ void transpose_tile_h(const float* __restrict__ W,
                                                 h16* __restrict__ hi, h16* __restrict__ lo,
                                                 int K, int N, int k0, int n0,
                                                 float tbuf[32][33])
{
    int tx = threadIdx.x, ty = threadIdx.y;
    #pragma unroll
    for (int i = 0; i < 32; i += 8)
        tbuf[ty + i][tx] = W[(size_t)(k0 + ty + i) * N + n0 + tx];
    __syncthreads();
    #pragma unroll
    for (int i = 0; i < 32; i += 8)
        split_store_h(hi, lo, (size_t)(n0 + ty + i) * K + k0 + tx, tbuf[tx][ty + i]);
}

#define TPM_CC  1024
#define T_QKV   (LL*TPM_CC)
#define T_W1    (LL*(32*128))
#define T_LM    (32*500)
#define T_PATCH 768
#define T_IM2C  ((BB*NPATCH*KIM)/1024)   // 1323

__global__ void prep_weights_k(const float* __restrict__ wq, const float* __restrict__ wk,
                               const float* __restrict__ wv, const float* __restrict__ wo,
                               const float* __restrict__ w1, const float* __restrict__ w2,
                               const float* __restrict__ lm_w, const float* __restrict__ patch_w,
                               const float* __restrict__ images,
                               bf16* qkvh, bf16* qkvl, bf16* woh, bf16* wol,
                               h16* w1h, h16* w1l, h16* w2h, h16* w2l,
                               h16* lmh, h16* lml, bf16* pwh, bf16* pwl,
                               bf16* imh, bf16* iml)
{
    __shared__ float tbuf[32][33];
    int t = blockIdx.x;
    const long long QKV_Z = (long long)3 * CC * CC;

    if (t < 3 * T_QKV) {
        int which = t / T_QKV;
        int r = t % T_QKV;
        int l = r / TPM_CC;
        int loc = r % TPM_CC;
        int n0 = (loc & 31) * 32, k0 = (loc >> 5) * 32;
        const float* W = (which == 0 ? wq : which == 1 ? wk : wv) + (size_t)l * CC * CC;
        bf16* hi = qkvh + (size_t)l * QKV_Z + (size_t)which * CC * CC;
        bf16* lo = qkvl + (size_t)l * QKV_Z + (size_t)which * CC * CC;
        transpose_tile(W, hi, lo, CC, CC, k0, n0, tbuf);
        return;
    }
    t -= 3 * T_QKV;
    if (t < T_QKV) {
        int l = t / TPM_CC, loc = t % TPM_CC;
        int n0 = (loc & 31) * 32, k0 = (loc >> 5) * 32;
        transpose_tile(wo + (size_t)l * CC * CC, woh + (size_t)l * CC * CC,
                       wol + (size_t)l * CC * CC, CC, CC, k0, n0, tbuf);
        return;
    }
    t -= T_QKV;
    if (t < T_W1) {
        int l = t / (32 * 128), loc = t % (32 * 128);
        int n0 = (loc % 128) * 32, k0 = (loc / 128) * 32;
        transpose_tile_h(w1 + (size_t)l * CC * FF_, w1h + (size_t)l * CC * FF_,
                         w1l + (size_t)l * CC * FF_, CC, FF_, k0, n0, tbuf);
        return;
    }
    t -= T_W1;
    if (t < T_W1) {
        int l = t / (128 * 32), loc = t % (128 * 32);
        int n0 = (loc & 31) * 32, k0 = (loc >> 5) * 32;
        transpose_tile_h(w2 + (size_t)l * CC * FF_, w2h + (size_t)l * CC * FF_,
                         w2l + (size_t)l * CC * FF_, FF_, CC, k0, n0, tbuf);
        return;
    }
    t -= T_W1;
    if (t < T_LM) {
        int n0 = (t % 500) * 32, k0 = (t / 500) * 32;
        transpose_tile_h(lm_w, lmh, lml, CC, VV, k0, n0, tbuf);
        return;
    }
    t -= T_LM;
    if (t < T_PATCH) {
        int base = t * 1024;
        int tid = threadIdx.y * 32 + threadIdx.x;
        #pragma unroll
        for (int i = 0; i < 4; i++) {
            int idx = base + tid + i * 256;
            split_store(pwh, pwl, idx, patch_w[idx]);
        }
        return;
    }
    t -= T_PATCH;
    {
        int tid = threadIdx.y * 32 + threadIdx.x;
        #pragma unroll
        for (int i = 0; i < 4; i++) {
            int idx = t * 1024 + tid + i * 256;
            int k = idx % KIM;
            int bn = idx / KIM;
            int n = bn % NPATCH;
            int b = bn / NPATCH;
            int ci = k >> 8;
            int rr = k & 255;
            int kh = rr >> 4;
            int kw = rr & 15;
            int ph = n / 21, pw = n % 21;
            float v = images[(((size_t)b * 3 + ci) * IMG + ph * PATCH + kh) * IMG + pw * PATCH + kw];
            split_store(imh, iml, idx, v);
        }
    }
}

// ---------------- host-side GEMM launchers ----------------
#define SMEM_GEMM  ((4 * 128 * LDS + 4 * 128 * LDS) * 2)
#define SMEM_2P    ((2 * 128 * LDS + 4 * 128 * LDS) * 2)

static inline void tc(const bf16* Ah, const bf16* Al, const bf16* Bh, const bf16* Bl,
                      const float* bias, const float* res,
                      float* outF, bf16* outH, bf16* outL,
                      int M, int N, int K, int ldc,
                      float alpha = 1.f, int relu = 0, int outMode = 0,
                      bf16* okh = nullptr, bf16* okl = nullptr,
                      bf16* ovh = nullptr, bf16* ovl = nullptr)
{
    dim3 grid((N + 127) / 128, (M + 127) / 128, 1);
    gemm_mma<<<grid, 256, SMEM_GEMM>>>(Ah, Al, Bh, Bl, bias, res,
        outF, outH, outL, okh, okl, ovh, ovl, M, N, K, ldc, alpha, relu, outMode);
}

static inline void tc2p(const h16* A, const h16* Bh, const h16* Bl,
                        const float* bias, const float* res,
                        float* outF, h16* outH16, int M, int N, int K, int relu = 0)
{
    dim3 grid(N / 128, M / 128);
    gemm_2p<<<grid, 256, SMEM_2P>>>(A, Bh, Bl, bias, res, outF, outH16, M, N, K, relu);
}

#define SYM(name) ({ void* _p; cudaGetSymbolAddress(&_p, name); _p; })

extern "C" void kernel_launch(void* const* d_in, const int* in_sizes, int n_in,
                              void* d_out, int out_size)
{
    const int*   text_tokens = (const int*)  d_in[0];
    const float* images      = (const float*)d_in[1];
    const float* tok_emb     = (const float*)d_in[2];
    const float* txt_pos     = (const float*)d_in[3];
    const float* img_pos     = (const float*)d_in[4];
    const float* patch_w     = (const float*)d_in[5];
    const float* patch_b     = (const float*)d_in[6];
    const float* ln1_g       = (const float*)d_in[7];
    const float* ln1_b       = (const float*)d_in[8];
    const float* wq          = (const float*)d_in[9];
    const float* wk          = (const float*)d_in[10];
    const float* wv          = (const float*)d_in[11];
    const float* wo          = (const float*)d_in[12];
    const float* bo          = (const float*)d_in[13];
    const float* ln2_g       = (const float*)d_in[14];
    const float* ln2_b       = (const float*)d_in[15];
    const float* w1          = (const float*)d_in[16];
    const float* b1          = (const float*)d_in[17];
    const float* w2          = (const float*)d_in[18];
    const float* b2          = (const float*)d_in[19];
    const float* lnf_g       = (const float*)d_in[20];
    const float* lnf_b       = (const float*)d_in[21];
    const float* lm_w        = (const float*)d_in[22];
    const float* lm_b        = (const float*)d_in[23];
    float* out = (float*)d_out;

    cudaFuncSetAttribute(gemm_mma, cudaFuncAttributeMaxDynamicSharedMemorySize, SMEM_GEMM);
    cudaFuncSetAttribute(gemm_2p,  cudaFuncAttributeMaxDynamicSharedMemorySize, SMEM_2P);
    const int FLASH_SMEM = (2 * 128 * LDF + 2 * 4 * 64 * LDF) * 2;
    cudaFuncSetAttribute(flash_attn_k, cudaFuncAttributeMaxDynamicSharedMemorySize, FLASH_SMEM);

    float* px   = (float*)SYM(g_x);
    float* ppp  = (float*)SYM(g_pp);
    bf16 *pqh = (bf16*)SYM(g_qh), *pql = (bf16*)SYM(g_ql);
    bf16 *pkh = (bf16*)SYM(g_kh), *pkl = (bf16*)SYM(g_kl);
    bf16 *pvth = (bf16*)SYM(g_vth), *pvtl = (bf16*)SYM(g_vtl);
    bf16 *pah = (bf16*)SYM(g_ah), *pal = (bf16*)SYM(g_al);
    h16  *pf16 = (h16*)SYM(g_f16);
    bf16 *pwqkvh = (bf16*)SYM(g_wqkvh), *pwqkvl = (bf16*)SYM(g_wqkvl);
    bf16 *pwoh = (bf16*)SYM(g_woh), *pwol = (bf16*)SYM(g_wol);
    h16  *pw1h = (h16*)SYM(g_w1h), *pw1l = (h16*)SYM(g_w1l);
    h16  *pw2h = (h16*)SYM(g_w2h), *pw2l = (h16*)SYM(g_w2l);
    h16  *plmh = (h16*)SYM(g_lmh), *plml = (h16*)SYM(g_lml);
    bf16 *ppwh = (bf16*)SYM(g_pwh), *ppwl = (bf16*)SYM(g_pwl);
    bf16 *pimh = (bf16*)SYM(g_imh), *piml = (bf16*)SYM(g_iml);
    h16  *pah16 = (h16*)pah;                 // reuse activation buffer as fp16

    // ---- [1] all weight prep + im2col in one launch ----
    const int nPrep = 4 * T_QKV + 2 * T_W1 + T_LM + T_PATCH + T_IM2C;
    prep_weights_k<<<nPrep, dim3(32, 8)>>>(wq, wk, wv, wo, w1, w2, lm_w, patch_w, images,
        pwqkvh, pwqkvl, pwoh, pwol, pw1h, pw1l, pw2h, pw2l, plmh, plml, ppwh, ppwl,
        pimh, piml);

    // ---- [2] patch GEMM  [3] fused embed+LN1(l=0) ----
    tc(pimh, piml, ppwh, ppwl, patch_b, nullptr, ppp, nullptr, nullptr,
       BB*NPATCH, CC, KIM, CC);
    embed_ln_k<<<BB*TT, 256>>>(text_tokens, tok_emb, txt_pos, img_pos, ppp,
                               ln1_g, ln1_b, px, pah, pal);

    const int M = MTOK;
    for (int l = 0; l < LL; l++) {
        size_t wOff = (size_t)l * CC * CC, w1Off = (size_t)l * CC * FF_;
        size_t qkvOff = (size_t)l * 3 * CC * CC;

        if (l > 0)
            layernorm_split_k<<<M, 256>>>(px, ln1_g + l*CC, ln1_b + l*CC, pah, pal);

        tc(pah, pal, pwqkvh + qkvOff, pwqkvl + qkvOff, nullptr, nullptr,
           nullptr, pqh, pql, M, 3*CC, CC, 0, 1.f, 0, /*outMode*/1,
           pkh, pkl, pvth, pvtl);

        flash_attn_k<<<BB*HH*8, 256, FLASH_SMEM>>>(
            pqh, pql, pkh, pkl, pvth, pvtl, pah, pal);

        tc(pah, pal, pwoh + wOff, pwol + wOff, bo + l*CC, px, px, nullptr, nullptr,
           M, CC, CC, CC);

        // LN2 -> single fp16, then 2-pass fp16 FFN
        layernorm_h16_k<<<M, 256>>>(px, ln2_g + l*CC, ln2_b + l*CC, pah16);
        tc2p(pah16, pw1h + w1Off, pw1l + w1Off, b1 + l*FF_, nullptr,
             nullptr, pf16, M, FF_, CC, /*relu*/1);
        tc2p(pf16, pw2h + w1Off, pw2l + w1Off, b2 + l*CC, px,
             px, nullptr, M, CC, FF_);
    }

    // ---- final LN (single fp16) + LM head (2-pass fp16) ----
    layernorm_h16_k<<<M, 256>>>(px, lnf_g, lnf_b, pah16);
    tc2p(pah16, plmh, plml, lm_b, nullptr, out, nullptr, M, VV, CC);
}

// round 17
// speedup vs baseline: 3.0713x; 1.1486x over previous
#include <cuda_runtime.h>
#include <cuda_bf16.h>
#include <cuda_fp16.h>
#include <cstdint>

typedef __nv_bfloat16 bf16;
typedef __half h16;

// ---------------- problem constants ----------------
#define BB    4
#define TT    1024
#define CC    1024
#define HH    16
#define HD    64
#define LL    6
#define VV    16000
#define TTXT  580
#define FF_   4096
#define NPATCH 441
#define KIM   768
#define IMG   336
#define PATCH 16
#define MTOK  (BB*TT)          // 4096

// ---------------- scratch (device globals; no allocation) ----------------
__device__ float g_x  [(size_t)MTOK*CC];
__device__ float g_pp [(size_t)BB*NPATCH*CC];

__device__ h16 g_a16[(size_t)MTOK*CC];          // LN out / flash out (single fp16)
__device__ h16 g_f16[(size_t)MTOK*FF_];         // FFN intermediate
__device__ h16 g_q16[(size_t)MTOK*CC];
__device__ h16 g_kh16[(size_t)MTOK*CC], g_kl16[(size_t)MTOK*CC];
__device__ h16 g_vth16[(size_t)MTOK*CC], g_vtl16[(size_t)MTOK*CC];

__device__ h16 g_wqkvh[(size_t)LL*3*CC*CC], g_wqkvl[(size_t)LL*3*CC*CC];
__device__ h16 g_woh[(size_t)LL*CC*CC], g_wol[(size_t)LL*CC*CC];
__device__ h16 g_w1h[(size_t)LL*CC*FF_], g_w1l[(size_t)LL*CC*FF_];
__device__ h16 g_w2h[(size_t)LL*CC*FF_], g_w2l[(size_t)LL*CC*FF_];
__device__ h16 g_lmh[(size_t)CC*VV],    g_lml[(size_t)CC*VV];
__device__ bf16 g_pwh[(size_t)CC*KIM],  g_pwl[(size_t)CC*KIM];
__device__ bf16 g_imh[(size_t)BB*NPATCH*KIM], g_iml[(size_t)BB*NPATCH*KIM];

// ---------------- low-level helpers ----------------
__device__ __forceinline__ uint32_t smem_u32(const void* p) {
    uint32_t a;
    asm("{ .reg .u64 t; cvta.to.shared.u64 t, %1; cvt.u32.u64 %0, t; }" : "=r"(a) : "l"(p));
    return a;
}
__device__ __forceinline__ void cpa16(uint32_t dst, const void* src, int szbytes) {
    asm volatile("cp.async.cg.shared.global [%0], [%1], 16, %2;"
                 :: "r"(dst), "l"(src), "r"(szbytes) : "memory");
}
__device__ __forceinline__ void ldsm4(uint32_t (&r)[4], uint32_t addr) {
    asm volatile("ldmatrix.sync.aligned.m8n8.x4.shared.b16 {%0,%1,%2,%3}, [%4];"
                 : "=r"(r[0]), "=r"(r[1]), "=r"(r[2]), "=r"(r[3]) : "r"(addr));
}
__device__ __forceinline__ void mma_bf16(float (&d)[4], const uint32_t (&a)[4],
                                         uint32_t b0, uint32_t b1) {
    asm volatile("mma.sync.aligned.m16n8k16.row.col.f32.bf16.bf16.f32 "
                 "{%0,%1,%2,%3}, {%4,%5,%6,%7}, {%8,%9}, {%0,%1,%2,%3};"
                 : "+f"(d[0]), "+f"(d[1]), "+f"(d[2]), "+f"(d[3])
                 : "r"(a[0]), "r"(a[1]), "r"(a[2]), "r"(a[3]), "r"(b0), "r"(b1));
}
__device__ __forceinline__ void mma_f16(float (&d)[4], const uint32_t (&a)[4],
                                        uint32_t b0, uint32_t b1) {
    asm volatile("mma.sync.aligned.m16n8k16.row.col.f32.f16.f16.f32 "
                 "{%0,%1,%2,%3}, {%4,%5,%6,%7}, {%8,%9}, {%0,%1,%2,%3};"
                 : "+f"(d[0]), "+f"(d[1]), "+f"(d[2]), "+f"(d[3])
                 : "r"(a[0]), "r"(a[1]), "r"(a[2]), "r"(a[3]), "r"(b0), "r"(b1));
}
__device__ __forceinline__ uint32_t pack_split(float v0, float v1, uint32_t& lw) {
    bf16 h0 = __float2bfloat16(v0), h1 = __float2bfloat16(v1);
    float r0 = v0 - __bfloat162float(h0), r1 = v1 - __bfloat162float(h1);
    bf16 l0 = __float2bfloat16(r0), l1 = __float2bfloat16(r1);
    lw = (uint32_t)__bfloat16_as_ushort(l0) | ((uint32_t)__bfloat16_as_ushort(l1) << 16);
    return (uint32_t)__bfloat16_as_ushort(h0) | ((uint32_t)__bfloat16_as_ushort(h1) << 16);
}
__device__ __forceinline__ uint32_t pack_h2(float v0, float v1) {
    __half2 hv = __floats2half2_rn(v0, v1);
    return *(uint32_t*)&hv;
}

// ---------------- split-bf16 3-pass GEMM (patch conv only) ----------------
#define LDS 40
#define BM  128
#define BN_ 128

__global__ __launch_bounds__(256, 2)
void gemm_mma(const bf16* __restrict__ Ah, const bf16* __restrict__ Al,
              const bf16* __restrict__ Bh, const bf16* __restrict__ Bl,
              const float* __restrict__ bias, float* __restrict__ outF,
              int M, int Nfull, int K, int ldc)
{
    constexpr int MI = 2;
    constexpr int NI = 8;
    constexpr int ASZ = BM * LDS;
    constexpr int BSZ = BN_ * LDS;

    const int m0 = blockIdx.y * BM;
    const int n0 = blockIdx.x * BN_;

    extern __shared__ bf16 sm[];
    const uint32_t sbase = smem_u32(sm);

    const int tid = threadIdx.x;
    const int nch = K >> 5;

    auto load_stage = [&](int st, int k0) {
        #pragma unroll
        for (int i = tid; i < BM * 4; i += 256) {
            int r = i >> 2, c8 = (i & 3) << 3;
            int gr = m0 + r;
            int ok = (gr < M) ? 16 : 0;
            if (gr >= M) gr = m0;
            size_t go = (size_t)gr * K + k0 + c8;
            uint32_t so = (uint32_t)((st * ASZ + r * LDS + c8) * 2);
            cpa16(sbase + so, Ah + go, ok);
            cpa16(sbase + so + 2 * ASZ * 2, Al + go, ok);
        }
        #pragma unroll
        for (int i = tid; i < BN_ * 4; i += 256) {
            int r = i >> 2, c8 = (i & 3) << 3;
            int gn = n0 + r;
            int ok = (gn < Nfull) ? 16 : 0;
            if (gn >= Nfull) gn = n0;
            size_t go = (size_t)gn * K + k0 + c8;
            uint32_t so = (uint32_t)((4 * ASZ + st * BSZ + r * LDS + c8) * 2);
            cpa16(sbase + so, Bh + go, ok);
            cpa16(sbase + so + 2 * BSZ * 2, Bl + go, ok);
        }
        asm volatile("cp.async.commit_group;" ::: "memory");
    };

    const int wid = tid >> 5, lane = tid & 31;
    const int wr = wid & 3, wc = wid >> 2;
    const int wmBase = wr * 32, wnBase = wc * 64;

    float acc[MI][NI][4];
    #pragma unroll
    for (int mi = 0; mi < MI; mi++)
        #pragma unroll
        for (int ni = 0; ni < NI; ni++)
            #pragma unroll
            for (int j = 0; j < 4; j++) acc[mi][ni][j] = 0.f;

    load_stage(0, 0);

    for (int ch = 0; ch < nch; ch++) {
        asm volatile("cp.async.wait_group 0;" ::: "memory");
        __syncthreads();
        if (ch + 1 < nch) load_stage((ch + 1) & 1, (ch + 1) << 5);

        const int st = ch & 1;
        const uint32_t aHb = sbase + (uint32_t)(st * ASZ * 2);
        const uint32_t aLb = aHb + (uint32_t)(2 * ASZ * 2);
        const uint32_t bHb = sbase + (uint32_t)((4 * ASZ + st * BSZ) * 2);
        const uint32_t bLb = bHb + (uint32_t)(2 * BSZ * 2);

        #pragma unroll
        for (int kk = 0; kk < 2; kk++) {
            const int colOff = kk * 16 + ((lane >> 4) << 3);
            uint32_t afH[MI][4], afL[MI][4];
            #pragma unroll
            for (int mi = 0; mi < MI; mi++) {
                uint32_t off = (uint32_t)(((wmBase + mi * 16 + (lane & 15)) * LDS + colOff) * 2);
                ldsm4(afH[mi], aHb + off);
                ldsm4(afL[mi], aLb + off);
            }
            uint32_t bfH[4][4], bfL[4][4];
            #pragma unroll
            for (int nj = 0; nj < 4; nj++) {
                uint32_t off = (uint32_t)(((wnBase + nj * 16 + (lane & 15)) * LDS + colOff) * 2);
                ldsm4(bfH[nj], bHb + off);
                ldsm4(bfL[nj], bLb + off);
            }
            #pragma unroll
            for (int nj = 0; nj < 4; nj++) {
                #pragma unroll
                for (int mi = 0; mi < MI; mi++) {
                    mma_bf16(acc[mi][2*nj],   afH[mi], bfH[nj][0], bfH[nj][2]);
                    mma_bf16(acc[mi][2*nj+1], afH[mi], bfH[nj][1], bfH[nj][3]);
                }
                #pragma unroll
                for (int mi = 0; mi < MI; mi++) {
                    mma_bf16(acc[mi][2*nj],   afH[mi], bfL[nj][0], bfL[nj][2]);
                    mma_bf16(acc[mi][2*nj+1], afH[mi], bfL[nj][1], bfL[nj][3]);
                }
                #pragma unroll
                for (int mi = 0; mi < MI; mi++) {
                    mma_bf16(acc[mi][2*nj],   afL[mi], bfH[nj][0], bfH[nj][2]);
                    mma_bf16(acc[mi][2*nj+1], afL[mi], bfH[nj][1], bfH[nj][3]);
                }
            }
        }
    }

    const int g = lane >> 2, t4 = lane & 3;
    #pragma unroll
    for (int mi = 0; mi < MI; mi++) {
        #pragma unroll
        for (int ni = 0; ni < NI; ni++) {
            int col = n0 + wnBase + ni * 8 + t4 * 2;
            if (col >= Nfull) continue;
            #pragma unroll
            for (int half = 0; half < 2; half++) {
                int row = m0 + wmBase + mi * 16 + g + half * 8;
                if (row >= M) continue;
                float v0 = acc[mi][ni][half * 2 + 0] + bias[col];
                float v1 = acc[mi][ni][half * 2 + 1] + bias[col + 1];
                *(float2*)(outF + (long long)row * ldc + col) = make_float2(v0, v1);
            }
        }
    }
}

// ---------------- 2-pass fp16 GEMM (QKV / Wo / FFN / LM head) ----------------
// A: [M,K] fp16 single; B: [N,K] fp16 hi/lo. M,N,K % 128 == 0.
// outMode 0: C = A@(Bh+Bl)^T + bias (+res) (relu) -> fp32 and/or fp16
// outMode 1: QKV scatter (q single fp16 [b,h,t,d]; k split fp16; vt split fp16 [b,h,d,t])
__global__ __launch_bounds__(256, 2)
void gemm_2p(const h16* __restrict__ A,
             const h16* __restrict__ Bh, const h16* __restrict__ Bl,
             const float* __restrict__ bias, const float* __restrict__ res,
             float* __restrict__ outF, h16* __restrict__ outH16,
             h16* __restrict__ oq, h16* __restrict__ okh, h16* __restrict__ okl,
             h16* __restrict__ ovh, h16* __restrict__ ovl,
             int M, int N, int K, int relu, int outMode)
{
    constexpr int MI = 2;
    constexpr int NI = 8;
    constexpr int ASZ = BM * LDS;
    constexpr int BSZ = BN_ * LDS;

    const int m0 = blockIdx.y * BM;
    const int n0 = blockIdx.x * BN_;

    extern __shared__ h16 smh[];
    const uint32_t sbase = smem_u32(smh);

    const int tid = threadIdx.x;
    const int nch = K >> 5;

    auto load_stage = [&](int st, int k0) {
        #pragma unroll
        for (int i = tid; i < BM * 4; i += 256) {
            int r = i >> 2, c8 = (i & 3) << 3;
            size_t go = (size_t)(m0 + r) * K + k0 + c8;
            uint32_t so = (uint32_t)((st * ASZ + r * LDS + c8) * 2);
            cpa16(sbase + so, A + go, 16);
        }
        #pragma unroll
        for (int i = tid; i < BN_ * 4; i += 256) {
            int r = i >> 2, c8 = (i & 3) << 3;
            size_t go = (size_t)(n0 + r) * K + k0 + c8;
            uint32_t so = (uint32_t)((2 * ASZ + st * BSZ + r * LDS + c8) * 2);
            cpa16(sbase + so, Bh + go, 16);
            cpa16(sbase + so + 2 * BSZ * 2, Bl + go, 16);
        }
        asm volatile("cp.async.commit_group;" ::: "memory");
    };

    const int wid = tid >> 5, lane = tid & 31;
    const int wr = wid & 3, wc = wid >> 2;
    const int wmBase = wr * 32, wnBase = wc * 64;

    float acc[MI][NI][4];
    #pragma unroll
    for (int mi = 0; mi < MI; mi++)
        #pragma unroll
        for (int ni = 0; ni < NI; ni++)
            #pragma unroll
            for (int j = 0; j < 4; j++) acc[mi][ni][j] = 0.f;

    load_stage(0, 0);

    for (int ch = 0; ch < nch; ch++) {
        asm volatile("cp.async.wait_group 0;" ::: "memory");
        __syncthreads();
        if (ch + 1 < nch) load_stage((ch + 1) & 1, (ch + 1) << 5);

        const int st = ch & 1;
        const uint32_t aB  = sbase + (uint32_t)(st * ASZ * 2);
        const uint32_t bHb = sbase + (uint32_t)((2 * ASZ + st * BSZ) * 2);
        const uint32_t bLb = bHb + (uint32_t)(2 * BSZ * 2);

        #pragma unroll
        for (int kk = 0; kk < 2; kk++) {
            const int colOff = kk * 16 + ((lane >> 4) << 3);
            uint32_t af[MI][4];
            #pragma unroll
            for (int mi = 0; mi < MI; mi++) {
                uint32_t off = (uint32_t)(((wmBase + mi * 16 + (lane & 15)) * LDS + colOff) * 2);
                ldsm4(af[mi], aB + off);
            }
            uint32_t bfH[4][4], bfL[4][4];
            #pragma unroll
            for (int nj = 0; nj < 4; nj++) {
                uint32_t off = (uint32_t)(((wnBase + nj * 16 + (lane & 15)) * LDS + colOff) * 2);
                ldsm4(bfH[nj], bHb + off);
                ldsm4(bfL[nj], bLb + off);
            }
            #pragma unroll
            for (int nj = 0; nj < 4; nj++) {
                #pragma unroll
                for (int mi = 0; mi < MI; mi++) {
                    mma_f16(acc[mi][2*nj],   af[mi], bfH[nj][0], bfH[nj][2]);
                    mma_f16(acc[mi][2*nj+1], af[mi], bfH[nj][1], bfH[nj][3]);
                }
                #pragma unroll
                for (int mi = 0; mi < MI; mi++) {
                    mma_f16(acc[mi][2*nj],   af[mi], bfL[nj][0], bfL[nj][2]);
                    mma_f16(acc[mi][2*nj+1], af[mi], bfL[nj][1], bfL[nj][3]);
                }
            }
        }
    }

    const int g = lane >> 2, t4 = lane & 3;
    #pragma unroll
    for (int mi = 0; mi < MI; mi++) {
        #pragma unroll
        for (int ni = 0; ni < NI; ni++) {
            int col = n0 + wnBase + ni * 8 + t4 * 2;
            #pragma unroll
            for (int half = 0; half < 2; half++) {
                int row = m0 + wmBase + mi * 16 + g + half * 8;
                float v0 = acc[mi][ni][half * 2 + 0];
                float v1 = acc[mi][ni][half * 2 + 1];
                if (outMode == 1) {
                    int which = col >> 10;
                    int c = col & 1023;
                    int h = c >> 6, d = c & 63;
                    int b = row >> 10, t = row & 1023;
                    if (which == 0) {
                        size_t base = (((size_t)(b * HH + h)) * TT + t) * HD + d;
                        *(uint32_t*)(oq + base) = pack_h2(v0, v1);
                    } else if (which == 1) {
                        size_t base = (((size_t)(b * HH + h)) * TT + t) * HD + d;
                        h16 h0 = __float2half(v0), h1 = __float2half(v1);
                        h16 l0 = __float2half(v0 - __half2float(h0));
                        h16 l1 = __float2half(v1 - __half2float(h1));
                        okh[base] = h0; okh[base + 1] = h1;
                        okl[base] = l0; okl[base + 1] = l1;
                    } else {
                        size_t vb = (((size_t)(b * HH + h)) * HD + d) * TT + t;
                        h16 h0 = __float2half(v0), h1 = __float2half(v1);
                        h16 l0 = __float2half(v0 - __half2float(h0));
                        h16 l1 = __float2half(v1 - __half2float(h1));
                        ovh[vb] = h0; ovh[vb + TT] = h1;
                        ovl[vb] = l0; ovl[vb + TT] = l1;
                    }
                } else {
                    long long base = (long long)row * N + col;
                    v0 += bias[col]; v1 += bias[col + 1];
                    if (res) { v0 += res[base]; v1 += res[base + 1]; }
                    if (relu) { v0 = fmaxf(v0, 0.f); v1 = fmaxf(v1, 0.f); }
                    if (outF) *(float2*)(outF + base) = make_float2(v0, v1);
                    if (outH16) *(uint32_t*)(outH16 + base) = pack_h2(v0, v1);
                }
            }
        }
    }
}

// ---------------- fused flash attention (2-pass fp16, longest-first) ----------------
#define LDF 72
__global__ __launch_bounds__(256, 2)
void flash_attn_k(const h16* __restrict__ q,
                  const h16* __restrict__ kh, const h16* __restrict__ kl,
                  const h16* __restrict__ vth, const h16* __restrict__ vtl,
                  h16* __restrict__ o16)
{
    extern __shared__ h16 smf[];
    const uint32_t sbase = smem_u32(smf);
    const int id = blockIdx.x;
    const int rb = 7 - (id >> 6);
    const int bh = id & 63;
    const int m0 = rb * 128;
    const int tid = threadIdx.x, wid = tid >> 5, lane = tid & 31;
    const int g = lane >> 2, t4 = lane & 3;

    const uint32_t OKV = 128*LDF;        // Q at 0
    const uint32_t KVS = 4*64*LDF;

    for (int i = tid; i < 128 * 8; i += 256) {
        int r = i >> 3, c = (i & 7) << 3;
        size_t go = ((size_t)bh * TT + m0 + r) * HD + c;
        cpa16(sbase + (r * LDF + c) * 2, q + go, 16);
    }
    asm volatile("cp.async.commit_group;" ::: "memory");

    auto load_kv = [&](int st, int j0) {
        uint32_t base = OKV + (uint32_t)st * KVS;
        for (int i = tid; i < 64 * 8; i += 256) {
            int r = i >> 3, c = (i & 7) << 3;
            size_t gk = ((size_t)bh * TT + j0 + r) * HD + c;
            size_t gv = ((size_t)bh * HD + r) * TT + j0 + c;
            cpa16(sbase + (base            + r * LDF + c) * 2, kh  + gk, 16);
            cpa16(sbase + (base +   64*LDF + r * LDF + c) * 2, kl  + gk, 16);
            cpa16(sbase + (base + 2*64*LDF + r * LDF + c) * 2, vth + gv, 16);
            cpa16(sbase + (base + 3*64*LDF + r * LDF + c) * 2, vtl + gv, 16);
        }
        asm volatile("cp.async.commit_group;" ::: "memory");
    };

    const int ntiles = 2 * rb + 2;
    load_kv(0, 0);

    float oacc[8][4];
    #pragma unroll
    for (int ni = 0; ni < 8; ni++)
        #pragma unroll
        for (int j = 0; j < 4; j++) oacc[ni][j] = 0.f;
    float mrow[2] = { -1e30f, -1e30f };
    float lrow[2] = { 0.f, 0.f };

    const int row0 = m0 + wid * 16 + g;

    for (int t = 0; t < ntiles; t++) {
        const int j0 = t << 6;
        asm volatile("cp.async.wait_group 0;" ::: "memory");
        __syncthreads();
        if (t + 1 < ntiles) load_kv((t + 1) & 1, j0 + 64);

        const uint32_t kvb = OKV + (uint32_t)(t & 1) * KVS;
        const uint32_t kHb = sbase + kvb * 2;
        const uint32_t kLb = sbase + (kvb + 64*LDF) * 2;
        const uint32_t vHb = sbase + (kvb + 2*64*LDF) * 2;
        const uint32_t vLb = sbase + (kvb + 3*64*LDF) * 2;

        float acc[8][4];
        #pragma unroll
        for (int ni = 0; ni < 8; ni++)
            #pragma unroll
            for (int j = 0; j < 4; j++) acc[ni][j] = 0.f;

        // ---- S = Q @ (Kh+Kl)^T : 2-pass ----
        #pragma unroll
        for (int kk = 0; kk < 4; kk++) {
            const int colOff = kk * 16 + ((lane >> 4) << 3);
            uint32_t aQ[4];
            uint32_t aoff = (uint32_t)(((wid * 16 + (lane & 15)) * LDF + colOff) * 2);
            ldsm4(aQ, sbase + aoff);
            uint32_t bH[4][4], bL[4][4];
            #pragma unroll
            for (int nj = 0; nj < 4; nj++) {
                uint32_t boff = (uint32_t)(((nj * 16 + (lane & 15)) * LDF + colOff) * 2);
                ldsm4(bH[nj], kHb + boff);
                ldsm4(bL[nj], kLb + boff);
            }
            #pragma unroll
            for (int nj = 0; nj < 4; nj++) {
                mma_f16(acc[2*nj],   aQ, bH[nj][0], bH[nj][2]);
                mma_f16(acc[2*nj+1], aQ, bH[nj][1], bH[nj][3]);
                mma_f16(acc[2*nj],   aQ, bL[nj][0], bL[nj][2]);
                mma_f16(acc[2*nj+1], aQ, bL[nj][1], bL[nj][3]);
            }
        }

        #pragma unroll
        for (int ni = 0; ni < 8; ni++) {
            int colBase = j0 + ni * 8 + t4 * 2;
            #pragma unroll
            for (int j = 0; j < 4; j++) {
                int row = row0 + ((j >> 1) << 3);
                int col = colBase + (j & 1);
                float v = acc[ni][j] * 0.125f;
                acc[ni][j] = (col <= row) ? v : -1e30f;
            }
        }

        #pragma unroll
        for (int half = 0; half < 2; half++) {
            float mt = -1e30f;
            #pragma unroll
            for (int ni = 0; ni < 8; ni++) {
                mt = fmaxf(mt, acc[ni][half*2+0]);
                mt = fmaxf(mt, acc[ni][half*2+1]);
            }
            mt = fmaxf(mt, __shfl_xor_sync(0xffffffffu, mt, 1));
            mt = fmaxf(mt, __shfl_xor_sync(0xffffffffu, mt, 2));
            float mnew = fmaxf(mrow[half], mt);
            float scale = __expf(mrow[half] - mnew);
            mrow[half] = mnew;
            float sum = 0.f;
            #pragma unroll
            for (int ni = 0; ni < 8; ni++) {
                float e0 = __expf(acc[ni][half*2+0] - mnew);
                float e1 = __expf(acc[ni][half*2+1] - mnew);
                acc[ni][half*2+0] = e0;
                acc[ni][half*2+1] = e1;
                sum += e0 + e1;
            }
            sum += __shfl_xor_sync(0xffffffffu, sum, 1);
            sum += __shfl_xor_sync(0xffffffffu, sum, 2);
            lrow[half] = lrow[half] * scale + sum;
            #pragma unroll
            for (int ni = 0; ni < 8; ni++) {
                oacc[ni][half*2+0] *= scale;
                oacc[ni][half*2+1] *= scale;
            }
        }

        // ---- O += P @ (Vh+Vl)^T : P single fp16 in registers, 2-pass ----
        #pragma unroll
        for (int kk = 0; kk < 4; kk++) {
            uint32_t aP[4];
            aP[0] = pack_h2(acc[2*kk][0],   acc[2*kk][1]);
            aP[1] = pack_h2(acc[2*kk][2],   acc[2*kk][3]);
            aP[2] = pack_h2(acc[2*kk+1][0], acc[2*kk+1][1]);
            aP[3] = pack_h2(acc[2*kk+1][2], acc[2*kk+1][3]);
            const int colOff = kk * 16 + ((lane >> 4) << 3);
            uint32_t bH[4][4], bL[4][4];
            #pragma unroll
            for (int nj = 0; nj < 4; nj++) {
                uint32_t boff = (uint32_t)(((nj * 16 + (lane & 15)) * LDF + colOff) * 2);
                ldsm4(bH[nj], vHb + boff);
                ldsm4(bL[nj], vLb + boff);
            }
            #pragma unroll
            for (int nj = 0; nj < 4; nj++) {
                mma_f16(oacc[2*nj],   aP, bH[nj][0], bH[nj][2]);
                mma_f16(oacc[2*nj+1], aP, bH[nj][1], bH[nj][3]);
                mma_f16(oacc[2*nj],   aP, bL[nj][0], bL[nj][2]);
                mma_f16(oacc[2*nj+1], aP, bL[nj][1], bL[nj][3]);
            }
        }
    }

    const int b = bh >> 4, h = bh & 15;
    float inv0 = 1.f / lrow[0], inv1 = 1.f / lrow[1];
    #pragma unroll
    for (int ni = 0; ni < 8; ni++) {
        int d = ni * 8 + t4 * 2;
        #pragma unroll
        for (int half = 0; half < 2; half++) {
            int trow = m0 + wid * 16 + g + half * 8;
            float inv = half ? inv1 : inv0;
            size_t base = ((size_t)b * TT + trow) * CC + h * HD + d;
            *(uint32_t*)(o16 + base) = pack_h2(oacc[ni][half*2+0] * inv,
                                               oacc[ni][half*2+1] * inv);
        }
    }
}

// ---------------- block reductions ----------------
__device__ __forceinline__ float blockReduceSum256(float v, float* sh) {
    #pragma unroll
    for (int o = 16; o > 0; o >>= 1) v += __shfl_xor_sync(0xffffffffu, v, o);
    int w = threadIdx.x >> 5;
    if ((threadIdx.x & 31) == 0) sh[w] = v;
    __syncthreads();
    if (threadIdx.x < 8) {
        v = sh[threadIdx.x];
        #pragma unroll
        for (int o = 4; o > 0; o >>= 1) v += __shfl_xor_sync(0xffu, v, o);
        if (threadIdx.x == 0) sh[0] = v;
    }
    __syncthreads();
    float r = sh[0]; __syncthreads(); return r;
}

__device__ __forceinline__ void split_store(bf16* H, bf16* L, size_t i, float v) {
    bf16 h = __float2bfloat16(v);
    H[i] = h;
    L[i] = __float2bfloat16(v - __bfloat162float(h));
}
__device__ __forceinline__ void split_store_h(h16* H, h16* L, size_t i, float v) {
    h16 h = __float2half(v);
    H[i] = h;
    L[i] = __float2half(v - __half2float(h));
}

// ---------------- layernorm -> single fp16 ----------------
__global__ __launch_bounds__(256)
void layernorm_h16_k(const float* __restrict__ x, const float* __restrict__ g,
                     const float* __restrict__ b, h16* __restrict__ o)
{
    __shared__ float sh[8];
    const size_t row = blockIdx.x;
    const float* xr = x + row * CC;
    const int c = threadIdx.x * 4;
    float4 xv = *(const float4*)(xr + c);
    float s  = xv.x + xv.y + xv.z + xv.w;
    float ss = xv.x*xv.x + xv.y*xv.y + xv.z*xv.z + xv.w*xv.w;
    s = blockReduceSum256(s, sh);
    ss = blockReduceSum256(ss, sh);
    float mean = s * (1.f / CC);
    float var = ss * (1.f / CC) - mean * mean;
    float inv = rsqrtf(var + 1e-5f);
    float4 gv = *(const float4*)(g + c);
    float4 bv = *(const float4*)(b + c);
    size_t base = row * CC + c;
    o[base + 0] = __float2half((xv.x - mean) * inv * gv.x + bv.x);
    o[base + 1] = __float2half((xv.y - mean) * inv * gv.y + bv.y);
    o[base + 2] = __float2half((xv.z - mean) * inv * gv.z + bv.z);
    o[base + 3] = __float2half((xv.w - mean) * inv * gv.w + bv.w);
}

// ---------------- fused embed + layer0 LN1 -> x fp32 + single fp16 ----------------
__global__ __launch_bounds__(256)
void embed_ln_k(const int* __restrict__ toks, const float* __restrict__ tok_emb,
                const float* __restrict__ txt_pos, const float* __restrict__ img_pos,
                const float* __restrict__ p, const float* __restrict__ g,
                const float* __restrict__ b,
                float* __restrict__ x, h16* __restrict__ o)
{
    __shared__ float sh[8];
    const int bt = blockIdx.x;
    const int bb = bt >> 10;
    const int t = bt & 1023;
    const int c = threadIdx.x * 4;
    const float* src;
    const float* extra = nullptr;
    if (t == 0)      src = tok_emb + 1 * CC;
    else if (t == 1) src = tok_emb + 8 * CC;
    else if (t < 443) {
        int n = t - 2;
        src = p + ((size_t)(bb * NPATCH + n)) * CC;
        extra = img_pos + (size_t)n * CC;
    }
    else if (t == 443) src = tok_emb + 9 * CC;
    else {
        int tok = toks[bb * TTXT + (t - 444)];
        src = tok_emb + (size_t)tok * CC;
    }
    float4 v = *(const float4*)(src + c);
    float4 tp = *(const float4*)(txt_pos + (size_t)t * CC + c);
    v.x += tp.x; v.y += tp.y; v.z += tp.z; v.w += tp.w;
    if (extra) {
        float4 e = *(const float4*)(extra + c);
        v.x += e.x; v.y += e.y; v.z += e.z; v.w += e.w;
    }
    size_t base = (size_t)bt * CC + c;
    *(float4*)(x + base) = v;

    float s  = v.x + v.y + v.z + v.w;
    float ss = v.x*v.x + v.y*v.y + v.z*v.z + v.w*v.w;
    s = blockReduceSum256(s, sh);
    ss = blockReduceSum256(ss, sh);
    float mean = s * (1.f / CC);
    float var = ss * (1.f / CC) - mean * mean;
    float inv = rsqrtf(var + 1e-5f);
    float4 gv = *(const float4*)(g + c);
    float4 bv = *(const float4*)(b + c);
    o[base + 0] = __float2half((v.x - mean) * inv * gv.x + bv.x);
    o[base + 1] = __float2half((v.y - mean) * inv * gv.y + bv.y);
    o[base + 2] = __float2half((v.z - mean) * inv * gv.z + bv.z);
    o[base + 3] = __float2half((v.w - mean) * inv * gv.w + bv.w);
}

// ---------------- fused weight prep + im2col in ONE launch ----------------
__device__ __forceinline__ void transpose_tile(const float* __restrict__ W,
                                               bf16* __restrict__ hi, bf16* __restrict__ lo,
                                               int K, int N, int k0, int n0,
                                               float tbuf[32][33])
{
    int tx = threadIdx.x, ty = threadIdx.y;
    #pragma unroll
    for (int i = 0; i < 32; i += 8)
        tbuf[ty + i][tx] = W[(size_t)(k0 + ty + i) * N + n0 + tx];
    __syncthreads();
    #pragma unroll
    for (int i = 0; i < 32; i += 8)
        split_store(hi, lo, (size_t)(n0 + ty + i) * K + k0 + tx, tbuf[tx][ty + i]);
}
__device__ __forceinline__ void transpose_tile_h(const float* __restrict__ W,
                                                 h16* __restrict__ hi, h16* __restrict__ lo,
                                                 int K, int N, int k0, int n0,
                                                 float tbuf[32][33])
{
    int tx = threadIdx.x, ty = threadIdx.y;
    #pragma unroll
    for (int i = 0; i < 32; i += 8)
        tbuf[ty + i][tx] = W[(size_t)(k0 + ty + i) * N + n0 + tx];
    __syncthreads();
    #pragma unroll
    for (int i = 0; i < 32; i += 8)
        split_store_h(hi, lo, (size_t)(n0 + ty + i) * K + k0 + tx, tbuf[tx][ty + i]);
}

#define TPM_CC  1024
#define T_QKV   (LL*TPM_CC)
#define T_W1    (LL*(32*128))
#define T_LM    (32*500)
#define T_PATCH 768
#define T_IM2C  ((BB*NPATCH*KIM)/1024)

__global__ void prep_weights_k(const float* __restrict__ wq, const float* __restrict__ wk,
                               const float* __restrict__ wv, const float* __restrict__ wo,
                               const float* __restrict__ w1, const float* __restrict__ w2,
                               const float* __restrict__ lm_w, const float* __restrict__ patch_w,
                               const float* __restrict__ images,
                               h16* qkvh, h16* qkvl, h16* woh, h16* wol,
                               h16* w1h, h16* w1l, h16* w2h, h16* w2l,
                               h16* lmh, h16* lml, bf16* pwh, bf16* pwl,
                               bf16* imh, bf16* iml)
{
    __shared__ float tbuf[32][33];
    int t = blockIdx.x;
    const long long QKV_Z = (long long)3 * CC * CC;

    if (t < 3 * T_QKV) {
        int which = t / T_QKV;
        int r = t % T_QKV;
        int l = r / TPM_CC;
        int loc = r % TPM_CC;
        int n0 = (loc & 31) * 32, k0 = (loc >> 5) * 32;
        const float* W = (which == 0 ? wq : which == 1 ? wk : wv) + (size_t)l * CC * CC;
        h16* hi = qkvh + (size_t)l * QKV_Z + (size_t)which * CC * CC;
        h16* lo = qkvl + (size_t)l * QKV_Z + (size_t)which * CC * CC;
        transpose_tile_h(W, hi, lo, CC, CC, k0, n0, tbuf);
        return;
    }
    t -= 3 * T_QKV;
    if (t < T_QKV) {
        int l = t / TPM_CC, loc = t % TPM_CC;
        int n0 = (loc & 31) * 32, k0 = (loc >> 5) * 32;
        transpose_tile_h(wo + (size_t)l * CC * CC, woh + (size_t)l * CC * CC,
                         wol + (size_t)l * CC * CC, CC, CC, k0, n0, tbuf);
        return;
    }
    t -= T_QKV;
    if (t < T_W1) {
        int l = t / (32 * 128), loc = t % (32 * 128);
        int n0 = (loc % 128) * 32, k0 = (loc / 128) * 32;
        transpose_tile_h(w1 + (size_t)l * CC * FF_, w1h + (size_t)l * CC * FF_,
                         w1l + (size_t)l * CC * FF_, CC, FF_, k0, n0, tbuf);
        return;
    }
    t -= T_W1;
    if (t < T_W1) {
        int l = t / (128 * 32), loc = t % (128 * 32);
        int n0 = (loc & 31) * 32, k0 = (loc >> 5) * 32;
        transpose_tile_h(w2 + (size_t)l * CC * FF_, w2h + (size_t)l * CC * FF_,
                         w2l + (size_t)l * CC * FF_, FF_, CC, k0, n0, tbuf);
        return;
    }
    t -= T_W1;
    if (t < T_LM) {
        int n0 = (t % 500) * 32, k0 = (t / 500) * 32;
        transpose_tile_h(lm_w, lmh, lml, CC, VV, k0, n0, tbuf);
        return;
    }
    t -= T_LM;
    if (t < T_PATCH) {
        int base = t * 1024;
        int tid = threadIdx.y * 32 + threadIdx.x;
        #pragma unroll
        for (int i = 0; i < 4; i++) {
            int idx = base + tid + i * 256;
            split_store(pwh, pwl, idx, patch_w[idx]);
        }
        return;
    }
    t -= T_PATCH;
    {
        int tid = threadIdx.y * 32 + threadIdx.x;
        #pragma unroll
        for (int i = 0; i < 4; i++) {
            int idx = t * 1024 + tid + i * 256;
            int k = idx % KIM;
            int bn = idx / KIM;
            int n = bn % NPATCH;
            int b = bn / NPATCH;
            int ci = k >> 8;
            int rr = k & 255;
            int kh = rr >> 4;
            int kw = rr & 15;
            int ph = n / 21, pw = n % 21;
            float v = images[(((size_t)b * 3 + ci) * IMG + ph * PATCH + kh) * IMG + pw * PATCH + kw];
            split_store(imh, iml, idx, v);
        }
    }
}

// ---------------- host-side launchers ----------------
#define SMEM_GEMM  ((4 * 128 * LDS + 4 * 128 * LDS) * 2)
#define SMEM_2P    ((2 * 128 * LDS + 4 * 128 * LDS) * 2)
#define FLASH_SMEM ((128 * LDF + 2 * 4 * 64 * LDF) * 2)

static inline void tc2p(const h16* A, const h16* Bh, const h16* Bl,
                        const float* bias, const float* res,
                        float* outF, h16* outH16, int M, int N, int K,
                        int relu = 0, int outMode = 0,
                        h16* oq = nullptr, h16* okh = nullptr, h16* okl = nullptr,
                        h16* ovh = nullptr, h16* ovl = nullptr)
{
    dim3 grid(N / 128, M / 128);
    gemm_2p<<<grid, 256, SMEM_2P>>>(A, Bh, Bl, bias, res, outF, outH16,
                                    oq, okh, okl, ovh, ovl, M, N, K, relu, outMode);
}

#define SYM(name) ({ void* _p; cudaGetSymbolAddress(&_p, name); _p; })

extern "C" void kernel_launch(void* const* d_in, const int* in_sizes, int n_in,
                              void* d_out, int out_size)
{
    const int*   text_tokens = (const int*)  d_in[0];
    const float* images      = (const float*)d_in[1];
    const float* tok_emb     = (const float*)d_in[2];
    const float* txt_pos     = (const float*)d_in[3];
    const float* img_pos     = (const float*)d_in[4];
    const float* patch_w     = (const float*)d_in[5];
    const float* patch_b     = (const float*)d_in[6];
    const float* ln1_g       = (const float*)d_in[7];
    const float* ln1_b       = (const float*)d_in[8];
    const float* wq          = (const float*)d_in[9];
    const float* wk          = (const float*)d_in[10];
    const float* wv          = (const float*)d_in[11];
    const float* wo          = (const float*)d_in[12];
    const float* bo          = (const float*)d_in[13];
    const float* ln2_g       = (const float*)d_in[14];
    const float* ln2_b       = (const float*)d_in[15];
    const float* w1          = (const float*)d_in[16];
    const float* b1          = (const float*)d_in[17];
    const float* w2          = (const float*)d_in[18];
    const float* b2          = (const float*)d_in[19];
    const float* lnf_g       = (const float*)d_in[20];
    const float* lnf_b       = (const float*)d_in[21];
    const float* lm_w        = (const float*)d_in[22];
    const float* lm_b        = (const float*)d_in[23];
    float* out = (float*)d_out;

    cudaFuncSetAttribute(gemm_mma, cudaFuncAttributeMaxDynamicSharedMemorySize, SMEM_GEMM);
    cudaFuncSetAttribute(gemm_2p,  cudaFuncAttributeMaxDynamicSharedMemorySize, SMEM_2P);
    cudaFuncSetAttribute(flash_attn_k, cudaFuncAttributeMaxDynamicSharedMemorySize, FLASH_SMEM);

    float* px   = (float*)SYM(g_x);
    float* ppp  = (float*)SYM(g_pp);
    h16 *pa16 = (h16*)SYM(g_a16);
    h16 *pf16 = (h16*)SYM(g_f16);
    h16 *pq16 = (h16*)SYM(g_q16);
    h16 *pkh = (h16*)SYM(g_kh16), *pkl = (h16*)SYM(g_kl16);
    h16 *pvth = (h16*)SYM(g_vth16), *pvtl = (h16*)SYM(g_vtl16);
    h16 *pwqkvh = (h16*)SYM(g_wqkvh), *pwqkvl = (h16*)SYM(g_wqkvl);
    h16 *pwoh = (h16*)SYM(g_woh), *pwol = (h16*)SYM(g_wol);
    h16 *pw1h = (h16*)SYM(g_w1h), *pw1l = (h16*)SYM(g_w1l);
    h16 *pw2h = (h16*)SYM(g_w2h), *pw2l = (h16*)SYM(g_w2l);
    h16 *plmh = (h16*)SYM(g_lmh), *plml = (h16*)SYM(g_lml);
    bf16 *ppwh = (bf16*)SYM(g_pwh), *ppwl = (bf16*)SYM(g_pwl);
    bf16 *pimh = (bf16*)SYM(g_imh), *piml = (bf16*)SYM(g_iml);

    // ---- [1] all weight prep + im2col in one launch ----
    const int nPrep = 4 * T_QKV + 2 * T_W1 + T_LM + T_PATCH + T_IM2C;
    prep_weights_k<<<nPrep, dim3(32, 8)>>>(wq, wk, wv, wo, w1, w2, lm_w, patch_w, images,
        pwqkvh, pwqkvl, pwoh, pwol, pw1h, pw1l, pw2h, pw2l, plmh, plml, ppwh, ppwl,
        pimh, piml);

    // ---- [2] patch GEMM (3-pass bf16)  [3] fused embed+LN1(l=0) ----
    {
        dim3 grid((CC + 127) / 128, (BB*NPATCH + 127) / 128);
        gemm_mma<<<grid, 256, SMEM_GEMM>>>(pimh, piml, ppwh, ppwl, patch_b, ppp,
                                           BB*NPATCH, CC, KIM, CC);
    }
    embed_ln_k<<<BB*TT, 256>>>(text_tokens, tok_emb, txt_pos, img_pos, ppp,
                               ln1_g, ln1_b, px, pa16);

    const int M = MTOK;
    for (int l = 0; l < LL; l++) {
        size_t wOff = (size_t)l * CC * CC, w1Off = (size_t)l * CC * FF_;
        size_t qkvOff = (size_t)l * 3 * CC * CC;

        if (l > 0)
            layernorm_h16_k<<<M, 256>>>(px, ln1_g + l*CC, ln1_b + l*CC, pa16);

        // QKV: 2-pass fp16 with scatter (q single; k split; vt split)
        tc2p(pa16, pwqkvh + qkvOff, pwqkvl + qkvOff, nullptr, nullptr,
             nullptr, nullptr, M, 3*CC, CC, 0, /*outMode*/1,
             pq16, pkh, pkl, pvth, pvtl);

        // flash attention (2-pass fp16) -> single fp16 at [b,t,h,d]
        flash_attn_k<<<BB*HH*8, 256, FLASH_SMEM>>>(
            pq16, pkh, pkl, pvth, pvtl, pa16);

        // Wo: 2-pass fp16 + bias + residual -> x
        tc2p(pa16, pwoh + wOff, pwol + wOff, bo + l*CC, px, px, nullptr,
             M, CC, CC);

        // LN2 -> single fp16, then 2-pass fp16 FFN
        layernorm_h16_k<<<M, 256>>>(px, ln2_g + l*CC, ln2_b + l*CC, pa16);
        tc2p(pa16, pw1h + w1Off, pw1l + w1Off, b1 + l*FF_, nullptr,
             nullptr, pf16, M, FF_, CC, /*relu*/1);
        tc2p(pf16, pw2h + w1Off, pw2l + w1Off, b2 + l*CC, px,
             px, nullptr, M, CC, FF_);
    }

    // ---- final LN (single fp16) + LM head (2-pass fp16) ----
    layernorm_h16_k<<<M, 256>>>(px, lnf_g, lnf_b, pa16);
    tc2p(pa16, plmh, plml, lm_b, nullptr, out, nullptr, M, VV, CC);
}